// round 11
// baseline (speedup 1.0000x reference)
#include <cuda_runtime.h>
#include <math.h>
#include <stdint.h>

#define Bsz 8192
#define Vn  8
#define FcN 64
#define BNEPS 1e-5f

__device__ float g_h1 [(size_t)Bsz*Vn*128];
__device__ float g_h2 [(size_t)Bsz*Vn*128];
__device__ float g_e  [(size_t)Bsz*Vn*512];
__device__ float g_hd1[(size_t)Bsz*Vn*256];
__device__ float g_hd2[(size_t)Bsz*Vn*256];
__device__ float g_HY [(size_t)Bsz*FcN*40];
__device__ float g_r1 [(size_t)Bsz*FcN*256];
__device__ float g_r2 [(size_t)Bsz*FcN*256];
__device__ float g_P   [(size_t)Bsz*Vn*32];
__device__ float g_y   [(size_t)Bsz*FcN*8];
__device__ float g_xequ[(size_t)Bsz*FcN*8];
__device__ float g_xeq1[(size_t)Bsz*FcN*8];
__device__ float g_sig [(size_t)Bsz*512];
__device__ float g_W2e[Vn*128*128]; __device__ float g_b2e[Vn*128];
__device__ float g_W3e[Vn*128*512]; __device__ float g_b3e[Vn*512];
__device__ float g_W2d[Vn*256*256]; __device__ float g_b2d[Vn*256];
__device__ float g_W3d[Vn*256*32];  __device__ float g_b3d[Vn*32];
__device__ float g_part[32*Vn*256*2];
__device__ float g_consts[4];

__device__ __forceinline__ uint32_t f2tf32(float f) {
    uint32_t r; asm("cvt.rna.tf32.f32 %0, %1;" : "=r"(r) : "f"(f)); return r;
}
__device__ __forceinline__ void split_tf32(float f, uint32_t& hi, uint32_t& lo) {
    hi = f2tf32(f);
    lo = f2tf32(f - __uint_as_float(hi));
}
__device__ __forceinline__ void mma8(float* c, const uint32_t* a, const uint32_t* b) {
    asm volatile(
        "mma.sync.aligned.m16n8k8.row.col.f32.tf32.tf32.f32 "
        "{%0,%1,%2,%3}, {%4,%5,%6,%7}, {%8,%9}, {%0,%1,%2,%3};"
        : "+f"(c[0]), "+f"(c[1]), "+f"(c[2]), "+f"(c[3])
        : "r"(a[0]), "r"(a[1]), "r"(a[2]), "r"(a[3]), "r"(b[0]), "r"(b[1]));
}

__global__ void prep_kernel(const int* __restrict__ snrp) {
    int iv = *snrp;
    float S;
    if (iv >= -1000 && iv <= 1000) S = (float)iv;
    else                            S = __int_as_float(iv);
    float snr = powf(10.f, -S * 0.1f);
    g_consts[0] = 4.f * snr;
    g_consts[1] = sqrtf(4.f * snr);
}

// ================= 3-term GEMM (round-7 proven): 512 thr, warp 32x32 ==========
#define AST 20
#define BST 136
#define AS_SZ   (128 * AST)
#define BS_SZ   (16 * BST)
#define A_BUF3  (2 * AS_SZ)
#define B_BUF3  (2 * BS_SZ)
#define BS_BASE3 (2 * A_BUF3)

__global__ __launch_bounds__(512) void mma_gemm3(
    const float* __restrict__ A, int lda, long sAv,
    const float* __restrict__ W, long sWv,
    const float* __restrict__ bias, int sbv,
    float* __restrict__ C, int ldc, long sCv,
    int K, int N, int relu)
{
    extern __shared__ uint32_t smem[];

    const int v = blockIdx.z;
    A    += (long)v * sAv;
    W    += (long)v * sWv;
    bias += (long)v * sbv;
    C    += (long)v * sCv;

    const long row0 = (long)blockIdx.y << 7;
    const int  col0 = blockIdx.x << 7;

    const int tid  = threadIdx.x;
    const int lane = tid & 31;
    const int wid  = tid >> 5;
    const int m0 = (wid & 3) << 5;
    const int n0 = (wid >> 2) << 5;

    const int ar  = tid >> 2;
    const int akq = (tid & 3) << 2;
    const int bk  = tid >> 5;
    const int bnq = (tid & 31) << 2;
    const bool bok = (col0 + bnq) < N;

    const float* Ap = A + (row0 + ar) * (long)lda;
    const float* Wp = W + (long)col0 + bnq;

    const int nch = (K + 15) >> 4;

    auto store_tiles = [&](int nb, float4 a4, float4 b4) {
        uint32_t* ash = smem + nb * A_BUF3 + ar * AST + akq;
        uint32_t* asl = ash + AS_SZ;
        split_tf32(a4.x, ash[0], asl[0]); split_tf32(a4.y, ash[1], asl[1]);
        split_tf32(a4.z, ash[2], asl[2]); split_tf32(a4.w, ash[3], asl[3]);
        uint32_t* bsh = smem + BS_BASE3 + nb * B_BUF3 + bk * BST + bnq;
        uint32_t* bsl = bsh + BS_SZ;
        split_tf32(b4.x, bsh[0], bsl[0]); split_tf32(b4.y, bsh[1], bsl[1]);
        split_tf32(b4.z, bsh[2], bsl[2]); split_tf32(b4.w, bsh[3], bsl[3]);
    };

    {
        float4 a4 = make_float4(0.f, 0.f, 0.f, 0.f);
        if (akq < K) a4 = *(const float4*)(Ap + akq);
        float4 b4 = make_float4(0.f, 0.f, 0.f, 0.f);
        if (bok && bk < K) b4 = *(const float4*)(Wp + (long)bk * N);
        store_tiles(0, a4, b4);
    }
    __syncthreads();

    float c[2][4][4] = {};
    int buf = 0;
    for (int ch = 0; ch < nch; ++ch) {
        float4 a4 = make_float4(0.f, 0.f, 0.f, 0.f);
        float4 b4 = make_float4(0.f, 0.f, 0.f, 0.f);
        const int nk0 = (ch + 1) << 4;
        const bool more = (ch + 1) < nch;
        if (more) {
            if (nk0 + akq < K) a4 = *(const float4*)(Ap + nk0 + akq);
            if (bok && (nk0 + bk) < K) b4 = *(const float4*)(Wp + (long)(nk0 + bk) * N);
        }

        const uint32_t* asb = smem + buf * A_BUF3 + (m0 + (lane >> 2)) * AST + (lane & 3);
        const uint32_t* bsb = smem + BS_BASE3 + buf * B_BUF3 + (lane & 3) * BST + n0 + (lane >> 2);
#pragma unroll
        for (int kk = 0; kk < 2; ++kk) {
            uint32_t ah[2][4], al[2][4];
#pragma unroll
            for (int i = 0; i < 2; ++i) {
                const uint32_t* p = asb + (i << 4) * AST + (kk << 3);
                ah[i][0] = p[0];
                ah[i][1] = p[8 * AST];
                ah[i][2] = p[4];
                ah[i][3] = p[8 * AST + 4];
                const uint32_t* pl = p + AS_SZ;
                al[i][0] = pl[0];
                al[i][1] = pl[8 * AST];
                al[i][2] = pl[4];
                al[i][3] = pl[8 * AST + 4];
            }
            uint32_t bh[4][2], bl[4][2];
#pragma unroll
            for (int j = 0; j < 4; ++j) {
                const uint32_t* q = bsb + (kk << 3) * BST + (j << 3);
                bh[j][0] = q[0];
                bh[j][1] = q[4 * BST];
                const uint32_t* ql = q + BS_SZ;
                bl[j][0] = ql[0];
                bl[j][1] = ql[4 * BST];
            }
#pragma unroll
            for (int i = 0; i < 2; ++i)
#pragma unroll
                for (int j = 0; j < 4; ++j) {
                    mma8(c[i][j], al[i], bh[j]);
                    mma8(c[i][j], ah[i], bl[j]);
                    mma8(c[i][j], ah[i], bh[j]);
                }
        }

        if (more) store_tiles(buf ^ 1, a4, b4);
        __syncthreads();
        buf ^= 1;
    }

#pragma unroll
    for (int i = 0; i < 2; ++i) {
        const long row = row0 + m0 + (i << 4) + (lane >> 2);
#pragma unroll
        for (int j = 0; j < 4; ++j) {
            const int col = col0 + n0 + (j << 3) + ((lane & 3) << 1);
            if (col < N) {
                const float2 bv = *(const float2*)(bias + col);
                float v0 = c[i][j][0] + bv.x;
                float v1 = c[i][j][1] + bv.y;
                float v2 = c[i][j][2] + bv.x;
                float v3 = c[i][j][3] + bv.y;
                if (relu) {
                    v0 = fmaxf(v0, 0.f); v1 = fmaxf(v1, 0.f);
                    v2 = fmaxf(v2, 0.f); v3 = fmaxf(v3, 0.f);
                }
                float2 o0 = {v0, v1}, o1 = {v2, v3};
                *(float2*)(C + row * (long)ldc + col)       = o0;
                *(float2*)(C + (row + 8) * (long)ldc + col) = o1;
            }
        }
    }
}

// ========== 1-term GEMM (round-9 verified layout): 256 thr, warp 32x64 =========
// Fragment-native smem: addr(row,k) = row*16 + (k&3)*4 + (k>>2); plane 2048 u32.
__global__ __launch_bounds__(256, 2) void mma_gemm1(
    const float* __restrict__ A, int lda, long sAv,
    const float* __restrict__ W, long sWv,
    const float* __restrict__ bias, int sbv,
    float* __restrict__ C, int ldc, long sCv,
    int K, int N, int relu)
{
    extern __shared__ uint32_t smem[];
    constexpr int PL    = 2048;
    constexpr int B_OFF = 2 * PL;

    const int v = blockIdx.z;
    A    += (long)v * sAv;
    W    += (long)v * sWv;
    bias += (long)v * sbv;
    C    += (long)v * sCv;

    const long row0 = (long)blockIdx.y << 7;
    const int  col0 = blockIdx.x << 7;

    const int tid  = threadIdx.x;
    const int lane = tid & 31;
    const int wid  = tid >> 5;
    const int m0 = (wid & 3) << 5;
    const int n0 = (wid >> 2) << 6;
    const int lr = lane >> 2, lc = lane & 3;

    const int ar = tid >> 2, aq = tid & 3;
    const int kb = tid & 15, nq = tid >> 4;
    const int nch = (K + 15) >> 4;

    float4 a4[2], b4[2];

    auto load_g = [&](int k0) {
#pragma unroll
        for (int it = 0; it < 2; ++it) {
            const int r = ar + (it << 6);
            a4[it] = make_float4(0.f, 0.f, 0.f, 0.f);
            if (4 * aq + k0 < K)
                a4[it] = *(const float4*)(A + (row0 + r) * (long)lda + k0 + 4 * aq);
            const int nn = nq + (it << 4);
            b4[it] = make_float4(0.f, 0.f, 0.f, 0.f);
            if ((k0 + kb < K) && (col0 + 4 * nn < N))
                b4[it] = *(const float4*)(W + (long)(k0 + kb) * N + col0 + 4 * nn);
        }
    };

    auto store_s = [&](int buf) {
        uint32_t* ab = smem + buf * PL;
        uint32_t* bb = smem + B_OFF + buf * PL;
#pragma unroll
        for (int it = 0; it < 2; ++it) {
            const int r = ar + (it << 6);
            const float* av = &a4[it].x;
#pragma unroll
            for (int t = 0; t < 4; ++t) {
                const int tt = (t + r + (r >> 2)) & 3;
                ab[r * 16 + tt * 4 + aq] = f2tf32(av[tt]);
            }
            const int nn = nq + (it << 4);
            const int klo = kb & 3, p = kb >> 2;
            const float* bv = &b4[it].x;
#pragma unroll
            for (int t = 0; t < 4; ++t) {
                const int tt = (t + nn) & 3;
                const int n = 4 * nn + tt;
                bb[n * 16 + klo * 4 + p] = f2tf32(bv[tt]);
            }
        }
    };

    load_g(0);
    store_s(0);
    __syncthreads();

    float c[2][8][4] = {};
    int buf = 0;
    for (int ch = 0; ch < nch; ++ch) {
        const bool more = (ch + 1) < nch;
        if (more) load_g((ch + 1) << 4);

        const uint32_t* ab = smem + buf * PL;
        const uint32_t* bb = smem + B_OFF + buf * PL;

        uint4 AH[2][2];
#pragma unroll
        for (int i = 0; i < 2; ++i) {
            const int r = m0 + i * 16 + lr;
            AH[i][0] = *(const uint4*)(ab + r * 16 + lc * 4);
            AH[i][1] = *(const uint4*)(ab + (r + 8) * 16 + lc * 4);
        }
#pragma unroll
        for (int j = 0; j < 8; ++j) {
            const int n = n0 + j * 8 + lr;
            const uint4 BH = *(const uint4*)(bb + n * 16 + lc * 4);
#pragma unroll
            for (int kk = 0; kk < 2; ++kk) {
                uint32_t bh[2];
                bh[0] = kk ? BH.z : BH.x;
                bh[1] = kk ? BH.w : BH.y;
#pragma unroll
                for (int i = 0; i < 2; ++i) {
                    uint32_t ah[4];
                    ah[0] = kk ? AH[i][0].z : AH[i][0].x;
                    ah[1] = kk ? AH[i][1].z : AH[i][1].x;
                    ah[2] = kk ? AH[i][0].w : AH[i][0].y;
                    ah[3] = kk ? AH[i][1].w : AH[i][1].y;
                    mma8(c[i][j], ah, bh);
                }
            }
        }

        if (more) store_s(buf ^ 1);
        __syncthreads();
        buf ^= 1;
    }

#pragma unroll
    for (int i = 0; i < 2; ++i) {
        const long r0e = row0 + m0 + i * 16 + lr;
#pragma unroll
        for (int j = 0; j < 8; ++j) {
            const int col = col0 + n0 + j * 8 + lc * 2;
            if (col < N) {
                const float2 bv = *(const float2*)(bias + col);
                float v0 = c[i][j][0] + bv.x;
                float v1 = c[i][j][1] + bv.y;
                float v2 = c[i][j][2] + bv.x;
                float v3 = c[i][j][3] + bv.y;
                if (relu) {
                    v0 = fmaxf(v0, 0.f); v1 = fmaxf(v1, 0.f);
                    v2 = fmaxf(v2, 0.f); v3 = fmaxf(v3, 0.f);
                }
                float2 o0 = {v0, v1}, o1 = {v2, v3};
                *(float2*)(C + r0e * (long)ldc + col)       = o0;
                *(float2*)(C + (r0e + 8) * (long)ldc + col) = o1;
            }
        }
    }
}

__global__ void stats_kernel(const float* __restrict__ h, int C, float* __restrict__ part) {
    const int v = blockIdx.x, s = blockIdx.y, c = threadIdx.x;
    const long stride = (long)Vn * C;
    const float* p = h + ((long)(s * 256) * Vn + v) * C + c;
    float sum = 0.f, sq = 0.f;
#pragma unroll 4
    for (int i = 0; i < 256; ++i) {
        float val = p[(long)i * stride];
        sum += val;
        sq = fmaf(val, val, sq);
    }
    const long o = (((long)s * Vn + v) * C + c) * 2;
    part[o] = sum; part[o + 1] = sq;
}

__global__ void fuse_kernel(const float* __restrict__ W, const float* __restrict__ bias,
                            const float* __restrict__ g, const float* __restrict__ be,
                            int Cin, int Nout,
                            float* __restrict__ Wp, float* __restrict__ bp)
{
    const int v = blockIdx.x, tid = threadIdx.x;
    __shared__ float sa[512], sc[512];
    for (int n = tid; n < Cin; n += blockDim.x) {
        float sum = 0.f, sq = 0.f;
        for (int s = 0; s < 32; ++s) {
            const long o = (((long)s * Vn + v) * Cin + n) * 2;
            sum += g_part[o]; sq += g_part[o + 1];
        }
        const float mu  = sum * (1.f / Bsz);
        const float var = sq * (1.f / Bsz) - mu * mu;
        const float rs  = rsqrtf(var + BNEPS);
        const float a   = g[v * Cin + n] * rs;
        sa[n] = a;
        sc[n] = be[v * Cin + n] - mu * a;
    }
    __syncthreads();
    const int slice = (Nout + gridDim.y - 1) / gridDim.y;
    const int j0 = blockIdx.y * slice;
    const int j1 = min(j0 + slice, Nout);
    const float* wv = W + (long)v * Cin * Nout;
    float* wpv = Wp + (long)v * Cin * Nout;
    for (int j = j0 + tid; j < j1; j += blockDim.x) {
        float acc = bias[v * Nout + j];
        for (int n = 0; n < Cin; ++n) {
            const float w = wv[(long)n * Nout + j];
            wpv[(long)n * Nout + j] = sa[n] * w;
            acc = fmaf(sc[n], w, acc);
        }
        bp[v * Nout + j] = acc;
    }
}

__global__ void combine_kernel(float* __restrict__ enc_sig) {
    const int b = blockIdx.x;
    const int d = threadIdx.x;
    __shared__ float red[16];
    __shared__ float tot_s;
    float acc = 0.f;
#pragma unroll
    for (int v = 0; v < Vn; ++v) {
        const float ev = g_e[((long)b * Vn + v) * 512 + d];
        float s = ev * ev;
#pragma unroll
        for (int o = 16; o; o >>= 1) s += __shfl_xor_sync(0xffffffffu, s, o);
        if ((d & 31) == 0) red[d >> 5] = s;
        __syncthreads();
        if (d < 32) {
            float t = (d < 16) ? red[d] : 0.f;
#pragma unroll
            for (int o = 8; o; o >>= 1) t += __shfl_xor_sync(0xffffffffu, t, o);
            if (d == 0) tot_s = t;
        }
        __syncthreads();
        const float alpha = 8.f * rsqrtf(tot_s);
        acc = fmaf(alpha, ev, acc);
        __syncthreads();
    }
    enc_sig[(long)b * 512 + d] = acc * 0.70710678118654752f;
}

struct C2 { float x, y; };
__device__ __forceinline__ C2 cmul(C2 a, C2 b) { return {a.x*b.x - a.y*b.y, a.x*b.y + a.y*b.x}; }
__device__ __forceinline__ C2 cmulc(C2 a, C2 b) { return {a.x*b.x + a.y*b.y, a.x*b.y - a.y*b.x}; }

__global__ void channel_kernel(const float* __restrict__ Hri, const float* __restrict__ noiseri,
                               const float* __restrict__ encsig,
                               float* __restrict__ yout, float* __restrict__ xeq1out)
{
    const int b = blockIdx.x;
    const int f = threadIdx.x;
    __shared__ C2 H[4][4];
    __shared__ C2 Ainv[4][4];
    const float is2 = 0.70710678118654752f;

    if (f < 16) {
        const int r = f >> 2, t = f & 3;
        const long o = (((long)(b * 4 + r)) * 4 + t) * 2;
        H[r][t] = {Hri[o] * is2, Hri[o + 1] * is2};
    }
    __syncthreads();

    const float lam = g_consts[0];
    const float nsc = g_consts[1];

    if (f == 0) {
        C2 Am[4][8];
        for (int i = 0; i < 4; ++i) {
            for (int j = 0; j < 4; ++j) {
                C2 a = {0.f, 0.f};
                for (int r = 0; r < 4; ++r) {
                    C2 p = cmulc(H[r][i], H[r][j]);
                    a.x += p.x; a.y += p.y;
                }
                if (i == j) a.x += lam;
                Am[i][j] = a;
                Am[i][4 + j] = (i == j) ? C2{1.f, 0.f} : C2{0.f, 0.f};
            }
        }
        for (int p = 0; p < 4; ++p) {
            C2 dg = Am[p][p];
            const float inv = 1.f / (dg.x * dg.x + dg.y * dg.y);
            const C2 dinv = {dg.x * inv, -dg.y * inv};
            for (int j = 0; j < 8; ++j) Am[p][j] = cmul(Am[p][j], dinv);
            for (int r = 0; r < 4; ++r) {
                if (r == p) continue;
                const C2 fac = Am[r][p];
                for (int j = 0; j < 8; ++j) {
                    const C2 q = cmul(fac, Am[p][j]);
                    Am[r][j].x -= q.x; Am[r][j].y -= q.y;
                }
            }
        }
        for (int i = 0; i < 4; ++i)
            for (int j = 0; j < 4; ++j)
                Ainv[i][j] = Am[i][4 + j];
    }
    __syncthreads();

    C2 s[4];
#pragma unroll
    for (int t = 0; t < 4; ++t) {
        const long o = ((long)b * 512) + ((long)(f * 4 + t)) * 2;
        s[t] = {encsig[o], encsig[o + 1]};
    }
    const long nbase = ((long)(b * 64 + f)) * 8;
    C2 yv[4];
#pragma unroll
    for (int r = 0; r < 4; ++r) {
        C2 a = {0.f, 0.f};
#pragma unroll
        for (int t = 0; t < 4; ++t) { C2 p = cmul(H[r][t], s[t]); a.x += p.x; a.y += p.y; }
        a.x += nsc * noiseri[nbase + r * 2]     * is2;
        a.y += nsc * noiseri[nbase + r * 2 + 1] * is2;
        yv[r] = a;
        yout[nbase + r * 2]     = a.x;
        yout[nbase + r * 2 + 1] = a.y;
    }
    C2 hy[4];
#pragma unroll
    for (int t = 0; t < 4; ++t) {
        C2 a = {0.f, 0.f};
#pragma unroll
        for (int r = 0; r < 4; ++r) { C2 p = cmulc(H[r][t], yv[r]); a.x += p.x; a.y += p.y; }
        hy[t] = a;
    }
#pragma unroll
    for (int t = 0; t < 4; ++t) {
        C2 a = {0.f, 0.f};
#pragma unroll
        for (int k = 0; k < 4; ++k) { C2 p = cmul(Ainv[t][k], hy[k]); a.x += p.x; a.y += p.y; }
        xeq1out[nbase + t * 2]     = a.x;
        xeq1out[nbase + t * 2 + 1] = a.y;
    }
    float* hyp = &g_HY[((long)(b * 64 + f)) * 40];
#pragma unroll
    for (int r = 0; r < 4; ++r)
#pragma unroll
        for (int t = 0; t < 4; ++t) {
            hyp[(r * 4 + t) * 2]     = H[r][t].x;
            hyp[(r * 4 + t) * 2 + 1] = H[r][t].y;
        }
#pragma unroll
    for (int r = 0; r < 4; ++r) {
        hyp[32 + r * 2]     = yv[r].x;
        hyp[32 + r * 2 + 1] = yv[r].y;
    }
}

__global__ __launch_bounds__(256) void res3_add_kernel(
    const float* __restrict__ r2, const float* __restrict__ W3,
    const float* __restrict__ b3, const float* __restrict__ xeq1,
    float* __restrict__ xequ)
{
    __shared__ float wt[8][256];
    __shared__ float bs[8];
    const int tid = threadIdx.x;
    if (tid < 8) bs[tid] = b3[tid];
#pragma unroll
    for (int j = 0; j < 8; ++j)
        wt[j][tid] = W3[tid * 8 + j];
    __syncthreads();

    const int warp = tid >> 5, lane = tid & 31;
    const long row = (long)blockIdx.x * 8 + warp;
    const float* rp = r2 + row * 256;
    float acc[8] = {};
#pragma unroll
    for (int ii = 0; ii < 8; ++ii) {
        const int i = ii * 32 + lane;
        const float rv = rp[i];
#pragma unroll
        for (int j = 0; j < 8; ++j) acc[j] = fmaf(rv, wt[j][i], acc[j]);
    }
#pragma unroll
    for (int j = 0; j < 8; ++j)
#pragma unroll
        for (int o = 16; o; o >>= 1) acc[j] += __shfl_xor_sync(0xffffffffu, acc[j], o);
    if (lane == 0) {
        const long ob = row * 8;
#pragma unroll
        for (int j = 0; j < 8; ++j)
            xequ[ob + j] = xeq1[ob + j] + acc[j] + bs[j];
    }
}

__global__ void emit_kernel(const float* __restrict__ src, float* __restrict__ out,
                            long off, long n, long out_size, int mode) {
    const long i = (long)blockIdx.x * blockDim.x + threadIdx.x;
    if (i >= n) return;
    const long o = off + i;
    if (o >= out_size) return;
    out[o] = (mode == 0) ? src[i] : src[2 * i];
}

extern "C" void kernel_launch(void* const* d_in, const int* in_sizes, int n_in,
                              void* d_out, int out_size) {
    const float* x        = (const float*)d_in[0];
    const int*   snr      = (const int*)  d_in[1];
    const float* H_ri     = (const float*)d_in[2];
    const float* noise_ri = (const float*)d_in[3];
    const float* enc_W1 = (const float*)d_in[4];  const float* enc_b1 = (const float*)d_in[5];
    const float* enc_g1 = (const float*)d_in[6];  const float* enc_be1= (const float*)d_in[7];
    const float* enc_W2 = (const float*)d_in[8];  const float* enc_b2 = (const float*)d_in[9];
    const float* enc_g2 = (const float*)d_in[10]; const float* enc_be2= (const float*)d_in[11];
    const float* enc_W3 = (const float*)d_in[12]; const float* enc_b3 = (const float*)d_in[13];
    const float* dec_W1 = (const float*)d_in[14]; const float* dec_b1 = (const float*)d_in[15];
    const float* dec_g1 = (const float*)d_in[16]; const float* dec_be1= (const float*)d_in[17];
    const float* dec_W2 = (const float*)d_in[18]; const float* dec_b2 = (const float*)d_in[19];
    const float* dec_g2 = (const float*)d_in[20]; const float* dec_be2= (const float*)d_in[21];
    const float* dec_W3 = (const float*)d_in[22]; const float* dec_b3 = (const float*)d_in[23];
    const float* res_W1 = (const float*)d_in[24]; const float* res_b1 = (const float*)d_in[25];
    const float* res_W2 = (const float*)d_in[26]; const float* res_b2 = (const float*)d_in[27];
    const float* res_W3 = (const float*)d_in[28]; const float* res_b3 = (const float*)d_in[29];

    float *h1, *h2, *e, *hd1, *hd2, *HY, *r1, *r2;
    float *Ps, *ys, *xequs, *xeq1s, *sigs;
    float *W2e, *b2e, *W3e, *b3e, *W2d, *b2d, *W3d, *b3d, *part;
    cudaGetSymbolAddress((void**)&h1,  g_h1);
    cudaGetSymbolAddress((void**)&h2,  g_h2);
    cudaGetSymbolAddress((void**)&e,   g_e);
    cudaGetSymbolAddress((void**)&hd1, g_hd1);
    cudaGetSymbolAddress((void**)&hd2, g_hd2);
    cudaGetSymbolAddress((void**)&HY,  g_HY);
    cudaGetSymbolAddress((void**)&r1,  g_r1);
    cudaGetSymbolAddress((void**)&r2,  g_r2);
    cudaGetSymbolAddress((void**)&Ps,    g_P);
    cudaGetSymbolAddress((void**)&ys,    g_y);
    cudaGetSymbolAddress((void**)&xequs, g_xequ);
    cudaGetSymbolAddress((void**)&xeq1s, g_xeq1);
    cudaGetSymbolAddress((void**)&sigs,  g_sig);
    cudaGetSymbolAddress((void**)&W2e, g_W2e); cudaGetSymbolAddress((void**)&b2e, g_b2e);
    cudaGetSymbolAddress((void**)&W3e, g_W3e); cudaGetSymbolAddress((void**)&b3e, g_b3e);
    cudaGetSymbolAddress((void**)&W2d, g_W2d); cudaGetSymbolAddress((void**)&b2d, g_b2d);
    cudaGetSymbolAddress((void**)&W3d, g_W3d); cudaGetSymbolAddress((void**)&b3d, g_b3d);
    cudaGetSymbolAddress((void**)&part, g_part);

    float* out = (float*)d_out;
    const long LP = 2097152, LY = 4194304, LX = 4194304, LS = 4194304;
    const long FULL = LP + LY + LX + LX + LS;
    const bool direct = ((long)out_size == FULL);
    float* P    = direct ? out                     : Ps;
    float* y    = direct ? out + LP                : ys;
    float* xequ = direct ? out + LP + LY           : xequs;
    float* xeq1 = direct ? out + LP + LY + LX      : xeq1s;
    float* sig  = direct ? out + LP + LY + LX + LX : sigs;

    const int SMB3 = (2 * A_BUF3 + 2 * B_BUF3) * 4;  // 75776 B
    const int SMB1 = 4 * 2048 * 4;                   // 32768 B
    cudaFuncSetAttribute(mma_gemm3, cudaFuncAttributeMaxDynamicSharedMemorySize, SMB3);
    cudaFuncSetAttribute(mma_gemm1, cudaFuncAttributeMaxDynamicSharedMemorySize, SMB1);

    prep_kernel<<<1, 1>>>(snr);

    // ---- encoder (3xTF32) ----
    mma_gemm3<<<dim3(1, 64, 8), 512, SMB3>>>(x, 256, 32, enc_W1, 32 * 128, enc_b1, 128,
                                             h1, 1024, 128, 32, 128, 1);
    stats_kernel<<<dim3(8, 32), 128>>>(h1, 128, part);
    fuse_kernel<<<dim3(8, 8), 256>>>(enc_W2, enc_b2, enc_g1, enc_be1, 128, 128, W2e, b2e);
    mma_gemm3<<<dim3(1, 64, 8), 512, SMB3>>>(h1, 1024, 128, W2e, 128 * 128, b2e, 128,
                                             h2, 1024, 128, 128, 128, 1);
    stats_kernel<<<dim3(8, 32), 128>>>(h2, 128, part);
    fuse_kernel<<<dim3(8, 8), 256>>>(enc_W3, enc_b3, enc_g2, enc_be2, 128, 512, W3e, b3e);
    mma_gemm3<<<dim3(4, 64, 8), 512, SMB3>>>(h2, 1024, 128, W3e, 128 * 512, b3e, 512,
                                             e, 4096, 512, 128, 512, 0);
    combine_kernel<<<8192, 512>>>(sig);

    // ---- channel + MMSE ----
    channel_kernel<<<8192, 64>>>(H_ri, noise_ri, sig, y, xeq1);

    // ---- residual MLP (1xTF32, fragment-native kernel) ----
    mma_gemm1<<<dim3(2, 4096, 1), 256, SMB1>>>(HY, 40, 0, res_W1, 0, res_b1, 0,
                                               r1, 256, 0, 40, 256, 1);
    mma_gemm1<<<dim3(2, 4096, 1), 256, SMB1>>>(r1, 256, 0, res_W2, 0, res_b2, 0,
                                               r2, 256, 0, 256, 256, 1);
    res3_add_kernel<<<65536, 256>>>(r2, res_W3, res_b3, xeq1, xequ);

    // ---- decoder: dec1 3x, dec2 1x, dec3 1x ----
    mma_gemm3<<<dim3(2, 64, 8), 512, SMB3>>>(xequ, 512, 0, dec_W1, 512 * 256, dec_b1, 256,
                                             hd1, 2048, 256, 512, 256, 1);
    stats_kernel<<<dim3(8, 32), 256>>>(hd1, 256, part);
    fuse_kernel<<<dim3(8, 8), 256>>>(dec_W2, dec_b2, dec_g1, dec_be1, 256, 256, W2d, b2d);
    mma_gemm1<<<dim3(2, 64, 8), 256, SMB1>>>(hd1, 2048, 256, W2d, 256 * 256, b2d, 256,
                                             hd2, 2048, 256, 256, 256, 1);
    stats_kernel<<<dim3(8, 32), 256>>>(hd2, 256, part);
    fuse_kernel<<<dim3(8, 8), 256>>>(dec_W3, dec_b3, dec_g2, dec_be2, 256, 32, W3d, b3d);
    mma_gemm1<<<dim3(1, 64, 8), 256, SMB1>>>(hd2, 2048, 256, W3d, 256 * 32, b3d, 32,
                                             P, 256, 32, 256, 32, 0);

    // ---- fallback emission only if layout differs ----
    if (!direct) {
        const long osz = (long)out_size;
        auto emit = [&](const float* src, long off, long n, int mode) {
            if (off >= osz || n <= 0) return;
            long grid = (n + 255) / 256;
            emit_kernel<<<(unsigned)grid, 256>>>(src, out, off, n, osz, mode);
        };
        if (osz == LP + LY/2 + LX + LX + LS) {
            long off = 0;
            emit(P,    off, LP,   0); off += LP;
            emit(y,    off, LY/2, 1); off += LY/2;
            emit(xequ, off, LX,   0); off += LX;
            emit(xeq1, off, LX,   0); off += LX;
            emit(sig,  off, LS,   0);
        } else {
            long off = 0;
            emit(P,    off, LP, 0); off += LP;
            emit(y,    off, LY, 0); off += LY;
            emit(xequ, off, LX, 0); off += LX;
            emit(xeq1, off, LX, 0); off += LX;
            emit(sig,  off, LS, 0);
        }
    }
}

// round 12
// speedup vs baseline: 1.2118x; 1.2118x over previous
#include <cuda_runtime.h>
#include <math.h>
#include <stdint.h>

#define Bsz 8192
#define Vn  8
#define FcN 64
#define BNEPS 1e-5f

__device__ float g_h1 [(size_t)Bsz*Vn*128];
__device__ float g_h2 [(size_t)Bsz*Vn*128];
__device__ float g_e  [(size_t)Bsz*Vn*512];
__device__ float g_hd1[(size_t)Bsz*Vn*256];
__device__ float g_hd2[(size_t)Bsz*Vn*256];
__device__ float g_HY [(size_t)Bsz*FcN*40];
__device__ float g_r1 [(size_t)Bsz*FcN*256];
__device__ float g_r2 [(size_t)Bsz*FcN*256];
__device__ float g_P   [(size_t)Bsz*Vn*32];
__device__ float g_y   [(size_t)Bsz*FcN*8];
__device__ float g_xequ[(size_t)Bsz*FcN*8];
__device__ float g_xeq1[(size_t)Bsz*FcN*8];
__device__ float g_sig [(size_t)Bsz*512];
__device__ float g_W2e[Vn*128*128]; __device__ float g_b2e[Vn*128];
__device__ float g_W3e[Vn*128*512]; __device__ float g_b3e[Vn*512];
__device__ float g_W2d[Vn*256*256]; __device__ float g_b2d[Vn*256];
__device__ float g_W3d[Vn*256*32];  __device__ float g_b3d[Vn*32];
__device__ float g_part[32*Vn*256*2];
__device__ float g_consts[4];

__device__ __forceinline__ uint32_t f2tf32(float f) {
    uint32_t r; asm("cvt.rna.tf32.f32 %0, %1;" : "=r"(r) : "f"(f)); return r;
}
__device__ __forceinline__ void split_tf32(float f, uint32_t& hi, uint32_t& lo) {
    hi = f2tf32(f);
    lo = f2tf32(f - __uint_as_float(hi));
}
__device__ __forceinline__ void mma8(float* c, const uint32_t* a, const uint32_t* b) {
    asm volatile(
        "mma.sync.aligned.m16n8k8.row.col.f32.tf32.tf32.f32 "
        "{%0,%1,%2,%3}, {%4,%5,%6,%7}, {%8,%9}, {%0,%1,%2,%3};"
        : "+f"(c[0]), "+f"(c[1]), "+f"(c[2]), "+f"(c[3])
        : "r"(a[0]), "r"(a[1]), "r"(a[2]), "r"(a[3]), "r"(b[0]), "r"(b[1]));
}

__global__ void prep_kernel(const int* __restrict__ snrp) {
    int iv = *snrp;
    float S;
    if (iv >= -1000 && iv <= 1000) S = (float)iv;
    else                            S = __int_as_float(iv);
    float snr = powf(10.f, -S * 0.1f);
    g_consts[0] = 4.f * snr;
    g_consts[1] = sqrtf(4.f * snr);
}

// ================= 3-term GEMM (round-7 proven): 512 thr, warp 32x32 ==========
#define AST 20
#define BST 136
#define AS_SZ   (128 * AST)
#define BS_SZ   (16 * BST)
#define A_BUF3  (2 * AS_SZ)
#define B_BUF3  (2 * BS_SZ)
#define BS_BASE3 (2 * A_BUF3)

__global__ __launch_bounds__(512) void mma_gemm3(
    const float* __restrict__ A, int lda, long sAv,
    const float* __restrict__ W, long sWv,
    const float* __restrict__ bias, int sbv,
    float* __restrict__ C, int ldc, long sCv,
    int K, int N, int relu)
{
    extern __shared__ uint32_t smem[];

    const int v = blockIdx.z;
    A    += (long)v * sAv;
    W    += (long)v * sWv;
    bias += (long)v * sbv;
    C    += (long)v * sCv;

    const long row0 = (long)blockIdx.y << 7;
    const int  col0 = blockIdx.x << 7;

    const int tid  = threadIdx.x;
    const int lane = tid & 31;
    const int wid  = tid >> 5;
    const int m0 = (wid & 3) << 5;
    const int n0 = (wid >> 2) << 5;

    const int ar  = tid >> 2;
    const int akq = (tid & 3) << 2;
    const int bk  = tid >> 5;
    const int bnq = (tid & 31) << 2;
    const bool bok = (col0 + bnq) < N;

    const float* Ap = A + (row0 + ar) * (long)lda;
    const float* Wp = W + (long)col0 + bnq;

    const int nch = (K + 15) >> 4;

    auto store_tiles = [&](int nb, float4 a4, float4 b4) {
        uint32_t* ash = smem + nb * A_BUF3 + ar * AST + akq;
        uint32_t* asl = ash + AS_SZ;
        split_tf32(a4.x, ash[0], asl[0]); split_tf32(a4.y, ash[1], asl[1]);
        split_tf32(a4.z, ash[2], asl[2]); split_tf32(a4.w, ash[3], asl[3]);
        uint32_t* bsh = smem + BS_BASE3 + nb * B_BUF3 + bk * BST + bnq;
        uint32_t* bsl = bsh + BS_SZ;
        split_tf32(b4.x, bsh[0], bsl[0]); split_tf32(b4.y, bsh[1], bsl[1]);
        split_tf32(b4.z, bsh[2], bsl[2]); split_tf32(b4.w, bsh[3], bsl[3]);
    };

    {
        float4 a4 = make_float4(0.f, 0.f, 0.f, 0.f);
        if (akq < K) a4 = *(const float4*)(Ap + akq);
        float4 b4 = make_float4(0.f, 0.f, 0.f, 0.f);
        if (bok && bk < K) b4 = *(const float4*)(Wp + (long)bk * N);
        store_tiles(0, a4, b4);
    }
    __syncthreads();

    float c[2][4][4] = {};
    int buf = 0;
    for (int ch = 0; ch < nch; ++ch) {
        float4 a4 = make_float4(0.f, 0.f, 0.f, 0.f);
        float4 b4 = make_float4(0.f, 0.f, 0.f, 0.f);
        const int nk0 = (ch + 1) << 4;
        const bool more = (ch + 1) < nch;
        if (more) {
            if (nk0 + akq < K) a4 = *(const float4*)(Ap + nk0 + akq);
            if (bok && (nk0 + bk) < K) b4 = *(const float4*)(Wp + (long)(nk0 + bk) * N);
        }

        const uint32_t* asb = smem + buf * A_BUF3 + (m0 + (lane >> 2)) * AST + (lane & 3);
        const uint32_t* bsb = smem + BS_BASE3 + buf * B_BUF3 + (lane & 3) * BST + n0 + (lane >> 2);
#pragma unroll
        for (int kk = 0; kk < 2; ++kk) {
            uint32_t ah[2][4], al[2][4];
#pragma unroll
            for (int i = 0; i < 2; ++i) {
                const uint32_t* p = asb + (i << 4) * AST + (kk << 3);
                ah[i][0] = p[0];
                ah[i][1] = p[8 * AST];
                ah[i][2] = p[4];
                ah[i][3] = p[8 * AST + 4];
                const uint32_t* pl = p + AS_SZ;
                al[i][0] = pl[0];
                al[i][1] = pl[8 * AST];
                al[i][2] = pl[4];
                al[i][3] = pl[8 * AST + 4];
            }
            uint32_t bh[4][2], bl[4][2];
#pragma unroll
            for (int j = 0; j < 4; ++j) {
                const uint32_t* q = bsb + (kk << 3) * BST + (j << 3);
                bh[j][0] = q[0];
                bh[j][1] = q[4 * BST];
                const uint32_t* ql = q + BS_SZ;
                bl[j][0] = ql[0];
                bl[j][1] = ql[4 * BST];
            }
#pragma unroll
            for (int i = 0; i < 2; ++i)
#pragma unroll
                for (int j = 0; j < 4; ++j) {
                    mma8(c[i][j], al[i], bh[j]);
                    mma8(c[i][j], ah[i], bl[j]);
                    mma8(c[i][j], ah[i], bh[j]);
                }
        }

        if (more) store_tiles(buf ^ 1, a4, b4);
        __syncthreads();
        buf ^= 1;
    }

#pragma unroll
    for (int i = 0; i < 2; ++i) {
        const long row = row0 + m0 + (i << 4) + (lane >> 2);
#pragma unroll
        for (int j = 0; j < 4; ++j) {
            const int col = col0 + n0 + (j << 3) + ((lane & 3) << 1);
            if (col < N) {
                const float2 bv = *(const float2*)(bias + col);
                float v0 = c[i][j][0] + bv.x;
                float v1 = c[i][j][1] + bv.y;
                float v2 = c[i][j][2] + bv.x;
                float v3 = c[i][j][3] + bv.y;
                if (relu) {
                    v0 = fmaxf(v0, 0.f); v1 = fmaxf(v1, 0.f);
                    v2 = fmaxf(v2, 0.f); v3 = fmaxf(v3, 0.f);
                }
                float2 o0 = {v0, v1}, o1 = {v2, v3};
                *(float2*)(C + row * (long)ldc + col)       = o0;
                *(float2*)(C + (row + 8) * (long)ldc + col) = o1;
            }
        }
    }
}

// ========= 1-term GEMM: 512 thr, warp 32x32, K-chunk 32 (latency-hiding) ======
// A smem: [128 rows][32 k], row stride 36 (banks 4r%32 distinct per 8 rows).
// B smem: [32 k][128 n], row stride 136 (proven conflict-free).
#define AST1 36
#define A_BUF1 (128 * AST1)     // 4608 u32
#define B_BUF1 (32 * BST)       // 4352 u32
#define BS_BASE1 (2 * A_BUF1)   // 9216

__global__ __launch_bounds__(512) void mma_gemm1(
    const float* __restrict__ A, int lda, long sAv,
    const float* __restrict__ W, long sWv,
    const float* __restrict__ bias, int sbv,
    float* __restrict__ C, int ldc, long sCv,
    int K, int N, int relu)
{
    extern __shared__ uint32_t smem[];

    const int v = blockIdx.z;
    A    += (long)v * sAv;
    W    += (long)v * sWv;
    bias += (long)v * sbv;
    C    += (long)v * sCv;

    const long row0 = (long)blockIdx.y << 7;
    const int  col0 = blockIdx.x << 7;

    const int tid  = threadIdx.x;
    const int lane = tid & 31;
    const int wid  = tid >> 5;
    const int m0 = (wid & 3) << 5;
    const int n0 = (wid >> 2) << 5;

    const int ar  = tid >> 2;
    const int akq = (tid & 3) << 2;
    const int bk  = tid >> 5;
    const int bnq = (tid & 31) << 2;
    const bool bok = (col0 + bnq) < N;

    const float* Ap = A + (row0 + ar) * (long)lda;
    const float* Wp = W + (long)col0 + bnq;

    const int nch = (K + 31) >> 5;   // 32-wide chunks

    auto load_pair = [&](int k0, float4* a4, float4* b4) {
#pragma unroll
        for (int s = 0; s < 2; ++s) {
            const int ka = k0 + (s << 4);
            a4[s] = make_float4(0.f, 0.f, 0.f, 0.f);
            if (ka + akq < K) a4[s] = *(const float4*)(Ap + ka + akq);
            b4[s] = make_float4(0.f, 0.f, 0.f, 0.f);
            if (bok && (ka + bk) < K) b4[s] = *(const float4*)(Wp + (long)(ka + bk) * N);
        }
    };

    auto store_tiles = [&](int nb, const float4* a4, const float4* b4) {
        uint32_t* ab = smem + nb * A_BUF1 + ar * AST1 + akq;
        uint32_t* bb = smem + BS_BASE1 + nb * B_BUF1 + bk * BST + bnq;
#pragma unroll
        for (int s = 0; s < 2; ++s) {
            uint32_t* a = ab + (s << 4);
            a[0] = f2tf32(a4[s].x); a[1] = f2tf32(a4[s].y);
            a[2] = f2tf32(a4[s].z); a[3] = f2tf32(a4[s].w);
            uint32_t* b = bb + (s << 4) * BST;
            b[0] = f2tf32(b4[s].x); b[1] = f2tf32(b4[s].y);
            b[2] = f2tf32(b4[s].z); b[3] = f2tf32(b4[s].w);
        }
    };

    {
        float4 a4[2], b4[2];
        load_pair(0, a4, b4);
        store_tiles(0, a4, b4);
    }
    __syncthreads();

    float c[2][4][4] = {};
    int buf = 0;
    for (int ch = 0; ch < nch; ++ch) {
        float4 a4[2], b4[2];
        const bool more = (ch + 1) < nch;
        if (more) load_pair((ch + 1) << 5, a4, b4);

        const uint32_t* asb = smem + buf * A_BUF1 + (m0 + (lane >> 2)) * AST1 + (lane & 3);
        const uint32_t* bsb = smem + BS_BASE1 + buf * B_BUF1 + (lane & 3) * BST + n0 + (lane >> 2);
#pragma unroll
        for (int kk = 0; kk < 4; ++kk) {
            uint32_t ah[2][4];
#pragma unroll
            for (int i = 0; i < 2; ++i) {
                const uint32_t* p = asb + (i << 4) * AST1 + (kk << 3);
                ah[i][0] = p[0];
                ah[i][1] = p[8 * AST1];
                ah[i][2] = p[4];
                ah[i][3] = p[8 * AST1 + 4];
            }
            uint32_t bh[4][2];
#pragma unroll
            for (int j = 0; j < 4; ++j) {
                const uint32_t* q = bsb + (kk << 3) * BST + (j << 3);
                bh[j][0] = q[0];
                bh[j][1] = q[4 * BST];
            }
#pragma unroll
            for (int i = 0; i < 2; ++i)
#pragma unroll
                for (int j = 0; j < 4; ++j)
                    mma8(c[i][j], ah[i], bh[j]);
        }

        if (more) store_tiles(buf ^ 1, a4, b4);
        __syncthreads();
        buf ^= 1;
    }

#pragma unroll
    for (int i = 0; i < 2; ++i) {
        const long row = row0 + m0 + (i << 4) + (lane >> 2);
#pragma unroll
        for (int j = 0; j < 4; ++j) {
            const int col = col0 + n0 + (j << 3) + ((lane & 3) << 1);
            if (col < N) {
                const float2 bv = *(const float2*)(bias + col);
                float v0 = c[i][j][0] + bv.x;
                float v1 = c[i][j][1] + bv.y;
                float v2 = c[i][j][2] + bv.x;
                float v3 = c[i][j][3] + bv.y;
                if (relu) {
                    v0 = fmaxf(v0, 0.f); v1 = fmaxf(v1, 0.f);
                    v2 = fmaxf(v2, 0.f); v3 = fmaxf(v3, 0.f);
                }
                float2 o0 = {v0, v1}, o1 = {v2, v3};
                *(float2*)(C + row * (long)ldc + col)       = o0;
                *(float2*)(C + (row + 8) * (long)ldc + col) = o1;
            }
        }
    }
}

__global__ void stats_kernel(const float* __restrict__ h, int C, float* __restrict__ part) {
    const int v = blockIdx.x, s = blockIdx.y, c = threadIdx.x;
    const long stride = (long)Vn * C;
    const float* p = h + ((long)(s * 256) * Vn + v) * C + c;
    float sum = 0.f, sq = 0.f;
#pragma unroll 4
    for (int i = 0; i < 256; ++i) {
        float val = p[(long)i * stride];
        sum += val;
        sq = fmaf(val, val, sq);
    }
    const long o = (((long)s * Vn + v) * C + c) * 2;
    part[o] = sum; part[o + 1] = sq;
}

__global__ void fuse_kernel(const float* __restrict__ W, const float* __restrict__ bias,
                            const float* __restrict__ g, const float* __restrict__ be,
                            int Cin, int Nout,
                            float* __restrict__ Wp, float* __restrict__ bp)
{
    const int v = blockIdx.x, tid = threadIdx.x;
    __shared__ float sa[512], sc[512];
    for (int n = tid; n < Cin; n += blockDim.x) {
        float sum = 0.f, sq = 0.f;
        for (int s = 0; s < 32; ++s) {
            const long o = (((long)s * Vn + v) * Cin + n) * 2;
            sum += g_part[o]; sq += g_part[o + 1];
        }
        const float mu  = sum * (1.f / Bsz);
        const float var = sq * (1.f / Bsz) - mu * mu;
        const float rs  = rsqrtf(var + BNEPS);
        const float a   = g[v * Cin + n] * rs;
        sa[n] = a;
        sc[n] = be[v * Cin + n] - mu * a;
    }
    __syncthreads();
    const int slice = (Nout + gridDim.y - 1) / gridDim.y;
    const int j0 = blockIdx.y * slice;
    const int j1 = min(j0 + slice, Nout);
    const float* wv = W + (long)v * Cin * Nout;
    float* wpv = Wp + (long)v * Cin * Nout;
    for (int j = j0 + tid; j < j1; j += blockDim.x) {
        float acc = bias[v * Nout + j];
        for (int n = 0; n < Cin; ++n) {
            const float w = wv[(long)n * Nout + j];
            wpv[(long)n * Nout + j] = sa[n] * w;
            acc = fmaf(sc[n], w, acc);
        }
        bp[v * Nout + j] = acc;
    }
}

__global__ void combine_kernel(float* __restrict__ enc_sig) {
    const int b = blockIdx.x;
    const int d = threadIdx.x;
    __shared__ float red[16];
    __shared__ float tot_s;
    float acc = 0.f;
#pragma unroll
    for (int v = 0; v < Vn; ++v) {
        const float ev = g_e[((long)b * Vn + v) * 512 + d];
        float s = ev * ev;
#pragma unroll
        for (int o = 16; o; o >>= 1) s += __shfl_xor_sync(0xffffffffu, s, o);
        if ((d & 31) == 0) red[d >> 5] = s;
        __syncthreads();
        if (d < 32) {
            float t = (d < 16) ? red[d] : 0.f;
#pragma unroll
            for (int o = 8; o; o >>= 1) t += __shfl_xor_sync(0xffffffffu, t, o);
            if (d == 0) tot_s = t;
        }
        __syncthreads();
        const float alpha = 8.f * rsqrtf(tot_s);
        acc = fmaf(alpha, ev, acc);
        __syncthreads();
    }
    enc_sig[(long)b * 512 + d] = acc * 0.70710678118654752f;
}

struct C2 { float x, y; };
__device__ __forceinline__ C2 cmul(C2 a, C2 b) { return {a.x*b.x - a.y*b.y, a.x*b.y + a.y*b.x}; }
__device__ __forceinline__ C2 cmulc(C2 a, C2 b) { return {a.x*b.x + a.y*b.y, a.x*b.y - a.y*b.x}; }

__global__ void channel_kernel(const float* __restrict__ Hri, const float* __restrict__ noiseri,
                               const float* __restrict__ encsig,
                               float* __restrict__ yout, float* __restrict__ xeq1out)
{
    const int b = blockIdx.x;
    const int f = threadIdx.x;
    __shared__ C2 H[4][4];
    __shared__ C2 Ainv[4][4];
    const float is2 = 0.70710678118654752f;

    if (f < 16) {
        const int r = f >> 2, t = f & 3;
        const long o = (((long)(b * 4 + r)) * 4 + t) * 2;
        H[r][t] = {Hri[o] * is2, Hri[o + 1] * is2};
    }
    __syncthreads();

    const float lam = g_consts[0];
    const float nsc = g_consts[1];

    if (f == 0) {
        C2 Am[4][8];
        for (int i = 0; i < 4; ++i) {
            for (int j = 0; j < 4; ++j) {
                C2 a = {0.f, 0.f};
                for (int r = 0; r < 4; ++r) {
                    C2 p = cmulc(H[r][i], H[r][j]);
                    a.x += p.x; a.y += p.y;
                }
                if (i == j) a.x += lam;
                Am[i][j] = a;
                Am[i][4 + j] = (i == j) ? C2{1.f, 0.f} : C2{0.f, 0.f};
            }
        }
        for (int p = 0; p < 4; ++p) {
            C2 dg = Am[p][p];
            const float inv = 1.f / (dg.x * dg.x + dg.y * dg.y);
            const C2 dinv = {dg.x * inv, -dg.y * inv};
            for (int j = 0; j < 8; ++j) Am[p][j] = cmul(Am[p][j], dinv);
            for (int r = 0; r < 4; ++r) {
                if (r == p) continue;
                const C2 fac = Am[r][p];
                for (int j = 0; j < 8; ++j) {
                    const C2 q = cmul(fac, Am[p][j]);
                    Am[r][j].x -= q.x; Am[r][j].y -= q.y;
                }
            }
        }
        for (int i = 0; i < 4; ++i)
            for (int j = 0; j < 4; ++j)
                Ainv[i][j] = Am[i][4 + j];
    }
    __syncthreads();

    C2 s[4];
#pragma unroll
    for (int t = 0; t < 4; ++t) {
        const long o = ((long)b * 512) + ((long)(f * 4 + t)) * 2;
        s[t] = {encsig[o], encsig[o + 1]};
    }
    const long nbase = ((long)(b * 64 + f)) * 8;
    C2 yv[4];
#pragma unroll
    for (int r = 0; r < 4; ++r) {
        C2 a = {0.f, 0.f};
#pragma unroll
        for (int t = 0; t < 4; ++t) { C2 p = cmul(H[r][t], s[t]); a.x += p.x; a.y += p.y; }
        a.x += nsc * noiseri[nbase + r * 2]     * is2;
        a.y += nsc * noiseri[nbase + r * 2 + 1] * is2;
        yv[r] = a;
        yout[nbase + r * 2]     = a.x;
        yout[nbase + r * 2 + 1] = a.y;
    }
    C2 hy[4];
#pragma unroll
    for (int t = 0; t < 4; ++t) {
        C2 a = {0.f, 0.f};
#pragma unroll
        for (int r = 0; r < 4; ++r) { C2 p = cmulc(H[r][t], yv[r]); a.x += p.x; a.y += p.y; }
        hy[t] = a;
    }
#pragma unroll
    for (int t = 0; t < 4; ++t) {
        C2 a = {0.f, 0.f};
#pragma unroll
        for (int k = 0; k < 4; ++k) { C2 p = cmul(Ainv[t][k], hy[k]); a.x += p.x; a.y += p.y; }
        xeq1out[nbase + t * 2]     = a.x;
        xeq1out[nbase + t * 2 + 1] = a.y;
    }
    float* hyp = &g_HY[((long)(b * 64 + f)) * 40];
#pragma unroll
    for (int r = 0; r < 4; ++r)
#pragma unroll
        for (int t = 0; t < 4; ++t) {
            hyp[(r * 4 + t) * 2]     = H[r][t].x;
            hyp[(r * 4 + t) * 2 + 1] = H[r][t].y;
        }
#pragma unroll
    for (int r = 0; r < 4; ++r) {
        hyp[32 + r * 2]     = yv[r].x;
        hyp[32 + r * 2 + 1] = yv[r].y;
    }
}

__global__ __launch_bounds__(256) void res3_add_kernel(
    const float* __restrict__ r2, const float* __restrict__ W3,
    const float* __restrict__ b3, const float* __restrict__ xeq1,
    float* __restrict__ xequ)
{
    __shared__ float wt[8][256];
    __shared__ float bs[8];
    const int tid = threadIdx.x;
    if (tid < 8) bs[tid] = b3[tid];
#pragma unroll
    for (int j = 0; j < 8; ++j)
        wt[j][tid] = W3[tid * 8 + j];
    __syncthreads();

    const int warp = tid >> 5, lane = tid & 31;
    const long row = (long)blockIdx.x * 8 + warp;
    const float* rp = r2 + row * 256;
    float acc[8] = {};
#pragma unroll
    for (int ii = 0; ii < 8; ++ii) {
        const int i = ii * 32 + lane;
        const float rv = rp[i];
#pragma unroll
        for (int j = 0; j < 8; ++j) acc[j] = fmaf(rv, wt[j][i], acc[j]);
    }
#pragma unroll
    for (int j = 0; j < 8; ++j)
#pragma unroll
        for (int o = 16; o; o >>= 1) acc[j] += __shfl_xor_sync(0xffffffffu, acc[j], o);
    if (lane == 0) {
        const long ob = row * 8;
#pragma unroll
        for (int j = 0; j < 8; ++j)
            xequ[ob + j] = xeq1[ob + j] + acc[j] + bs[j];
    }
}

__global__ void emit_kernel(const float* __restrict__ src, float* __restrict__ out,
                            long off, long n, long out_size, int mode) {
    const long i = (long)blockIdx.x * blockDim.x + threadIdx.x;
    if (i >= n) return;
    const long o = off + i;
    if (o >= out_size) return;
    out[o] = (mode == 0) ? src[i] : src[2 * i];
}

extern "C" void kernel_launch(void* const* d_in, const int* in_sizes, int n_in,
                              void* d_out, int out_size) {
    const float* x        = (const float*)d_in[0];
    const int*   snr      = (const int*)  d_in[1];
    const float* H_ri     = (const float*)d_in[2];
    const float* noise_ri = (const float*)d_in[3];
    const float* enc_W1 = (const float*)d_in[4];  const float* enc_b1 = (const float*)d_in[5];
    const float* enc_g1 = (const float*)d_in[6];  const float* enc_be1= (const float*)d_in[7];
    const float* enc_W2 = (const float*)d_in[8];  const float* enc_b2 = (const float*)d_in[9];
    const float* enc_g2 = (const float*)d_in[10]; const float* enc_be2= (const float*)d_in[11];
    const float* enc_W3 = (const float*)d_in[12]; const float* enc_b3 = (const float*)d_in[13];
    const float* dec_W1 = (const float*)d_in[14]; const float* dec_b1 = (const float*)d_in[15];
    const float* dec_g1 = (const float*)d_in[16]; const float* dec_be1= (const float*)d_in[17];
    const float* dec_W2 = (const float*)d_in[18]; const float* dec_b2 = (const float*)d_in[19];
    const float* dec_g2 = (const float*)d_in[20]; const float* dec_be2= (const float*)d_in[21];
    const float* dec_W3 = (const float*)d_in[22]; const float* dec_b3 = (const float*)d_in[23];
    const float* res_W1 = (const float*)d_in[24]; const float* res_b1 = (const float*)d_in[25];
    const float* res_W2 = (const float*)d_in[26]; const float* res_b2 = (const float*)d_in[27];
    const float* res_W3 = (const float*)d_in[28]; const float* res_b3 = (const float*)d_in[29];

    float *h1, *h2, *e, *hd1, *hd2, *HY, *r1, *r2;
    float *Ps, *ys, *xequs, *xeq1s, *sigs;
    float *W2e, *b2e, *W3e, *b3e, *W2d, *b2d, *W3d, *b3d, *part;
    cudaGetSymbolAddress((void**)&h1,  g_h1);
    cudaGetSymbolAddress((void**)&h2,  g_h2);
    cudaGetSymbolAddress((void**)&e,   g_e);
    cudaGetSymbolAddress((void**)&hd1, g_hd1);
    cudaGetSymbolAddress((void**)&hd2, g_hd2);
    cudaGetSymbolAddress((void**)&HY,  g_HY);
    cudaGetSymbolAddress((void**)&r1,  g_r1);
    cudaGetSymbolAddress((void**)&r2,  g_r2);
    cudaGetSymbolAddress((void**)&Ps,    g_P);
    cudaGetSymbolAddress((void**)&ys,    g_y);
    cudaGetSymbolAddress((void**)&xequs, g_xequ);
    cudaGetSymbolAddress((void**)&xeq1s, g_xeq1);
    cudaGetSymbolAddress((void**)&sigs,  g_sig);
    cudaGetSymbolAddress((void**)&W2e, g_W2e); cudaGetSymbolAddress((void**)&b2e, g_b2e);
    cudaGetSymbolAddress((void**)&W3e, g_W3e); cudaGetSymbolAddress((void**)&b3e, g_b3e);
    cudaGetSymbolAddress((void**)&W2d, g_W2d); cudaGetSymbolAddress((void**)&b2d, g_b2d);
    cudaGetSymbolAddress((void**)&W3d, g_W3d); cudaGetSymbolAddress((void**)&b3d, g_b3d);
    cudaGetSymbolAddress((void**)&part, g_part);

    float* out = (float*)d_out;
    const long LP = 2097152, LY = 4194304, LX = 4194304, LS = 4194304;
    const long FULL = LP + LY + LX + LX + LS;
    const bool direct = ((long)out_size == FULL);
    float* P    = direct ? out                     : Ps;
    float* y    = direct ? out + LP                : ys;
    float* xequ = direct ? out + LP + LY           : xequs;
    float* xeq1 = direct ? out + LP + LY + LX      : xeq1s;
    float* sig  = direct ? out + LP + LY + LX + LX : sigs;

    const int SMB3 = (2 * A_BUF3 + 2 * B_BUF3) * 4;   // 75776 B
    const int SMB1 = (2 * A_BUF1 + 2 * B_BUF1) * 4;   // 71680 B
    cudaFuncSetAttribute(mma_gemm3, cudaFuncAttributeMaxDynamicSharedMemorySize, SMB3);
    cudaFuncSetAttribute(mma_gemm1, cudaFuncAttributeMaxDynamicSharedMemorySize, SMB1);

    prep_kernel<<<1, 1>>>(snr);

    // ---- encoder (3xTF32) ----
    mma_gemm3<<<dim3(1, 64, 8), 512, SMB3>>>(x, 256, 32, enc_W1, 32 * 128, enc_b1, 128,
                                             h1, 1024, 128, 32, 128, 1);
    stats_kernel<<<dim3(8, 32), 128>>>(h1, 128, part);
    fuse_kernel<<<dim3(8, 8), 256>>>(enc_W2, enc_b2, enc_g1, enc_be1, 128, 128, W2e, b2e);
    mma_gemm3<<<dim3(1, 64, 8), 512, SMB3>>>(h1, 1024, 128, W2e, 128 * 128, b2e, 128,
                                             h2, 1024, 128, 128, 128, 1);
    stats_kernel<<<dim3(8, 32), 128>>>(h2, 128, part);
    fuse_kernel<<<dim3(8, 8), 256>>>(enc_W3, enc_b3, enc_g2, enc_be2, 128, 512, W3e, b3e);
    mma_gemm3<<<dim3(4, 64, 8), 512, SMB3>>>(h2, 1024, 128, W3e, 128 * 512, b3e, 512,
                                             e, 4096, 512, 128, 512, 0);
    combine_kernel<<<8192, 512>>>(sig);

    // ---- channel + MMSE ----
    channel_kernel<<<8192, 64>>>(H_ri, noise_ri, sig, y, xeq1);

    // ---- residual MLP (1xTF32, K-chunk 32) ----
    mma_gemm1<<<dim3(2, 4096, 1), 512, SMB1>>>(HY, 40, 0, res_W1, 0, res_b1, 0,
                                               r1, 256, 0, 40, 256, 1);
    mma_gemm1<<<dim3(2, 4096, 1), 512, SMB1>>>(r1, 256, 0, res_W2, 0, res_b2, 0,
                                               r2, 256, 0, 256, 256, 1);
    res3_add_kernel<<<65536, 256>>>(r2, res_W3, res_b3, xeq1, xequ);

    // ---- decoder: dec1 3x, dec2 1x, dec3 1x ----
    mma_gemm3<<<dim3(2, 64, 8), 512, SMB3>>>(xequ, 512, 0, dec_W1, 512 * 256, dec_b1, 256,
                                             hd1, 2048, 256, 512, 256, 1);
    stats_kernel<<<dim3(8, 32), 256>>>(hd1, 256, part);
    fuse_kernel<<<dim3(8, 8), 256>>>(dec_W2, dec_b2, dec_g1, dec_be1, 256, 256, W2d, b2d);
    mma_gemm1<<<dim3(2, 64, 8), 512, SMB1>>>(hd1, 2048, 256, W2d, 256 * 256, b2d, 256,
                                             hd2, 2048, 256, 256, 256, 1);
    stats_kernel<<<dim3(8, 32), 256>>>(hd2, 256, part);
    fuse_kernel<<<dim3(8, 8), 256>>>(dec_W3, dec_b3, dec_g2, dec_be2, 256, 32, W3d, b3d);
    mma_gemm1<<<dim3(1, 64, 8), 512, SMB1>>>(hd2, 2048, 256, W3d, 256 * 32, b3d, 32,
                                             P, 256, 32, 256, 32, 0);

    // ---- fallback emission only if layout differs ----
    if (!direct) {
        const long osz = (long)out_size;
        auto emit = [&](const float* src, long off, long n, int mode) {
            if (off >= osz || n <= 0) return;
            long grid = (n + 255) / 256;
            emit_kernel<<<(unsigned)grid, 256>>>(src, out, off, n, osz, mode);
        };
        if (osz == LP + LY/2 + LX + LX + LS) {
            long off = 0;
            emit(P,    off, LP,   0); off += LP;
            emit(y,    off, LY/2, 1); off += LY/2;
            emit(xequ, off, LX,   0); off += LX;
            emit(xeq1, off, LX,   0); off += LX;
            emit(sig,  off, LS,   0);
        } else {
            long off = 0;
            emit(P,    off, LP, 0); off += LP;
            emit(y,    off, LY, 0); off += LY;
            emit(xequ, off, LX, 0); off += LX;
            emit(xeq1, off, LX, 0); off += LX;
            emit(sig,  off, LS, 0);
        }
    }
}

// round 13
// speedup vs baseline: 1.2800x; 1.0563x over previous
#include <cuda_runtime.h>
#include <math.h>
#include <stdint.h>

#define Bsz 8192
#define Vn  8
#define FcN 64
#define BNEPS 1e-5f

__device__ float g_h1 [(size_t)Bsz*Vn*128];
__device__ float g_h2 [(size_t)Bsz*Vn*128];
__device__ float g_e  [(size_t)Bsz*Vn*512];
__device__ float g_hd1[(size_t)Bsz*Vn*256];
__device__ float g_hd2[(size_t)Bsz*Vn*256];
__device__ float g_HY [(size_t)Bsz*FcN*40];
__device__ float g_r1 [(size_t)Bsz*FcN*256];
__device__ float g_r2 [(size_t)Bsz*FcN*256];
__device__ float g_P   [(size_t)Bsz*Vn*32];
__device__ float g_y   [(size_t)Bsz*FcN*8];
__device__ float g_xequ[(size_t)Bsz*FcN*8];
__device__ float g_xeq1[(size_t)Bsz*FcN*8];
__device__ float g_sig [(size_t)Bsz*512];
__device__ float g_W2e[Vn*128*128]; __device__ float g_b2e[Vn*128];
__device__ float g_W3e[Vn*128*512]; __device__ float g_b3e[Vn*512];
__device__ float g_W2d[Vn*256*256]; __device__ float g_b2d[Vn*256];
__device__ float g_W3d[Vn*256*32];  __device__ float g_b3d[Vn*32];
__device__ float g_part[32*Vn*256*2];
__device__ float g_consts[4];

__device__ __forceinline__ uint32_t f2tf32(float f) {
    uint32_t r; asm("cvt.rna.tf32.f32 %0, %1;" : "=r"(r) : "f"(f)); return r;
}
__device__ __forceinline__ void split_tf32(float f, uint32_t& hi, uint32_t& lo) {
    hi = f2tf32(f);
    lo = f2tf32(f - __uint_as_float(hi));
}
__device__ __forceinline__ void mma8(float* c, const uint32_t* a, const uint32_t* b) {
    asm volatile(
        "mma.sync.aligned.m16n8k8.row.col.f32.tf32.tf32.f32 "
        "{%0,%1,%2,%3}, {%4,%5,%6,%7}, {%8,%9}, {%0,%1,%2,%3};"
        : "+f"(c[0]), "+f"(c[1]), "+f"(c[2]), "+f"(c[3])
        : "r"(a[0]), "r"(a[1]), "r"(a[2]), "r"(a[3]), "r"(b[0]), "r"(b[1]));
}

__global__ void prep_kernel(const int* __restrict__ snrp) {
    int iv = *snrp;
    float S;
    if (iv >= -1000 && iv <= 1000) S = (float)iv;
    else                            S = __int_as_float(iv);
    float snr = powf(10.f, -S * 0.1f);
    g_consts[0] = 4.f * snr;
    g_consts[1] = sqrtf(4.f * snr);
}

// ================= 3-term GEMM (round-7 proven): 512 thr, warp 32x32 ==========
#define AST 20
#define BST 136
#define AS_SZ   (128 * AST)
#define BS_SZ   (16 * BST)
#define A_BUF3  (2 * AS_SZ)
#define B_BUF3  (2 * BS_SZ)
#define BS_BASE3 (2 * A_BUF3)

__global__ __launch_bounds__(512) void mma_gemm3(
    const float* __restrict__ A, int lda, long sAv,
    const float* __restrict__ W, long sWv,
    const float* __restrict__ bias, int sbv,
    float* __restrict__ C, int ldc, long sCv,
    int K, int N, int relu)
{
    extern __shared__ uint32_t smem[];

    const int v = blockIdx.z;
    A    += (long)v * sAv;
    W    += (long)v * sWv;
    bias += (long)v * sbv;
    C    += (long)v * sCv;

    const long row0 = (long)blockIdx.y << 7;
    const int  col0 = blockIdx.x << 7;

    const int tid  = threadIdx.x;
    const int lane = tid & 31;
    const int wid  = tid >> 5;
    const int m0 = (wid & 3) << 5;
    const int n0 = (wid >> 2) << 5;

    const int ar  = tid >> 2;
    const int akq = (tid & 3) << 2;
    const int bk  = tid >> 5;
    const int bnq = (tid & 31) << 2;
    const bool bok = (col0 + bnq) < N;

    const float* Ap = A + (row0 + ar) * (long)lda;
    const float* Wp = W + (long)col0 + bnq;

    const int nch = (K + 15) >> 4;

    auto store_tiles = [&](int nb, float4 a4, float4 b4) {
        uint32_t* ash = smem + nb * A_BUF3 + ar * AST + akq;
        uint32_t* asl = ash + AS_SZ;
        split_tf32(a4.x, ash[0], asl[0]); split_tf32(a4.y, ash[1], asl[1]);
        split_tf32(a4.z, ash[2], asl[2]); split_tf32(a4.w, ash[3], asl[3]);
        uint32_t* bsh = smem + BS_BASE3 + nb * B_BUF3 + bk * BST + bnq;
        uint32_t* bsl = bsh + BS_SZ;
        split_tf32(b4.x, bsh[0], bsl[0]); split_tf32(b4.y, bsh[1], bsl[1]);
        split_tf32(b4.z, bsh[2], bsl[2]); split_tf32(b4.w, bsh[3], bsl[3]);
    };

    {
        float4 a4 = make_float4(0.f, 0.f, 0.f, 0.f);
        if (akq < K) a4 = *(const float4*)(Ap + akq);
        float4 b4 = make_float4(0.f, 0.f, 0.f, 0.f);
        if (bok && bk < K) b4 = *(const float4*)(Wp + (long)bk * N);
        store_tiles(0, a4, b4);
    }
    __syncthreads();

    float c[2][4][4] = {};
    int buf = 0;
    for (int ch = 0; ch < nch; ++ch) {
        float4 a4 = make_float4(0.f, 0.f, 0.f, 0.f);
        float4 b4 = make_float4(0.f, 0.f, 0.f, 0.f);
        const int nk0 = (ch + 1) << 4;
        const bool more = (ch + 1) < nch;
        if (more) {
            if (nk0 + akq < K) a4 = *(const float4*)(Ap + nk0 + akq);
            if (bok && (nk0 + bk) < K) b4 = *(const float4*)(Wp + (long)(nk0 + bk) * N);
        }

        const uint32_t* asb = smem + buf * A_BUF3 + (m0 + (lane >> 2)) * AST + (lane & 3);
        const uint32_t* bsb = smem + BS_BASE3 + buf * B_BUF3 + (lane & 3) * BST + n0 + (lane >> 2);
#pragma unroll
        for (int kk = 0; kk < 2; ++kk) {
            uint32_t ah[2][4], al[2][4];
#pragma unroll
            for (int i = 0; i < 2; ++i) {
                const uint32_t* p = asb + (i << 4) * AST + (kk << 3);
                ah[i][0] = p[0];
                ah[i][1] = p[8 * AST];
                ah[i][2] = p[4];
                ah[i][3] = p[8 * AST + 4];
                const uint32_t* pl = p + AS_SZ;
                al[i][0] = pl[0];
                al[i][1] = pl[8 * AST];
                al[i][2] = pl[4];
                al[i][3] = pl[8 * AST + 4];
            }
            uint32_t bh[4][2], bl[4][2];
#pragma unroll
            for (int j = 0; j < 4; ++j) {
                const uint32_t* q = bsb + (kk << 3) * BST + (j << 3);
                bh[j][0] = q[0];
                bh[j][1] = q[4 * BST];
                const uint32_t* ql = q + BS_SZ;
                bl[j][0] = ql[0];
                bl[j][1] = ql[4 * BST];
            }
#pragma unroll
            for (int i = 0; i < 2; ++i)
#pragma unroll
                for (int j = 0; j < 4; ++j) {
                    mma8(c[i][j], al[i], bh[j]);
                    mma8(c[i][j], ah[i], bl[j]);
                    mma8(c[i][j], ah[i], bh[j]);
                }
        }

        if (more) store_tiles(buf ^ 1, a4, b4);
        __syncthreads();
        buf ^= 1;
    }

#pragma unroll
    for (int i = 0; i < 2; ++i) {
        const long row = row0 + m0 + (i << 4) + (lane >> 2);
#pragma unroll
        for (int j = 0; j < 4; ++j) {
            const int col = col0 + n0 + (j << 3) + ((lane & 3) << 1);
            if (col < N) {
                const float2 bv = *(const float2*)(bias + col);
                float v0 = c[i][j][0] + bv.x;
                float v1 = c[i][j][1] + bv.y;
                float v2 = c[i][j][2] + bv.x;
                float v3 = c[i][j][3] + bv.y;
                if (relu) {
                    v0 = fmaxf(v0, 0.f); v1 = fmaxf(v1, 0.f);
                    v2 = fmaxf(v2, 0.f); v3 = fmaxf(v3, 0.f);
                }
                float2 o0 = {v0, v1}, o1 = {v2, v3};
                *(float2*)(C + row * (long)ldc + col)       = o0;
                *(float2*)(C + (row + 8) * (long)ldc + col) = o1;
            }
        }
    }
}

// ========= 1-term GEMM: 512 thr, warp 32x32, K-chunk 32 (round-12 proven) =====
#define AST1 36
#define A_BUF1 (128 * AST1)
#define B_BUF1 (32 * BST)
#define BS_BASE1 (2 * A_BUF1)

__global__ __launch_bounds__(512) void mma_gemm1(
    const float* __restrict__ A, int lda, long sAv,
    const float* __restrict__ W, long sWv,
    const float* __restrict__ bias, int sbv,
    float* __restrict__ C, int ldc, long sCv,
    int K, int N, int relu)
{
    extern __shared__ uint32_t smem[];

    const int v = blockIdx.z;
    A    += (long)v * sAv;
    W    += (long)v * sWv;
    bias += (long)v * sbv;
    C    += (long)v * sCv;

    const long row0 = (long)blockIdx.y << 7;
    const int  col0 = blockIdx.x << 7;

    const int tid  = threadIdx.x;
    const int lane = tid & 31;
    const int wid  = tid >> 5;
    const int m0 = (wid & 3) << 5;
    const int n0 = (wid >> 2) << 5;

    const int ar  = tid >> 2;
    const int akq = (tid & 3) << 2;
    const int bk  = tid >> 5;
    const int bnq = (tid & 31) << 2;
    const bool bok = (col0 + bnq) < N;

    const float* Ap = A + (row0 + ar) * (long)lda;
    const float* Wp = W + (long)col0 + bnq;

    const int nch = (K + 31) >> 5;

    auto load_pair = [&](int k0, float4* a4, float4* b4) {
#pragma unroll
        for (int s = 0; s < 2; ++s) {
            const int ka = k0 + (s << 4);
            a4[s] = make_float4(0.f, 0.f, 0.f, 0.f);
            if (ka + akq < K) a4[s] = *(const float4*)(Ap + ka + akq);
            b4[s] = make_float4(0.f, 0.f, 0.f, 0.f);
            if (bok && (ka + bk) < K) b4[s] = *(const float4*)(Wp + (long)(ka + bk) * N);
        }
    };

    auto store_tiles = [&](int nb, const float4* a4, const float4* b4) {
        uint32_t* ab = smem + nb * A_BUF1 + ar * AST1 + akq;
        uint32_t* bb = smem + BS_BASE1 + nb * B_BUF1 + bk * BST + bnq;
#pragma unroll
        for (int s = 0; s < 2; ++s) {
            uint32_t* a = ab + (s << 4);
            a[0] = f2tf32(a4[s].x); a[1] = f2tf32(a4[s].y);
            a[2] = f2tf32(a4[s].z); a[3] = f2tf32(a4[s].w);
            uint32_t* b = bb + (s << 4) * BST;
            b[0] = f2tf32(b4[s].x); b[1] = f2tf32(b4[s].y);
            b[2] = f2tf32(b4[s].z); b[3] = f2tf32(b4[s].w);
        }
    };

    {
        float4 a4[2], b4[2];
        load_pair(0, a4, b4);
        store_tiles(0, a4, b4);
    }
    __syncthreads();

    float c[2][4][4] = {};
    int buf = 0;
    for (int ch = 0; ch < nch; ++ch) {
        float4 a4[2], b4[2];
        const bool more = (ch + 1) < nch;
        if (more) load_pair((ch + 1) << 5, a4, b4);

        const uint32_t* asb = smem + buf * A_BUF1 + (m0 + (lane >> 2)) * AST1 + (lane & 3);
        const uint32_t* bsb = smem + BS_BASE1 + buf * B_BUF1 + (lane & 3) * BST + n0 + (lane >> 2);
#pragma unroll
        for (int kk = 0; kk < 4; ++kk) {
            uint32_t ah[2][4];
#pragma unroll
            for (int i = 0; i < 2; ++i) {
                const uint32_t* p = asb + (i << 4) * AST1 + (kk << 3);
                ah[i][0] = p[0];
                ah[i][1] = p[8 * AST1];
                ah[i][2] = p[4];
                ah[i][3] = p[8 * AST1 + 4];
            }
            uint32_t bh[4][2];
#pragma unroll
            for (int j = 0; j < 4; ++j) {
                const uint32_t* q = bsb + (kk << 3) * BST + (j << 3);
                bh[j][0] = q[0];
                bh[j][1] = q[4 * BST];
            }
#pragma unroll
            for (int i = 0; i < 2; ++i)
#pragma unroll
                for (int j = 0; j < 4; ++j)
                    mma8(c[i][j], ah[i], bh[j]);
        }

        if (more) store_tiles(buf ^ 1, a4, b4);
        __syncthreads();
        buf ^= 1;
    }

#pragma unroll
    for (int i = 0; i < 2; ++i) {
        const long row = row0 + m0 + (i << 4) + (lane >> 2);
#pragma unroll
        for (int j = 0; j < 4; ++j) {
            const int col = col0 + n0 + (j << 3) + ((lane & 3) << 1);
            if (col < N) {
                const float2 bv = *(const float2*)(bias + col);
                float v0 = c[i][j][0] + bv.x;
                float v1 = c[i][j][1] + bv.y;
                float v2 = c[i][j][2] + bv.x;
                float v3 = c[i][j][3] + bv.y;
                if (relu) {
                    v0 = fmaxf(v0, 0.f); v1 = fmaxf(v1, 0.f);
                    v2 = fmaxf(v2, 0.f); v3 = fmaxf(v3, 0.f);
                }
                float2 o0 = {v0, v1}, o1 = {v2, v3};
                *(float2*)(C + row * (long)ldc + col)       = o0;
                *(float2*)(C + (row + 8) * (long)ldc + col) = o1;
            }
        }
    }
}

__global__ void stats_kernel(const float* __restrict__ h, int C, float* __restrict__ part) {
    const int v = blockIdx.x, s = blockIdx.y, c = threadIdx.x;
    const long stride = (long)Vn * C;
    const float* p = h + ((long)(s * 256) * Vn + v) * C + c;
    float sum = 0.f, sq = 0.f;
#pragma unroll 4
    for (int i = 0; i < 256; ++i) {
        float val = p[(long)i * stride];
        sum += val;
        sq = fmaf(val, val, sq);
    }
    const long o = (((long)s * Vn + v) * C + c) * 2;
    part[o] = sum; part[o + 1] = sq;
}

__global__ void fuse_kernel(const float* __restrict__ W, const float* __restrict__ bias,
                            const float* __restrict__ g, const float* __restrict__ be,
                            int Cin, int Nout,
                            float* __restrict__ Wp, float* __restrict__ bp)
{
    const int v = blockIdx.x, tid = threadIdx.x;
    __shared__ float sa[512], sc[512];
    for (int n = tid; n < Cin; n += blockDim.x) {
        float sum = 0.f, sq = 0.f;
        for (int s = 0; s < 32; ++s) {
            const long o = (((long)s * Vn + v) * Cin + n) * 2;
            sum += g_part[o]; sq += g_part[o + 1];
        }
        const float mu  = sum * (1.f / Bsz);
        const float var = sq * (1.f / Bsz) - mu * mu;
        const float rs  = rsqrtf(var + BNEPS);
        const float a   = g[v * Cin + n] * rs;
        sa[n] = a;
        sc[n] = be[v * Cin + n] - mu * a;
    }
    __syncthreads();
    const int slice = (Nout + gridDim.y - 1) / gridDim.y;
    const int j0 = blockIdx.y * slice;
    const int j1 = min(j0 + slice, Nout);
    const float* wv = W + (long)v * Cin * Nout;
    float* wpv = Wp + (long)v * Cin * Nout;
    for (int j = j0 + tid; j < j1; j += blockDim.x) {
        float acc = bias[v * Nout + j];
        for (int n = 0; n < Cin; ++n) {
            const float w = wv[(long)n * Nout + j];
            wpv[(long)n * Nout + j] = sa[n] * w;
            acc = fmaf(sc[n], w, acc);
        }
        bp[v * Nout + j] = acc;
    }
}

// ---- combine: 2 syncthreads total (all 8 norms reduced simultaneously) ----
__global__ void combine_kernel(float* __restrict__ enc_sig) {
    const int b = blockIdx.x;
    const int d = threadIdx.x;          // 512
    const int warp = d >> 5, lane = d & 31;
    __shared__ float partial[16][8];
    __shared__ float alpha[8];

    float ev[8];
    float s[8];
#pragma unroll
    for (int v = 0; v < 8; ++v) {
        ev[v] = g_e[((long)b * Vn + v) * 512 + d];
        s[v] = ev[v] * ev[v];
    }
#pragma unroll
    for (int v = 0; v < 8; ++v)
#pragma unroll
        for (int o = 16; o; o >>= 1) s[v] += __shfl_xor_sync(0xffffffffu, s[v], o);
    if (lane == 0)
#pragma unroll
        for (int v = 0; v < 8; ++v) partial[warp][v] = s[v];
    __syncthreads();
    if (warp < 8 && lane < 16) {
        float t = partial[lane][warp];
#pragma unroll
        for (int o = 8; o; o >>= 1) t += __shfl_xor_sync(0xffffu, t, o);
        if (lane == 0) alpha[warp] = 8.f * rsqrtf(t);
    }
    __syncthreads();
    float acc = 0.f;
#pragma unroll
    for (int v = 0; v < 8; ++v) acc = fmaf(alpha[v], ev[v], acc);
    enc_sig[(long)b * 512 + d] = acc * 0.70710678118654752f;
}

struct C2 { float x, y; };
__device__ __forceinline__ C2 cmul(C2 a, C2 b) { return {a.x*b.x - a.y*b.y, a.x*b.y + a.y*b.x}; }
__device__ __forceinline__ C2 cmulc(C2 a, C2 b) { return {a.x*b.x + a.y*b.y, a.x*b.y - a.y*b.x}; }

__global__ void channel_kernel(const float* __restrict__ Hri, const float* __restrict__ noiseri,
                               const float* __restrict__ encsig,
                               float* __restrict__ yout, float* __restrict__ xeq1out)
{
    const int b = blockIdx.x;
    const int f = threadIdx.x;
    __shared__ C2 H[4][4];
    __shared__ C2 Ainv[4][4];
    const float is2 = 0.70710678118654752f;

    if (f < 16) {
        const int r = f >> 2, t = f & 3;
        const long o = (((long)(b * 4 + r)) * 4 + t) * 2;
        H[r][t] = {Hri[o] * is2, Hri[o + 1] * is2};
    }
    __syncthreads();

    const float lam = g_consts[0];
    const float nsc = g_consts[1];

    if (f == 0) {
        C2 Am[4][8];
        for (int i = 0; i < 4; ++i) {
            for (int j = 0; j < 4; ++j) {
                C2 a = {0.f, 0.f};
                for (int r = 0; r < 4; ++r) {
                    C2 p = cmulc(H[r][i], H[r][j]);
                    a.x += p.x; a.y += p.y;
                }
                if (i == j) a.x += lam;
                Am[i][j] = a;
                Am[i][4 + j] = (i == j) ? C2{1.f, 0.f} : C2{0.f, 0.f};
            }
        }
        for (int p = 0; p < 4; ++p) {
            C2 dg = Am[p][p];
            const float inv = 1.f / (dg.x * dg.x + dg.y * dg.y);
            const C2 dinv = {dg.x * inv, -dg.y * inv};
            for (int j = 0; j < 8; ++j) Am[p][j] = cmul(Am[p][j], dinv);
            for (int r = 0; r < 4; ++r) {
                if (r == p) continue;
                const C2 fac = Am[r][p];
                for (int j = 0; j < 8; ++j) {
                    const C2 q = cmul(fac, Am[p][j]);
                    Am[r][j].x -= q.x; Am[r][j].y -= q.y;
                }
            }
        }
        for (int i = 0; i < 4; ++i)
            for (int j = 0; j < 4; ++j)
                Ainv[i][j] = Am[i][4 + j];
    }
    __syncthreads();

    C2 s[4];
#pragma unroll
    for (int t = 0; t < 4; ++t) {
        const long o = ((long)b * 512) + ((long)(f * 4 + t)) * 2;
        s[t] = {encsig[o], encsig[o + 1]};
    }
    const long nbase = ((long)(b * 64 + f)) * 8;
    C2 yv[4];
#pragma unroll
    for (int r = 0; r < 4; ++r) {
        C2 a = {0.f, 0.f};
#pragma unroll
        for (int t = 0; t < 4; ++t) { C2 p = cmul(H[r][t], s[t]); a.x += p.x; a.y += p.y; }
        a.x += nsc * noiseri[nbase + r * 2]     * is2;
        a.y += nsc * noiseri[nbase + r * 2 + 1] * is2;
        yv[r] = a;
        yout[nbase + r * 2]     = a.x;
        yout[nbase + r * 2 + 1] = a.y;
    }
    C2 hy[4];
#pragma unroll
    for (int t = 0; t < 4; ++t) {
        C2 a = {0.f, 0.f};
#pragma unroll
        for (int r = 0; r < 4; ++r) { C2 p = cmulc(H[r][t], yv[r]); a.x += p.x; a.y += p.y; }
        hy[t] = a;
    }
#pragma unroll
    for (int t = 0; t < 4; ++t) {
        C2 a = {0.f, 0.f};
#pragma unroll
        for (int k = 0; k < 4; ++k) { C2 p = cmul(Ainv[t][k], hy[k]); a.x += p.x; a.y += p.y; }
        xeq1out[nbase + t * 2]     = a.x;
        xeq1out[nbase + t * 2 + 1] = a.y;
    }
    float* hyp = &g_HY[((long)(b * 64 + f)) * 40];
#pragma unroll
    for (int r = 0; r < 4; ++r)
#pragma unroll
        for (int t = 0; t < 4; ++t) {
            hyp[(r * 4 + t) * 2]     = H[r][t].x;
            hyp[(r * 4 + t) * 2 + 1] = H[r][t].y;
        }
#pragma unroll
    for (int r = 0; r < 4; ++r) {
        hyp[32 + r * 2]     = yv[r].x;
        hyp[32 + r * 2 + 1] = yv[r].y;
    }
}

__global__ __launch_bounds__(256) void res3_add_kernel(
    const float* __restrict__ r2, const float* __restrict__ W3,
    const float* __restrict__ b3, const float* __restrict__ xeq1,
    float* __restrict__ xequ)
{
    __shared__ float wt[8][256];
    __shared__ float bs[8];
    const int tid = threadIdx.x;
    if (tid < 8) bs[tid] = b3[tid];
#pragma unroll
    for (int j = 0; j < 8; ++j)
        wt[j][tid] = W3[tid * 8 + j];
    __syncthreads();

    const int warp = tid >> 5, lane = tid & 31;
    const long row = (long)blockIdx.x * 8 + warp;
    const float* rp = r2 + row * 256;
    float acc[8] = {};
#pragma unroll
    for (int ii = 0; ii < 8; ++ii) {
        const int i = ii * 32 + lane;
        const float rv = rp[i];
#pragma unroll
        for (int j = 0; j < 8; ++j) acc[j] = fmaf(rv, wt[j][i], acc[j]);
    }
#pragma unroll
    for (int j = 0; j < 8; ++j)
#pragma unroll
        for (int o = 16; o; o >>= 1) acc[j] += __shfl_xor_sync(0xffffffffu, acc[j], o);
    if (lane == 0) {
        const long ob = row * 8;
#pragma unroll
        for (int j = 0; j < 8; ++j)
            xequ[ob + j] = xeq1[ob + j] + acc[j] + bs[j];
    }
}

__global__ void emit_kernel(const float* __restrict__ src, float* __restrict__ out,
                            long off, long n, long out_size, int mode) {
    const long i = (long)blockIdx.x * blockDim.x + threadIdx.x;
    if (i >= n) return;
    const long o = off + i;
    if (o >= out_size) return;
    out[o] = (mode == 0) ? src[i] : src[2 * i];
}

extern "C" void kernel_launch(void* const* d_in, const int* in_sizes, int n_in,
                              void* d_out, int out_size) {
    const float* x        = (const float*)d_in[0];
    const int*   snr      = (const int*)  d_in[1];
    const float* H_ri     = (const float*)d_in[2];
    const float* noise_ri = (const float*)d_in[3];
    const float* enc_W1 = (const float*)d_in[4];  const float* enc_b1 = (const float*)d_in[5];
    const float* enc_g1 = (const float*)d_in[6];  const float* enc_be1= (const float*)d_in[7];
    const float* enc_W2 = (const float*)d_in[8];  const float* enc_b2 = (const float*)d_in[9];
    const float* enc_g2 = (const float*)d_in[10]; const float* enc_be2= (const float*)d_in[11];
    const float* enc_W3 = (const float*)d_in[12]; const float* enc_b3 = (const float*)d_in[13];
    const float* dec_W1 = (const float*)d_in[14]; const float* dec_b1 = (const float*)d_in[15];
    const float* dec_g1 = (const float*)d_in[16]; const float* dec_be1= (const float*)d_in[17];
    const float* dec_W2 = (const float*)d_in[18]; const float* dec_b2 = (const float*)d_in[19];
    const float* dec_g2 = (const float*)d_in[20]; const float* dec_be2= (const float*)d_in[21];
    const float* dec_W3 = (const float*)d_in[22]; const float* dec_b3 = (const float*)d_in[23];
    const float* res_W1 = (const float*)d_in[24]; const float* res_b1 = (const float*)d_in[25];
    const float* res_W2 = (const float*)d_in[26]; const float* res_b2 = (const float*)d_in[27];
    const float* res_W3 = (const float*)d_in[28]; const float* res_b3 = (const float*)d_in[29];

    float *h1, *h2, *e, *hd1, *hd2, *HY, *r1, *r2;
    float *Ps, *ys, *xequs, *xeq1s, *sigs;
    float *W2e, *b2e, *W3e, *b3e, *W2d, *b2d, *W3d, *b3d, *part;
    cudaGetSymbolAddress((void**)&h1,  g_h1);
    cudaGetSymbolAddress((void**)&h2,  g_h2);
    cudaGetSymbolAddress((void**)&e,   g_e);
    cudaGetSymbolAddress((void**)&hd1, g_hd1);
    cudaGetSymbolAddress((void**)&hd2, g_hd2);
    cudaGetSymbolAddress((void**)&HY,  g_HY);
    cudaGetSymbolAddress((void**)&r1,  g_r1);
    cudaGetSymbolAddress((void**)&r2,  g_r2);
    cudaGetSymbolAddress((void**)&Ps,    g_P);
    cudaGetSymbolAddress((void**)&ys,    g_y);
    cudaGetSymbolAddress((void**)&xequs, g_xequ);
    cudaGetSymbolAddress((void**)&xeq1s, g_xeq1);
    cudaGetSymbolAddress((void**)&sigs,  g_sig);
    cudaGetSymbolAddress((void**)&W2e, g_W2e); cudaGetSymbolAddress((void**)&b2e, g_b2e);
    cudaGetSymbolAddress((void**)&W3e, g_W3e); cudaGetSymbolAddress((void**)&b3e, g_b3e);
    cudaGetSymbolAddress((void**)&W2d, g_W2d); cudaGetSymbolAddress((void**)&b2d, g_b2d);
    cudaGetSymbolAddress((void**)&W3d, g_W3d); cudaGetSymbolAddress((void**)&b3d, g_b3d);
    cudaGetSymbolAddress((void**)&part, g_part);

    float* out = (float*)d_out;
    const long LP = 2097152, LY = 4194304, LX = 4194304, LS = 4194304;
    const long FULL = LP + LY + LX + LX + LS;
    const bool direct = ((long)out_size == FULL);
    float* P    = direct ? out                     : Ps;
    float* y    = direct ? out + LP                : ys;
    float* xequ = direct ? out + LP + LY           : xequs;
    float* xeq1 = direct ? out + LP + LY + LX      : xeq1s;
    float* sig  = direct ? out + LP + LY + LX + LX : sigs;

    const int SMB3 = (2 * A_BUF3 + 2 * B_BUF3) * 4;   // 75776 B
    const int SMB1 = (2 * A_BUF1 + 2 * B_BUF1) * 4;   // 71680 B
    cudaFuncSetAttribute(mma_gemm3, cudaFuncAttributeMaxDynamicSharedMemorySize, SMB3);
    cudaFuncSetAttribute(mma_gemm1, cudaFuncAttributeMaxDynamicSharedMemorySize, SMB1);

    prep_kernel<<<1, 1>>>(snr);

    // ---- encoder: enc1/enc2 3x, enc3 1x ----
    mma_gemm3<<<dim3(1, 64, 8), 512, SMB3>>>(x, 256, 32, enc_W1, 32 * 128, enc_b1, 128,
                                             h1, 1024, 128, 32, 128, 1);
    stats_kernel<<<dim3(8, 32), 128>>>(h1, 128, part);
    fuse_kernel<<<dim3(8, 8), 256>>>(enc_W2, enc_b2, enc_g1, enc_be1, 128, 128, W2e, b2e);
    mma_gemm3<<<dim3(1, 64, 8), 512, SMB3>>>(h1, 1024, 128, W2e, 128 * 128, b2e, 128,
                                             h2, 1024, 128, 128, 128, 1);
    stats_kernel<<<dim3(8, 32), 128>>>(h2, 128, part);
    fuse_kernel<<<dim3(8, 8), 256>>>(enc_W3, enc_b3, enc_g2, enc_be2, 128, 512, W3e, b3e);
    mma_gemm1<<<dim3(4, 64, 8), 512, SMB1>>>(h2, 1024, 128, W3e, 128 * 512, b3e, 512,
                                             e, 4096, 512, 128, 512, 0);
    combine_kernel<<<8192, 512>>>(sig);

    // ---- channel + MMSE ----
    channel_kernel<<<8192, 64>>>(H_ri, noise_ri, sig, y, xeq1);

    // ---- residual MLP (1xTF32, K-chunk 32) ----
    mma_gemm1<<<dim3(2, 4096, 1), 512, SMB1>>>(HY, 40, 0, res_W1, 0, res_b1, 0,
                                               r1, 256, 0, 40, 256, 1);
    mma_gemm1<<<dim3(2, 4096, 1), 512, SMB1>>>(r1, 256, 0, res_W2, 0, res_b2, 0,
                                               r2, 256, 0, 256, 256, 1);
    res3_add_kernel<<<65536, 256>>>(r2, res_W3, res_b3, xeq1, xequ);

    // ---- decoder: dec1 3x, dec2 1x, dec3 1x ----
    mma_gemm3<<<dim3(2, 64, 8), 512, SMB3>>>(xequ, 512, 0, dec_W1, 512 * 256, dec_b1, 256,
                                             hd1, 2048, 256, 512, 256, 1);
    stats_kernel<<<dim3(8, 32), 256>>>(hd1, 256, part);
    fuse_kernel<<<dim3(8, 8), 256>>>(dec_W2, dec_b2, dec_g1, dec_be1, 256, 256, W2d, b2d);
    mma_gemm1<<<dim3(2, 64, 8), 512, SMB1>>>(hd1, 2048, 256, W2d, 256 * 256, b2d, 256,
                                             hd2, 2048, 256, 256, 256, 1);
    stats_kernel<<<dim3(8, 32), 256>>>(hd2, 256, part);
    fuse_kernel<<<dim3(8, 8), 256>>>(dec_W3, dec_b3, dec_g2, dec_be2, 256, 32, W3d, b3d);
    mma_gemm1<<<dim3(1, 64, 8), 512, SMB1>>>(hd2, 2048, 256, W3d, 256 * 32, b3d, 32,
                                             P, 256, 32, 256, 32, 0);

    // ---- fallback emission only if layout differs ----
    if (!direct) {
        const long osz = (long)out_size;
        auto emit = [&](const float* src, long off, long n, int mode) {
            if (off >= osz || n <= 0) return;
            long grid = (n + 255) / 256;
            emit_kernel<<<(unsigned)grid, 256>>>(src, out, off, n, osz, mode);
        };
        if (osz == LP + LY/2 + LX + LX + LS) {
            long off = 0;
            emit(P,    off, LP,   0); off += LP;
            emit(y,    off, LY/2, 1); off += LY/2;
            emit(xequ, off, LX,   0); off += LX;
            emit(xeq1, off, LX,   0); off += LX;
            emit(sig,  off, LS,   0);
        } else {
            long off = 0;
            emit(P,    off, LP, 0); off += LP;
            emit(y,    off, LY, 0); off += LY;
            emit(xequ, off, LX, 0); off += LX;
            emit(xeq1, off, LX, 0); off += LX;
            emit(sig,  off, LS, 0);
        }
    }
}

// round 14
// speedup vs baseline: 1.3995x; 1.0933x over previous
#include <cuda_runtime.h>
#include <math.h>
#include <stdint.h>

#define Bsz 8192
#define Vn  8
#define FcN 64
#define BNEPS 1e-5f

__device__ float g_h1 [(size_t)Bsz*Vn*128];
__device__ float g_h2 [(size_t)Bsz*Vn*128];
__device__ float g_e  [(size_t)Bsz*Vn*512];
__device__ float g_hd1[(size_t)Bsz*Vn*256];
__device__ float g_hd2[(size_t)Bsz*Vn*256];
__device__ float g_HY [(size_t)Bsz*FcN*40];
__device__ float g_r1 [(size_t)Bsz*FcN*256];
__device__ float g_r2 [(size_t)Bsz*FcN*256];
__device__ float g_P   [(size_t)Bsz*Vn*32];
__device__ float g_y   [(size_t)Bsz*FcN*8];
__device__ float g_xequ[(size_t)Bsz*FcN*8];
__device__ float g_xeq1[(size_t)Bsz*FcN*8];
__device__ float g_sig [(size_t)Bsz*512];
__device__ float g_W2e[Vn*128*128]; __device__ float g_b2e[Vn*128];
__device__ float g_W3e[Vn*128*512]; __device__ float g_b3e[Vn*512];
__device__ float g_W2d[Vn*256*256]; __device__ float g_b2d[Vn*256];
__device__ float g_W3d[Vn*256*32];  __device__ float g_b3d[Vn*32];
__device__ float g_part[32*Vn*256*2];
__device__ float g_consts[4];

__device__ __forceinline__ uint32_t f2tf32(float f) {
    uint32_t r; asm("cvt.rna.tf32.f32 %0, %1;" : "=r"(r) : "f"(f)); return r;
}
__device__ __forceinline__ void split_tf32(float f, uint32_t& hi, uint32_t& lo) {
    hi = f2tf32(f);
    lo = f2tf32(f - __uint_as_float(hi));
}
__device__ __forceinline__ void mma8(float* c, const uint32_t* a, const uint32_t* b) {
    asm volatile(
        "mma.sync.aligned.m16n8k8.row.col.f32.tf32.tf32.f32 "
        "{%0,%1,%2,%3}, {%4,%5,%6,%7}, {%8,%9}, {%0,%1,%2,%3};"
        : "+f"(c[0]), "+f"(c[1]), "+f"(c[2]), "+f"(c[3])
        : "r"(a[0]), "r"(a[1]), "r"(a[2]), "r"(a[3]), "r"(b[0]), "r"(b[1]));
}

__global__ void prep_kernel(const int* __restrict__ snrp) {
    int iv = *snrp;
    float S;
    if (iv >= -1000 && iv <= 1000) S = (float)iv;
    else                            S = __int_as_float(iv);
    float snr = powf(10.f, -S * 0.1f);
    g_consts[0] = 4.f * snr;
    g_consts[1] = sqrtf(4.f * snr);
}

// ================= 3-term GEMM (round-7 proven): 512 thr, warp 32x32 ==========
#define AST 20
#define BST 136
#define AS_SZ   (128 * AST)
#define BS_SZ   (16 * BST)
#define A_BUF3  (2 * AS_SZ)
#define B_BUF3  (2 * BS_SZ)
#define BS_BASE3 (2 * A_BUF3)

__global__ __launch_bounds__(512) void mma_gemm3(
    const float* __restrict__ A, int lda, long sAv,
    const float* __restrict__ W, long sWv,
    const float* __restrict__ bias, int sbv,
    float* __restrict__ C, int ldc, long sCv,
    int K, int N, int relu)
{
    extern __shared__ uint32_t smem[];

    const int v = blockIdx.z;
    A    += (long)v * sAv;
    W    += (long)v * sWv;
    bias += (long)v * sbv;
    C    += (long)v * sCv;

    const long row0 = (long)blockIdx.y << 7;
    const int  col0 = blockIdx.x << 7;

    const int tid  = threadIdx.x;
    const int lane = tid & 31;
    const int wid  = tid >> 5;
    const int m0 = (wid & 3) << 5;
    const int n0 = (wid >> 2) << 5;

    const int ar  = tid >> 2;
    const int akq = (tid & 3) << 2;
    const int bk  = tid >> 5;
    const int bnq = (tid & 31) << 2;
    const bool bok = (col0 + bnq) < N;

    const float* Ap = A + (row0 + ar) * (long)lda;
    const float* Wp = W + (long)col0 + bnq;

    const int nch = (K + 15) >> 4;

    auto store_tiles = [&](int nb, float4 a4, float4 b4) {
        uint32_t* ash = smem + nb * A_BUF3 + ar * AST + akq;
        uint32_t* asl = ash + AS_SZ;
        split_tf32(a4.x, ash[0], asl[0]); split_tf32(a4.y, ash[1], asl[1]);
        split_tf32(a4.z, ash[2], asl[2]); split_tf32(a4.w, ash[3], asl[3]);
        uint32_t* bsh = smem + BS_BASE3 + nb * B_BUF3 + bk * BST + bnq;
        uint32_t* bsl = bsh + BS_SZ;
        split_tf32(b4.x, bsh[0], bsl[0]); split_tf32(b4.y, bsh[1], bsl[1]);
        split_tf32(b4.z, bsh[2], bsl[2]); split_tf32(b4.w, bsh[3], bsl[3]);
    };

    {
        float4 a4 = make_float4(0.f, 0.f, 0.f, 0.f);
        if (akq < K) a4 = *(const float4*)(Ap + akq);
        float4 b4 = make_float4(0.f, 0.f, 0.f, 0.f);
        if (bok && bk < K) b4 = *(const float4*)(Wp + (long)bk * N);
        store_tiles(0, a4, b4);
    }
    __syncthreads();

    float c[2][4][4] = {};
    int buf = 0;
    for (int ch = 0; ch < nch; ++ch) {
        float4 a4 = make_float4(0.f, 0.f, 0.f, 0.f);
        float4 b4 = make_float4(0.f, 0.f, 0.f, 0.f);
        const int nk0 = (ch + 1) << 4;
        const bool more = (ch + 1) < nch;
        if (more) {
            if (nk0 + akq < K) a4 = *(const float4*)(Ap + nk0 + akq);
            if (bok && (nk0 + bk) < K) b4 = *(const float4*)(Wp + (long)(nk0 + bk) * N);
        }

        const uint32_t* asb = smem + buf * A_BUF3 + (m0 + (lane >> 2)) * AST + (lane & 3);
        const uint32_t* bsb = smem + BS_BASE3 + buf * B_BUF3 + (lane & 3) * BST + n0 + (lane >> 2);
#pragma unroll
        for (int kk = 0; kk < 2; ++kk) {
            uint32_t ah[2][4], al[2][4];
#pragma unroll
            for (int i = 0; i < 2; ++i) {
                const uint32_t* p = asb + (i << 4) * AST + (kk << 3);
                ah[i][0] = p[0];
                ah[i][1] = p[8 * AST];
                ah[i][2] = p[4];
                ah[i][3] = p[8 * AST + 4];
                const uint32_t* pl = p + AS_SZ;
                al[i][0] = pl[0];
                al[i][1] = pl[8 * AST];
                al[i][2] = pl[4];
                al[i][3] = pl[8 * AST + 4];
            }
            uint32_t bh[4][2], bl[4][2];
#pragma unroll
            for (int j = 0; j < 4; ++j) {
                const uint32_t* q = bsb + (kk << 3) * BST + (j << 3);
                bh[j][0] = q[0];
                bh[j][1] = q[4 * BST];
                const uint32_t* ql = q + BS_SZ;
                bl[j][0] = ql[0];
                bl[j][1] = ql[4 * BST];
            }
#pragma unroll
            for (int i = 0; i < 2; ++i)
#pragma unroll
                for (int j = 0; j < 4; ++j) {
                    mma8(c[i][j], al[i], bh[j]);
                    mma8(c[i][j], ah[i], bl[j]);
                    mma8(c[i][j], ah[i], bh[j]);
                }
        }

        if (more) store_tiles(buf ^ 1, a4, b4);
        __syncthreads();
        buf ^= 1;
    }

#pragma unroll
    for (int i = 0; i < 2; ++i) {
        const long row = row0 + m0 + (i << 4) + (lane >> 2);
#pragma unroll
        for (int j = 0; j < 4; ++j) {
            const int col = col0 + n0 + (j << 3) + ((lane & 3) << 1);
            if (col < N) {
                const float2 bv = *(const float2*)(bias + col);
                float v0 = c[i][j][0] + bv.x;
                float v1 = c[i][j][1] + bv.y;
                float v2 = c[i][j][2] + bv.x;
                float v3 = c[i][j][3] + bv.y;
                if (relu) {
                    v0 = fmaxf(v0, 0.f); v1 = fmaxf(v1, 0.f);
                    v2 = fmaxf(v2, 0.f); v3 = fmaxf(v3, 0.f);
                }
                float2 o0 = {v0, v1}, o1 = {v2, v3};
                *(float2*)(C + row * (long)ldc + col)       = o0;
                *(float2*)(C + (row + 8) * (long)ldc + col) = o1;
            }
        }
    }
}

// ==== 1-term GEMM: 256 thr, 8 warps, warp tile 32x64, K-chunk 32 ====
// Same proven smem layout (AST1=36, BST=136); 64 mma per warp per sync window.
#define AST1 36
#define A_BUF1 (128 * AST1)
#define B_BUF1 (32 * BST)
#define BS_BASE1 (2 * A_BUF1)

__global__ __launch_bounds__(256, 2) void mma_gemm1(
    const float* __restrict__ A, int lda, long sAv,
    const float* __restrict__ W, long sWv,
    const float* __restrict__ bias, int sbv,
    float* __restrict__ C, int ldc, long sCv,
    int K, int N, int relu)
{
    extern __shared__ uint32_t smem[];

    const int v = blockIdx.z;
    A    += (long)v * sAv;
    W    += (long)v * sWv;
    bias += (long)v * sbv;
    C    += (long)v * sCv;

    const long row0 = (long)blockIdx.y << 7;
    const int  col0 = blockIdx.x << 7;

    const int tid  = threadIdx.x;
    const int lane = tid & 31;
    const int wid  = tid >> 5;            // 0..7
    const int m0 = (wid & 3) << 5;        // 0,32,64,96
    const int n0 = (wid >> 2) << 6;       // 0,64

    // loaders: A row = tid>>1, k half = (tid&1)*16, 4 float4 each.
    //          B: warp wid stores k rows {wid, wid+8, wid+16, wid+24}, n = lane*4.
    const int arow = tid >> 1;
    const int ak16 = (tid & 1) << 4;
    const int bn   = lane << 2;
    const bool bok = (col0 + bn) < N;

    const float* Ap = A + (row0 + arow) * (long)lda + ak16;
    const float* Wp = W + (long)col0 + bn;

    const int nch = (K + 31) >> 5;

    float4 a4[4], b4[4];

    auto load_chunk = [&](int k0) {
#pragma unroll
        for (int s = 0; s < 4; ++s) {
            const int ka = k0 + ak16 + (s << 2);
            a4[s] = make_float4(0.f, 0.f, 0.f, 0.f);
            if (ka < K) a4[s] = *(const float4*)(Ap + k0 + (s << 2));
            const int kb = k0 + wid + (s << 3);
            b4[s] = make_float4(0.f, 0.f, 0.f, 0.f);
            if (bok && kb < K) b4[s] = *(const float4*)(Wp + (long)kb * N);
        }
    };

    auto store_chunk = [&](int nb) {
        uint32_t* ab = smem + nb * A_BUF1 + arow * AST1 + ak16;
        uint32_t* bb = smem + BS_BASE1 + nb * B_BUF1 + wid * BST + bn;
#pragma unroll
        for (int s = 0; s < 4; ++s) {
            uint4 t;
            t.x = f2tf32(a4[s].x); t.y = f2tf32(a4[s].y);
            t.z = f2tf32(a4[s].z); t.w = f2tf32(a4[s].w);
            *(uint4*)(ab + (s << 2)) = t;
            uint32_t* b = bb + (s << 3) * BST;
            b[0] = f2tf32(b4[s].x); b[1] = f2tf32(b4[s].y);
            b[2] = f2tf32(b4[s].z); b[3] = f2tf32(b4[s].w);
        }
    };

    load_chunk(0);
    store_chunk(0);
    __syncthreads();

    float c[2][8][4] = {};
    int buf = 0;
    for (int ch = 0; ch < nch; ++ch) {
        const bool more = (ch + 1) < nch;
        if (more) load_chunk((ch + 1) << 5);

        const uint32_t* asb = smem + buf * A_BUF1 + (m0 + (lane >> 2)) * AST1 + (lane & 3);
        const uint32_t* bsb = smem + BS_BASE1 + buf * B_BUF1 + (lane & 3) * BST + n0 + (lane >> 2);
#pragma unroll
        for (int kk = 0; kk < 4; ++kk) {
            uint32_t ah[2][4];
#pragma unroll
            for (int i = 0; i < 2; ++i) {
                const uint32_t* p = asb + (i << 4) * AST1 + (kk << 3);
                ah[i][0] = p[0];
                ah[i][1] = p[8 * AST1];
                ah[i][2] = p[4];
                ah[i][3] = p[8 * AST1 + 4];
            }
#pragma unroll
            for (int j = 0; j < 8; ++j) {
                const uint32_t* q = bsb + (kk << 3) * BST + (j << 3);
                uint32_t bh[2];
                bh[0] = q[0];
                bh[1] = q[4 * BST];
#pragma unroll
                for (int i = 0; i < 2; ++i)
                    mma8(c[i][j], ah[i], bh);
            }
        }

        if (more) store_chunk(buf ^ 1);
        __syncthreads();
        buf ^= 1;
    }

#pragma unroll
    for (int i = 0; i < 2; ++i) {
        const long row = row0 + m0 + (i << 4) + (lane >> 2);
#pragma unroll
        for (int j = 0; j < 8; ++j) {
            const int col = col0 + n0 + (j << 3) + ((lane & 3) << 1);
            if (col < N) {
                const float2 bv = *(const float2*)(bias + col);
                float v0 = c[i][j][0] + bv.x;
                float v1 = c[i][j][1] + bv.y;
                float v2 = c[i][j][2] + bv.x;
                float v3 = c[i][j][3] + bv.y;
                if (relu) {
                    v0 = fmaxf(v0, 0.f); v1 = fmaxf(v1, 0.f);
                    v2 = fmaxf(v2, 0.f); v3 = fmaxf(v3, 0.f);
                }
                float2 o0 = {v0, v1}, o1 = {v2, v3};
                *(float2*)(C + row * (long)ldc + col)       = o0;
                *(float2*)(C + (row + 8) * (long)ldc + col) = o1;
            }
        }
    }
}

__global__ void stats_kernel(const float* __restrict__ h, int C, float* __restrict__ part) {
    const int v = blockIdx.x, s = blockIdx.y, c = threadIdx.x;
    const long stride = (long)Vn * C;
    const float* p = h + ((long)(s * 256) * Vn + v) * C + c;
    float sum = 0.f, sq = 0.f;
#pragma unroll 4
    for (int i = 0; i < 256; ++i) {
        float val = p[(long)i * stride];
        sum += val;
        sq = fmaf(val, val, sq);
    }
    const long o = (((long)s * Vn + v) * C + c) * 2;
    part[o] = sum; part[o + 1] = sq;
}

__global__ void fuse_kernel(const float* __restrict__ W, const float* __restrict__ bias,
                            const float* __restrict__ g, const float* __restrict__ be,
                            int Cin, int Nout,
                            float* __restrict__ Wp, float* __restrict__ bp)
{
    const int v = blockIdx.x, tid = threadIdx.x;
    __shared__ float sa[512], sc[512];
    for (int n = tid; n < Cin; n += blockDim.x) {
        float sum = 0.f, sq = 0.f;
        for (int s = 0; s < 32; ++s) {
            const long o = (((long)s * Vn + v) * Cin + n) * 2;
            sum += g_part[o]; sq += g_part[o + 1];
        }
        const float mu  = sum * (1.f / Bsz);
        const float var = sq * (1.f / Bsz) - mu * mu;
        const float rs  = rsqrtf(var + BNEPS);
        const float a   = g[v * Cin + n] * rs;
        sa[n] = a;
        sc[n] = be[v * Cin + n] - mu * a;
    }
    __syncthreads();
    const int slice = (Nout + gridDim.y - 1) / gridDim.y;
    const int j0 = blockIdx.y * slice;
    const int j1 = min(j0 + slice, Nout);
    const float* wv = W + (long)v * Cin * Nout;
    float* wpv = Wp + (long)v * Cin * Nout;
    for (int j = j0 + tid; j < j1; j += blockDim.x) {
        float acc = bias[v * Nout + j];
        for (int n = 0; n < Cin; ++n) {
            const float w = wv[(long)n * Nout + j];
            wpv[(long)n * Nout + j] = sa[n] * w;
            acc = fmaf(sc[n], w, acc);
        }
        bp[v * Nout + j] = acc;
    }
}

// ---- combine: 2 syncthreads total ----
__global__ void combine_kernel(float* __restrict__ enc_sig) {
    const int b = blockIdx.x;
    const int d = threadIdx.x;          // 512
    const int warp = d >> 5, lane = d & 31;
    __shared__ float partial[16][8];
    __shared__ float alpha[8];

    float ev[8];
    float s[8];
#pragma unroll
    for (int v = 0; v < 8; ++v) {
        ev[v] = g_e[((long)b * Vn + v) * 512 + d];
        s[v] = ev[v] * ev[v];
    }
#pragma unroll
    for (int v = 0; v < 8; ++v)
#pragma unroll
        for (int o = 16; o; o >>= 1) s[v] += __shfl_xor_sync(0xffffffffu, s[v], o);
    if (lane == 0)
#pragma unroll
        for (int v = 0; v < 8; ++v) partial[warp][v] = s[v];
    __syncthreads();
    if (warp < 8 && lane < 16) {
        float t = partial[lane][warp];
#pragma unroll
        for (int o = 8; o; o >>= 1) t += __shfl_xor_sync(0xffffu, t, o);
        if (lane == 0) alpha[warp] = 8.f * rsqrtf(t);
    }
    __syncthreads();
    float acc = 0.f;
#pragma unroll
    for (int v = 0; v < 8; ++v) acc = fmaf(alpha[v], ev[v], acc);
    enc_sig[(long)b * 512 + d] = acc * 0.70710678118654752f;
}

struct C2 { float x, y; };
__device__ __forceinline__ C2 cmul(C2 a, C2 b) { return {a.x*b.x - a.y*b.y, a.x*b.y + a.y*b.x}; }
__device__ __forceinline__ C2 cmulc(C2 a, C2 b) { return {a.x*b.x + a.y*b.y, a.x*b.y - a.y*b.x}; }

__global__ void channel_kernel(const float* __restrict__ Hri, const float* __restrict__ noiseri,
                               const float* __restrict__ encsig,
                               float* __restrict__ yout, float* __restrict__ xeq1out)
{
    const int b = blockIdx.x;
    const int f = threadIdx.x;
    __shared__ C2 H[4][4];
    __shared__ C2 Ainv[4][4];
    const float is2 = 0.70710678118654752f;

    if (f < 16) {
        const int r = f >> 2, t = f & 3;
        const long o = (((long)(b * 4 + r)) * 4 + t) * 2;
        H[r][t] = {Hri[o] * is2, Hri[o + 1] * is2};
    }
    __syncthreads();

    const float lam = g_consts[0];
    const float nsc = g_consts[1];

    if (f == 0) {
        C2 Am[4][8];
        for (int i = 0; i < 4; ++i) {
            for (int j = 0; j < 4; ++j) {
                C2 a = {0.f, 0.f};
                for (int r = 0; r < 4; ++r) {
                    C2 p = cmulc(H[r][i], H[r][j]);
                    a.x += p.x; a.y += p.y;
                }
                if (i == j) a.x += lam;
                Am[i][j] = a;
                Am[i][4 + j] = (i == j) ? C2{1.f, 0.f} : C2{0.f, 0.f};
            }
        }
        for (int p = 0; p < 4; ++p) {
            C2 dg = Am[p][p];
            const float inv = 1.f / (dg.x * dg.x + dg.y * dg.y);
            const C2 dinv = {dg.x * inv, -dg.y * inv};
            for (int j = 0; j < 8; ++j) Am[p][j] = cmul(Am[p][j], dinv);
            for (int r = 0; r < 4; ++r) {
                if (r == p) continue;
                const C2 fac = Am[r][p];
                for (int j = 0; j < 8; ++j) {
                    const C2 q = cmul(fac, Am[p][j]);
                    Am[r][j].x -= q.x; Am[r][j].y -= q.y;
                }
            }
        }
        for (int i = 0; i < 4; ++i)
            for (int j = 0; j < 4; ++j)
                Ainv[i][j] = Am[i][4 + j];
    }
    __syncthreads();

    C2 s[4];
#pragma unroll
    for (int t = 0; t < 4; ++t) {
        const long o = ((long)b * 512) + ((long)(f * 4 + t)) * 2;
        s[t] = {encsig[o], encsig[o + 1]};
    }
    const long nbase = ((long)(b * 64 + f)) * 8;
    C2 yv[4];
#pragma unroll
    for (int r = 0; r < 4; ++r) {
        C2 a = {0.f, 0.f};
#pragma unroll
        for (int t = 0; t < 4; ++t) { C2 p = cmul(H[r][t], s[t]); a.x += p.x; a.y += p.y; }
        a.x += nsc * noiseri[nbase + r * 2]     * is2;
        a.y += nsc * noiseri[nbase + r * 2 + 1] * is2;
        yv[r] = a;
        yout[nbase + r * 2]     = a.x;
        yout[nbase + r * 2 + 1] = a.y;
    }
    C2 hy[4];
#pragma unroll
    for (int t = 0; t < 4; ++t) {
        C2 a = {0.f, 0.f};
#pragma unroll
        for (int r = 0; r < 4; ++r) { C2 p = cmulc(H[r][t], yv[r]); a.x += p.x; a.y += p.y; }
        hy[t] = a;
    }
#pragma unroll
    for (int t = 0; t < 4; ++t) {
        C2 a = {0.f, 0.f};
#pragma unroll
        for (int k = 0; k < 4; ++k) { C2 p = cmul(Ainv[t][k], hy[k]); a.x += p.x; a.y += p.y; }
        xeq1out[nbase + t * 2]     = a.x;
        xeq1out[nbase + t * 2 + 1] = a.y;
    }
    float* hyp = &g_HY[((long)(b * 64 + f)) * 40];
#pragma unroll
    for (int r = 0; r < 4; ++r)
#pragma unroll
        for (int t = 0; t < 4; ++t) {
            hyp[(r * 4 + t) * 2]     = H[r][t].x;
            hyp[(r * 4 + t) * 2 + 1] = H[r][t].y;
        }
#pragma unroll
    for (int r = 0; r < 4; ++r) {
        hyp[32 + r * 2]     = yv[r].x;
        hyp[32 + r * 2 + 1] = yv[r].y;
    }
}

__global__ __launch_bounds__(256) void res3_add_kernel(
    const float* __restrict__ r2, const float* __restrict__ W3,
    const float* __restrict__ b3, const float* __restrict__ xeq1,
    float* __restrict__ xequ)
{
    __shared__ float wt[8][256];
    __shared__ float bs[8];
    const int tid = threadIdx.x;
    if (tid < 8) bs[tid] = b3[tid];
#pragma unroll
    for (int j = 0; j < 8; ++j)
        wt[j][tid] = W3[tid * 8 + j];
    __syncthreads();

    const int warp = tid >> 5, lane = tid & 31;
    const long row = (long)blockIdx.x * 8 + warp;
    const float* rp = r2 + row * 256;
    float acc[8] = {};
#pragma unroll
    for (int ii = 0; ii < 8; ++ii) {
        const int i = ii * 32 + lane;
        const float rv = rp[i];
#pragma unroll
        for (int j = 0; j < 8; ++j) acc[j] = fmaf(rv, wt[j][i], acc[j]);
    }
#pragma unroll
    for (int j = 0; j < 8; ++j)
#pragma unroll
        for (int o = 16; o; o >>= 1) acc[j] += __shfl_xor_sync(0xffffffffu, acc[j], o);
    if (lane == 0) {
        const long ob = row * 8;
#pragma unroll
        for (int j = 0; j < 8; ++j)
            xequ[ob + j] = xeq1[ob + j] + acc[j] + bs[j];
    }
}

__global__ void emit_kernel(const float* __restrict__ src, float* __restrict__ out,
                            long off, long n, long out_size, int mode) {
    const long i = (long)blockIdx.x * blockDim.x + threadIdx.x;
    if (i >= n) return;
    const long o = off + i;
    if (o >= out_size) return;
    out[o] = (mode == 0) ? src[i] : src[2 * i];
}

extern "C" void kernel_launch(void* const* d_in, const int* in_sizes, int n_in,
                              void* d_out, int out_size) {
    const float* x        = (const float*)d_in[0];
    const int*   snr      = (const int*)  d_in[1];
    const float* H_ri     = (const float*)d_in[2];
    const float* noise_ri = (const float*)d_in[3];
    const float* enc_W1 = (const float*)d_in[4];  const float* enc_b1 = (const float*)d_in[5];
    const float* enc_g1 = (const float*)d_in[6];  const float* enc_be1= (const float*)d_in[7];
    const float* enc_W2 = (const float*)d_in[8];  const float* enc_b2 = (const float*)d_in[9];
    const float* enc_g2 = (const float*)d_in[10]; const float* enc_be2= (const float*)d_in[11];
    const float* enc_W3 = (const float*)d_in[12]; const float* enc_b3 = (const float*)d_in[13];
    const float* dec_W1 = (const float*)d_in[14]; const float* dec_b1 = (const float*)d_in[15];
    const float* dec_g1 = (const float*)d_in[16]; const float* dec_be1= (const float*)d_in[17];
    const float* dec_W2 = (const float*)d_in[18]; const float* dec_b2 = (const float*)d_in[19];
    const float* dec_g2 = (const float*)d_in[20]; const float* dec_be2= (const float*)d_in[21];
    const float* dec_W3 = (const float*)d_in[22]; const float* dec_b3 = (const float*)d_in[23];
    const float* res_W1 = (const float*)d_in[24]; const float* res_b1 = (const float*)d_in[25];
    const float* res_W2 = (const float*)d_in[26]; const float* res_b2 = (const float*)d_in[27];
    const float* res_W3 = (const float*)d_in[28]; const float* res_b3 = (const float*)d_in[29];

    float *h1, *h2, *e, *hd1, *hd2, *HY, *r1, *r2;
    float *Ps, *ys, *xequs, *xeq1s, *sigs;
    float *W2e, *b2e, *W3e, *b3e, *W2d, *b2d, *W3d, *b3d, *part;
    cudaGetSymbolAddress((void**)&h1,  g_h1);
    cudaGetSymbolAddress((void**)&h2,  g_h2);
    cudaGetSymbolAddress((void**)&e,   g_e);
    cudaGetSymbolAddress((void**)&hd1, g_hd1);
    cudaGetSymbolAddress((void**)&hd2, g_hd2);
    cudaGetSymbolAddress((void**)&HY,  g_HY);
    cudaGetSymbolAddress((void**)&r1,  g_r1);
    cudaGetSymbolAddress((void**)&r2,  g_r2);
    cudaGetSymbolAddress((void**)&Ps,    g_P);
    cudaGetSymbolAddress((void**)&ys,    g_y);
    cudaGetSymbolAddress((void**)&xequs, g_xequ);
    cudaGetSymbolAddress((void**)&xeq1s, g_xeq1);
    cudaGetSymbolAddress((void**)&sigs,  g_sig);
    cudaGetSymbolAddress((void**)&W2e, g_W2e); cudaGetSymbolAddress((void**)&b2e, g_b2e);
    cudaGetSymbolAddress((void**)&W3e, g_W3e); cudaGetSymbolAddress((void**)&b3e, g_b3e);
    cudaGetSymbolAddress((void**)&W2d, g_W2d); cudaGetSymbolAddress((void**)&b2d, g_b2d);
    cudaGetSymbolAddress((void**)&W3d, g_W3d); cudaGetSymbolAddress((void**)&b3d, g_b3d);
    cudaGetSymbolAddress((void**)&part, g_part);

    float* out = (float*)d_out;
    const long LP = 2097152, LY = 4194304, LX = 4194304, LS = 4194304;
    const long FULL = LP + LY + LX + LX + LS;
    const bool direct = ((long)out_size == FULL);
    float* P    = direct ? out                     : Ps;
    float* y    = direct ? out + LP                : ys;
    float* xequ = direct ? out + LP + LY           : xequs;
    float* xeq1 = direct ? out + LP + LY + LX      : xeq1s;
    float* sig  = direct ? out + LP + LY + LX + LX : sigs;

    const int SMB3 = (2 * A_BUF3 + 2 * B_BUF3) * 4;   // 75776 B
    const int SMB1 = (2 * A_BUF1 + 2 * B_BUF1) * 4;   // 71680 B
    cudaFuncSetAttribute(mma_gemm3, cudaFuncAttributeMaxDynamicSharedMemorySize, SMB3);
    cudaFuncSetAttribute(mma_gemm1, cudaFuncAttributeMaxDynamicSharedMemorySize, SMB1);

    prep_kernel<<<1, 1>>>(snr);

    // ---- encoder: enc1/enc2 3x, enc3 1x ----
    mma_gemm3<<<dim3(1, 64, 8), 512, SMB3>>>(x, 256, 32, enc_W1, 32 * 128, enc_b1, 128,
                                             h1, 1024, 128, 32, 128, 1);
    stats_kernel<<<dim3(8, 32), 128>>>(h1, 128, part);
    fuse_kernel<<<dim3(8, 8), 256>>>(enc_W2, enc_b2, enc_g1, enc_be1, 128, 128, W2e, b2e);
    mma_gemm3<<<dim3(1, 64, 8), 512, SMB3>>>(h1, 1024, 128, W2e, 128 * 128, b2e, 128,
                                             h2, 1024, 128, 128, 128, 1);
    stats_kernel<<<dim3(8, 32), 128>>>(h2, 128, part);
    fuse_kernel<<<dim3(8, 8), 256>>>(enc_W3, enc_b3, enc_g2, enc_be2, 128, 512, W3e, b3e);
    mma_gemm1<<<dim3(4, 64, 8), 256, SMB1>>>(h2, 1024, 128, W3e, 128 * 512, b3e, 512,
                                             e, 4096, 512, 128, 512, 0);
    combine_kernel<<<8192, 512>>>(sig);

    // ---- channel + MMSE ----
    channel_kernel<<<8192, 64>>>(H_ri, noise_ri, sig, y, xeq1);

    // ---- residual MLP (1xTF32) ----
    mma_gemm1<<<dim3(2, 4096, 1), 256, SMB1>>>(HY, 40, 0, res_W1, 0, res_b1, 0,
                                               r1, 256, 0, 40, 256, 1);
    mma_gemm1<<<dim3(2, 4096, 1), 256, SMB1>>>(r1, 256, 0, res_W2, 0, res_b2, 0,
                                               r2, 256, 0, 256, 256, 1);
    res3_add_kernel<<<65536, 256>>>(r2, res_W3, res_b3, xeq1, xequ);

    // ---- decoder: dec1 3x, dec2 1x, dec3 1x ----
    mma_gemm3<<<dim3(2, 64, 8), 512, SMB3>>>(xequ, 512, 0, dec_W1, 512 * 256, dec_b1, 256,
                                             hd1, 2048, 256, 512, 256, 1);
    stats_kernel<<<dim3(8, 32), 256>>>(hd1, 256, part);
    fuse_kernel<<<dim3(8, 8), 256>>>(dec_W2, dec_b2, dec_g1, dec_be1, 256, 256, W2d, b2d);
    mma_gemm1<<<dim3(2, 64, 8), 256, SMB1>>>(hd1, 2048, 256, W2d, 256 * 256, b2d, 256,
                                             hd2, 2048, 256, 256, 256, 1);
    stats_kernel<<<dim3(8, 32), 256>>>(hd2, 256, part);
    fuse_kernel<<<dim3(8, 8), 256>>>(dec_W3, dec_b3, dec_g2, dec_be2, 256, 32, W3d, b3d);
    mma_gemm1<<<dim3(1, 64, 8), 256, SMB1>>>(hd2, 2048, 256, W3d, 256 * 32, b3d, 32,
                                             P, 256, 32, 256, 32, 0);

    // ---- fallback emission only if layout differs ----
    if (!direct) {
        const long osz = (long)out_size;
        auto emit = [&](const float* src, long off, long n, int mode) {
            if (off >= osz || n <= 0) return;
            long grid = (n + 255) / 256;
            emit_kernel<<<(unsigned)grid, 256>>>(src, out, off, n, osz, mode);
        };
        if (osz == LP + LY/2 + LX + LX + LS) {
            long off = 0;
            emit(P,    off, LP,   0); off += LP;
            emit(y,    off, LY/2, 1); off += LY/2;
            emit(xequ, off, LX,   0); off += LX;
            emit(xeq1, off, LX,   0); off += LX;
            emit(sig,  off, LS,   0);
        } else {
            long off = 0;
            emit(P,    off, LP, 0); off += LP;
            emit(y,    off, LY, 0); off += LY;
            emit(xequ, off, LX, 0); off += LX;
            emit(xeq1, off, LX, 0); off += LX;
            emit(sig,  off, LS, 0);
        }
    }
}

// round 15
// speedup vs baseline: 1.7152x; 1.2256x over previous
#include <cuda_runtime.h>
#include <math.h>
#include <stdint.h>

#define Bsz 8192
#define Vn  8
#define FcN 64
#define BNEPS 1e-5f

__device__ float g_h1 [(size_t)Bsz*Vn*128];
__device__ float g_h2 [(size_t)Bsz*Vn*128];
__device__ float g_e  [(size_t)Bsz*Vn*512];
__device__ float g_hd1[(size_t)Bsz*Vn*256];
__device__ float g_hd2[(size_t)Bsz*Vn*256];
__device__ float g_HY [(size_t)Bsz*FcN*40];
__device__ float g_r1 [(size_t)Bsz*FcN*256];
__device__ float g_r3p[(size_t)4*Bsz*FcN*8];   // res3 partials (4 slots)
__device__ float g_P   [(size_t)Bsz*Vn*32];
__device__ float g_y   [(size_t)Bsz*FcN*8];
__device__ float g_xequ[(size_t)Bsz*FcN*8];
__device__ float g_xeq1[(size_t)Bsz*FcN*8];
__device__ float g_sig [(size_t)Bsz*512];
__device__ float g_W2e[Vn*128*128]; __device__ float g_b2e[Vn*128];
__device__ float g_W3e[Vn*128*512]; __device__ float g_b3e[Vn*512];
__device__ float g_W2d[Vn*256*256]; __device__ float g_b2d[Vn*256];
__device__ float g_W3d[Vn*256*32];  __device__ float g_b3d[Vn*32];
__device__ float g_part[32*Vn*256*2];
__device__ float g_consts[4];

__device__ __forceinline__ uint32_t f2tf32(float f) {
    uint32_t r; asm("cvt.rna.tf32.f32 %0, %1;" : "=r"(r) : "f"(f)); return r;
}
__device__ __forceinline__ void split_tf32(float f, uint32_t& hi, uint32_t& lo) {
    hi = f2tf32(f);
    lo = f2tf32(f - __uint_as_float(hi));
}
__device__ __forceinline__ void mma8(float* c, const uint32_t* a, const uint32_t* b) {
    asm volatile(
        "mma.sync.aligned.m16n8k8.row.col.f32.tf32.tf32.f32 "
        "{%0,%1,%2,%3}, {%4,%5,%6,%7}, {%8,%9}, {%0,%1,%2,%3};"
        : "+f"(c[0]), "+f"(c[1]), "+f"(c[2]), "+f"(c[3])
        : "r"(a[0]), "r"(a[1]), "r"(a[2]), "r"(a[3]), "r"(b[0]), "r"(b[1]));
}

__global__ void prep_kernel(const int* __restrict__ snrp) {
    int iv = *snrp;
    float S;
    if (iv >= -1000 && iv <= 1000) S = (float)iv;
    else                            S = __int_as_float(iv);
    float snr = powf(10.f, -S * 0.1f);
    g_consts[0] = 4.f * snr;
    g_consts[1] = sqrtf(4.f * snr);
}

// ================= 3-term GEMM (round-7 proven): 512 thr, warp 32x32 ==========
#define AST 20
#define BST 136
#define AS_SZ   (128 * AST)
#define BS_SZ   (16 * BST)
#define A_BUF3  (2 * AS_SZ)
#define B_BUF3  (2 * BS_SZ)
#define BS_BASE3 (2 * A_BUF3)

__global__ __launch_bounds__(512) void mma_gemm3(
    const float* __restrict__ A, int lda, long sAv,
    const float* __restrict__ W, long sWv,
    const float* __restrict__ bias, int sbv,
    float* __restrict__ C, int ldc, long sCv,
    int K, int N, int relu)
{
    extern __shared__ uint32_t smem[];

    const int v = blockIdx.z;
    A    += (long)v * sAv;
    W    += (long)v * sWv;
    bias += (long)v * sbv;
    C    += (long)v * sCv;

    const long row0 = (long)blockIdx.y << 7;
    const int  col0 = blockIdx.x << 7;

    const int tid  = threadIdx.x;
    const int lane = tid & 31;
    const int wid  = tid >> 5;
    const int m0 = (wid & 3) << 5;
    const int n0 = (wid >> 2) << 5;

    const int ar  = tid >> 2;
    const int akq = (tid & 3) << 2;
    const int bk  = tid >> 5;
    const int bnq = (tid & 31) << 2;
    const bool bok = (col0 + bnq) < N;

    const float* Ap = A + (row0 + ar) * (long)lda;
    const float* Wp = W + (long)col0 + bnq;

    const int nch = (K + 15) >> 4;

    auto store_tiles = [&](int nb, float4 a4, float4 b4) {
        uint32_t* ash = smem + nb * A_BUF3 + ar * AST + akq;
        uint32_t* asl = ash + AS_SZ;
        split_tf32(a4.x, ash[0], asl[0]); split_tf32(a4.y, ash[1], asl[1]);
        split_tf32(a4.z, ash[2], asl[2]); split_tf32(a4.w, ash[3], asl[3]);
        uint32_t* bsh = smem + BS_BASE3 + nb * B_BUF3 + bk * BST + bnq;
        uint32_t* bsl = bsh + BS_SZ;
        split_tf32(b4.x, bsh[0], bsl[0]); split_tf32(b4.y, bsh[1], bsl[1]);
        split_tf32(b4.z, bsh[2], bsl[2]); split_tf32(b4.w, bsh[3], bsl[3]);
    };

    {
        float4 a4 = make_float4(0.f, 0.f, 0.f, 0.f);
        if (akq < K) a4 = *(const float4*)(Ap + akq);
        float4 b4 = make_float4(0.f, 0.f, 0.f, 0.f);
        if (bok && bk < K) b4 = *(const float4*)(Wp + (long)bk * N);
        store_tiles(0, a4, b4);
    }
    __syncthreads();

    float c[2][4][4] = {};
    int buf = 0;
    for (int ch = 0; ch < nch; ++ch) {
        float4 a4 = make_float4(0.f, 0.f, 0.f, 0.f);
        float4 b4 = make_float4(0.f, 0.f, 0.f, 0.f);
        const int nk0 = (ch + 1) << 4;
        const bool more = (ch + 1) < nch;
        if (more) {
            if (nk0 + akq < K) a4 = *(const float4*)(Ap + nk0 + akq);
            if (bok && (nk0 + bk) < K) b4 = *(const float4*)(Wp + (long)(nk0 + bk) * N);
        }

        const uint32_t* asb = smem + buf * A_BUF3 + (m0 + (lane >> 2)) * AST + (lane & 3);
        const uint32_t* bsb = smem + BS_BASE3 + buf * B_BUF3 + (lane & 3) * BST + n0 + (lane >> 2);
#pragma unroll
        for (int kk = 0; kk < 2; ++kk) {
            uint32_t ah[2][4], al[2][4];
#pragma unroll
            for (int i = 0; i < 2; ++i) {
                const uint32_t* p = asb + (i << 4) * AST + (kk << 3);
                ah[i][0] = p[0];
                ah[i][1] = p[8 * AST];
                ah[i][2] = p[4];
                ah[i][3] = p[8 * AST + 4];
                const uint32_t* pl = p + AS_SZ;
                al[i][0] = pl[0];
                al[i][1] = pl[8 * AST];
                al[i][2] = pl[4];
                al[i][3] = pl[8 * AST + 4];
            }
            uint32_t bh[4][2], bl[4][2];
#pragma unroll
            for (int j = 0; j < 4; ++j) {
                const uint32_t* q = bsb + (kk << 3) * BST + (j << 3);
                bh[j][0] = q[0];
                bh[j][1] = q[4 * BST];
                const uint32_t* ql = q + BS_SZ;
                bl[j][0] = ql[0];
                bl[j][1] = ql[4 * BST];
            }
#pragma unroll
            for (int i = 0; i < 2; ++i)
#pragma unroll
                for (int j = 0; j < 4; ++j) {
                    mma8(c[i][j], al[i], bh[j]);
                    mma8(c[i][j], ah[i], bl[j]);
                    mma8(c[i][j], ah[i], bh[j]);
                }
        }

        if (more) store_tiles(buf ^ 1, a4, b4);
        __syncthreads();
        buf ^= 1;
    }

#pragma unroll
    for (int i = 0; i < 2; ++i) {
        const long row = row0 + m0 + (i << 4) + (lane >> 2);
#pragma unroll
        for (int j = 0; j < 4; ++j) {
            const int col = col0 + n0 + (j << 3) + ((lane & 3) << 1);
            if (col < N) {
                const float2 bv = *(const float2*)(bias + col);
                float v0 = c[i][j][0] + bv.x;
                float v1 = c[i][j][1] + bv.y;
                float v2 = c[i][j][2] + bv.x;
                float v3 = c[i][j][3] + bv.y;
                if (relu) {
                    v0 = fmaxf(v0, 0.f); v1 = fmaxf(v1, 0.f);
                    v2 = fmaxf(v2, 0.f); v3 = fmaxf(v3, 0.f);
                }
                float2 o0 = {v0, v1}, o1 = {v2, v3};
                *(float2*)(C + row * (long)ldc + col)       = o0;
                *(float2*)(C + (row + 8) * (long)ldc + col) = o1;
            }
        }
    }
}

// ==== 1-term GEMM (round-14 proven): 256 thr, 8 warps, warp 32x64, K-chunk 32 ====
#define AST1 36
#define A_BUF1 (128 * AST1)
#define B_BUF1 (32 * BST)
#define BS_BASE1 (2 * A_BUF1)

__global__ __launch_bounds__(256, 2) void mma_gemm1(
    const float* __restrict__ A, int lda, long sAv,
    const float* __restrict__ W, long sWv,
    const float* __restrict__ bias, int sbv,
    float* __restrict__ C, int ldc, long sCv,
    int K, int N, int relu)
{
    extern __shared__ uint32_t smem[];

    const int v = blockIdx.z;
    A    += (long)v * sAv;
    W    += (long)v * sWv;
    bias += (long)v * sbv;
    C    += (long)v * sCv;

    const long row0 = (long)blockIdx.y << 7;
    const int  col0 = blockIdx.x << 7;

    const int tid  = threadIdx.x;
    const int lane = tid & 31;
    const int wid  = tid >> 5;
    const int m0 = (wid & 3) << 5;
    const int n0 = (wid >> 2) << 6;

    const int arow = tid >> 1;
    const int ak16 = (tid & 1) << 4;
    const int bn   = lane << 2;
    const bool bok = (col0 + bn) < N;

    const float* Ap = A + (row0 + arow) * (long)lda + ak16;
    const float* Wp = W + (long)col0 + bn;

    const int nch = (K + 31) >> 5;

    float4 a4[4], b4[4];

    auto load_chunk = [&](int k0) {
#pragma unroll
        for (int s = 0; s < 4; ++s) {
            const int ka = k0 + ak16 + (s << 2);
            a4[s] = make_float4(0.f, 0.f, 0.f, 0.f);
            if (ka < K) a4[s] = *(const float4*)(Ap + k0 + (s << 2));
            const int kb = k0 + wid + (s << 3);
            b4[s] = make_float4(0.f, 0.f, 0.f, 0.f);
            if (bok && kb < K) b4[s] = *(const float4*)(Wp + (long)kb * N);
        }
    };

    auto store_chunk = [&](int nb) {
        uint32_t* ab = smem + nb * A_BUF1 + arow * AST1 + ak16;
        uint32_t* bb = smem + BS_BASE1 + nb * B_BUF1 + wid * BST + bn;
#pragma unroll
        for (int s = 0; s < 4; ++s) {
            uint4 t;
            t.x = f2tf32(a4[s].x); t.y = f2tf32(a4[s].y);
            t.z = f2tf32(a4[s].z); t.w = f2tf32(a4[s].w);
            *(uint4*)(ab + (s << 2)) = t;
            uint32_t* b = bb + (s << 3) * BST;
            b[0] = f2tf32(b4[s].x); b[1] = f2tf32(b4[s].y);
            b[2] = f2tf32(b4[s].z); b[3] = f2tf32(b4[s].w);
        }
    };

    load_chunk(0);
    store_chunk(0);
    __syncthreads();

    float c[2][8][4] = {};
    int buf = 0;
    for (int ch = 0; ch < nch; ++ch) {
        const bool more = (ch + 1) < nch;
        if (more) load_chunk((ch + 1) << 5);

        const uint32_t* asb = smem + buf * A_BUF1 + (m0 + (lane >> 2)) * AST1 + (lane & 3);
        const uint32_t* bsb = smem + BS_BASE1 + buf * B_BUF1 + (lane & 3) * BST + n0 + (lane >> 2);
#pragma unroll
        for (int kk = 0; kk < 4; ++kk) {
            uint32_t ah[2][4];
#pragma unroll
            for (int i = 0; i < 2; ++i) {
                const uint32_t* p = asb + (i << 4) * AST1 + (kk << 3);
                ah[i][0] = p[0];
                ah[i][1] = p[8 * AST1];
                ah[i][2] = p[4];
                ah[i][3] = p[8 * AST1 + 4];
            }
#pragma unroll
            for (int j = 0; j < 8; ++j) {
                const uint32_t* q = bsb + (kk << 3) * BST + (j << 3);
                uint32_t bh[2];
                bh[0] = q[0];
                bh[1] = q[4 * BST];
#pragma unroll
                for (int i = 0; i < 2; ++i)
                    mma8(c[i][j], ah[i], bh);
            }
        }

        if (more) store_chunk(buf ^ 1);
        __syncthreads();
        buf ^= 1;
    }

#pragma unroll
    for (int i = 0; i < 2; ++i) {
        const long row = row0 + m0 + (i << 4) + (lane >> 2);
#pragma unroll
        for (int j = 0; j < 8; ++j) {
            const int col = col0 + n0 + (j << 3) + ((lane & 3) << 1);
            if (col < N) {
                const float2 bv = *(const float2*)(bias + col);
                float v0 = c[i][j][0] + bv.x;
                float v1 = c[i][j][1] + bv.y;
                float v2 = c[i][j][2] + bv.x;
                float v3 = c[i][j][3] + bv.y;
                if (relu) {
                    v0 = fmaxf(v0, 0.f); v1 = fmaxf(v1, 0.f);
                    v2 = fmaxf(v2, 0.f); v3 = fmaxf(v3, 0.f);
                }
                float2 o0 = {v0, v1}, o1 = {v2, v3};
                *(float2*)(C + row * (long)ldc + col)       = o0;
                *(float2*)(C + (row + 8) * (long)ldc + col) = o1;
            }
        }
    }
}

// ==== res2 fused with res3 projection: r2 never hits DRAM ====
// Computes r2 = relu(r1@W2 + b2) in registers, projects through W3 [256,8],
// writes per-slot partials (slot = blockIdx.x*2 + n-warp; disjoint 64-col ranges).
__global__ __launch_bounds__(256, 2) void mma_gemm1_res2(
    const float* __restrict__ A,      // r1 [rows,256]
    const float* __restrict__ W,      // res_W2 [256,256]
    const float* __restrict__ bias,   // res_b2 [256]
    const float* __restrict__ W3,     // res_W3 [256,8]
    float* __restrict__ partial)      // [4][rows][8]
{
    extern __shared__ uint32_t smem[];
    const int K = 256, N = 256;
    uint32_t* wsu = smem + BS_BASE1 + 2 * B_BUF1;   // W3 staging: 2048 u32
    float* ws = (float*)wsu;

    const long row0 = (long)blockIdx.y << 7;
    const int  col0 = blockIdx.x << 7;

    const int tid  = threadIdx.x;
    const int lane = tid & 31;
    const int wid  = tid >> 5;
    const int m0 = (wid & 3) << 5;
    const int n0 = (wid >> 2) << 6;

    const int arow = tid >> 1;
    const int ak16 = (tid & 1) << 4;
    const int bn   = lane << 2;

    const float* Ap = A + (row0 + arow) * (long)K + ak16;
    const float* Wp = W + (long)col0 + bn;

    float4 a4[4], b4[4];

    auto load_chunk = [&](int k0) {
#pragma unroll
        for (int s = 0; s < 4; ++s) {
            a4[s] = *(const float4*)(Ap + k0 + (s << 2));
            b4[s] = *(const float4*)(Wp + (long)(k0 + wid + (s << 3)) * N);
        }
    };
    auto store_chunk = [&](int nb) {
        uint32_t* ab = smem + nb * A_BUF1 + arow * AST1 + ak16;
        uint32_t* bb = smem + BS_BASE1 + nb * B_BUF1 + wid * BST + bn;
#pragma unroll
        for (int s = 0; s < 4; ++s) {
            uint4 t;
            t.x = f2tf32(a4[s].x); t.y = f2tf32(a4[s].y);
            t.z = f2tf32(a4[s].z); t.w = f2tf32(a4[s].w);
            *(uint4*)(ab + (s << 2)) = t;
            uint32_t* b = bb + (s << 3) * BST;
            b[0] = f2tf32(b4[s].x); b[1] = f2tf32(b4[s].y);
            b[2] = f2tf32(b4[s].z); b[3] = f2tf32(b4[s].w);
        }
    };

    // stage W3 (256*8 floats)
#pragma unroll
    for (int q = 0; q < 8; ++q) ws[tid + q * 256] = W3[tid + q * 256];

    load_chunk(0);
    store_chunk(0);
    __syncthreads();

    float c[2][8][4] = {};
    int buf = 0;
    for (int ch = 0; ch < 8; ++ch) {        // K=256 -> 8 chunks
        const bool more = (ch + 1) < 8;
        if (more) load_chunk((ch + 1) << 5);

        const uint32_t* asb = smem + buf * A_BUF1 + (m0 + (lane >> 2)) * AST1 + (lane & 3);
        const uint32_t* bsb = smem + BS_BASE1 + buf * B_BUF1 + (lane & 3) * BST + n0 + (lane >> 2);
#pragma unroll
        for (int kk = 0; kk < 4; ++kk) {
            uint32_t ah[2][4];
#pragma unroll
            for (int i = 0; i < 2; ++i) {
                const uint32_t* p = asb + (i << 4) * AST1 + (kk << 3);
                ah[i][0] = p[0];
                ah[i][1] = p[8 * AST1];
                ah[i][2] = p[4];
                ah[i][3] = p[8 * AST1 + 4];
            }
#pragma unroll
            for (int j = 0; j < 8; ++j) {
                const uint32_t* q = bsb + (kk << 3) * BST + (j << 3);
                uint32_t bh[2];
                bh[0] = q[0];
                bh[1] = q[4 * BST];
#pragma unroll
                for (int i = 0; i < 2; ++i)
                    mma8(c[i][j], ah[i], bh);
            }
        }

        if (more) store_chunk(buf ^ 1);
        __syncthreads();
        buf ^= 1;
    }

    // epilogue: bias + relu, project through W3, quarter-warp reduce, store partials
    const int slot = blockIdx.x * 2 + (wid >> 2);
    float* pbase = partial + (long)slot * ((long)Bsz * FcN * 8);
#pragma unroll
    for (int i = 0; i < 2; ++i) {
        float pa[8] = {}, pb[8] = {};
#pragma unroll
        for (int j = 0; j < 8; ++j) {
            const int col = col0 + n0 + (j << 3) + ((lane & 3) << 1);
            const float2 bv = *(const float2*)(bias + col);
            const float v0 = fmaxf(c[i][j][0] + bv.x, 0.f);
            const float v1 = fmaxf(c[i][j][1] + bv.y, 0.f);
            const float v2 = fmaxf(c[i][j][2] + bv.x, 0.f);
            const float v3 = fmaxf(c[i][j][3] + bv.y, 0.f);
            const float* w0 = ws + col * 8;
            const float* w1 = w0 + 8;
#pragma unroll
            for (int t = 0; t < 8; ++t) {
                pa[t] = fmaf(v0, w0[t], fmaf(v1, w1[t], pa[t]));
                pb[t] = fmaf(v2, w0[t], fmaf(v3, w1[t], pb[t]));
            }
        }
#pragma unroll
        for (int t = 0; t < 8; ++t) {
            pa[t] += __shfl_xor_sync(0xffffffffu, pa[t], 1);
            pa[t] += __shfl_xor_sync(0xffffffffu, pa[t], 2);
            pb[t] += __shfl_xor_sync(0xffffffffu, pb[t], 1);
            pb[t] += __shfl_xor_sync(0xffffffffu, pb[t], 2);
        }
        if ((lane & 3) == 0) {
            const long rowA = row0 + m0 + (i << 4) + (lane >> 2);
            float* pA = pbase + rowA * 8;
            float* pB = pA + 64;   // rowA + 8
#pragma unroll
            for (int t = 0; t < 4; ++t) {
                float2 va = {pa[2 * t], pa[2 * t + 1]};
                float2 vb = {pb[2 * t], pb[2 * t + 1]};
                *(float2*)(pA + 2 * t) = va;
                *(float2*)(pB + 2 * t) = vb;
            }
        }
    }
}

// finalize: xequ = xeq1 + b3 + sum of 4 partials
__global__ void res3_fin(const float* __restrict__ partial, const float* __restrict__ b3,
                         const float* __restrict__ xeq1, float* __restrict__ xequ)
{
    const long i = (long)blockIdx.x * blockDim.x + threadIdx.x;
    const long R8 = (long)Bsz * FcN * 8;
    if (i >= R8) return;
    const int t = (int)(i & 7);
    float s = xeq1[i] + b3[t];
    s += partial[i];
    s += partial[R8 + i];
    s += partial[2 * R8 + i];
    s += partial[3 * R8 + i];
    xequ[i] = s;
}

__global__ void stats_kernel(const float* __restrict__ h, int C, float* __restrict__ part) {
    const int v = blockIdx.x, s = blockIdx.y, c = threadIdx.x;
    const long stride = (long)Vn * C;
    const float* p = h + ((long)(s * 256) * Vn + v) * C + c;
    float sum = 0.f, sq = 0.f;
#pragma unroll 4
    for (int i = 0; i < 256; ++i) {
        float val = p[(long)i * stride];
        sum += val;
        sq = fmaf(val, val, sq);
    }
    const long o = (((long)s * Vn + v) * C + c) * 2;
    part[o] = sum; part[o + 1] = sq;
}

__global__ void fuse_kernel(const float* __restrict__ W, const float* __restrict__ bias,
                            const float* __restrict__ g, const float* __restrict__ be,
                            int Cin, int Nout,
                            float* __restrict__ Wp, float* __restrict__ bp)
{
    const int v = blockIdx.x, tid = threadIdx.x;
    __shared__ float sa[512], sc[512];
    for (int n = tid; n < Cin; n += blockDim.x) {
        float sum = 0.f, sq = 0.f;
        for (int s = 0; s < 32; ++s) {
            const long o = (((long)s * Vn + v) * Cin + n) * 2;
            sum += g_part[o]; sq += g_part[o + 1];
        }
        const float mu  = sum * (1.f / Bsz);
        const float var = sq * (1.f / Bsz) - mu * mu;
        const float rs  = rsqrtf(var + BNEPS);
        const float a   = g[v * Cin + n] * rs;
        sa[n] = a;
        sc[n] = be[v * Cin + n] - mu * a;
    }
    __syncthreads();
    const int slice = (Nout + gridDim.y - 1) / gridDim.y;
    const int j0 = blockIdx.y * slice;
    const int j1 = min(j0 + slice, Nout);
    const float* wv = W + (long)v * Cin * Nout;
    float* wpv = Wp + (long)v * Cin * Nout;
    for (int j = j0 + tid; j < j1; j += blockDim.x) {
        float acc = bias[v * Nout + j];
        for (int n = 0; n < Cin; ++n) {
            const float w = wv[(long)n * Nout + j];
            wpv[(long)n * Nout + j] = sa[n] * w;
            acc = fmaf(sc[n], w, acc);
        }
        bp[v * Nout + j] = acc;
    }
}

__global__ void combine_kernel(float* __restrict__ enc_sig) {
    const int b = blockIdx.x;
    const int d = threadIdx.x;
    const int warp = d >> 5, lane = d & 31;
    __shared__ float partial[16][8];
    __shared__ float alpha[8];

    float ev[8];
    float s[8];
#pragma unroll
    for (int v = 0; v < 8; ++v) {
        ev[v] = g_e[((long)b * Vn + v) * 512 + d];
        s[v] = ev[v] * ev[v];
    }
#pragma unroll
    for (int v = 0; v < 8; ++v)
#pragma unroll
        for (int o = 16; o; o >>= 1) s[v] += __shfl_xor_sync(0xffffffffu, s[v], o);
    if (lane == 0)
#pragma unroll
        for (int v = 0; v < 8; ++v) partial[warp][v] = s[v];
    __syncthreads();
    if (warp < 8 && lane < 16) {
        float t = partial[lane][warp];
#pragma unroll
        for (int o = 8; o; o >>= 1) t += __shfl_xor_sync(0xffffu, t, o);
        if (lane == 0) alpha[warp] = 8.f * rsqrtf(t);
    }
    __syncthreads();
    float acc = 0.f;
#pragma unroll
    for (int v = 0; v < 8; ++v) acc = fmaf(alpha[v], ev[v], acc);
    enc_sig[(long)b * 512 + d] = acc * 0.70710678118654752f;
}

struct C2 { float x, y; };
__device__ __forceinline__ C2 cmul(C2 a, C2 b) { return {a.x*b.x - a.y*b.y, a.x*b.y + a.y*b.x}; }
__device__ __forceinline__ C2 cmulc(C2 a, C2 b) { return {a.x*b.x + a.y*b.y, a.x*b.y - a.y*b.x}; }

__global__ void channel_kernel(const float* __restrict__ Hri, const float* __restrict__ noiseri,
                               const float* __restrict__ encsig,
                               float* __restrict__ yout, float* __restrict__ xeq1out)
{
    const int b = blockIdx.x;
    const int f = threadIdx.x;
    __shared__ C2 H[4][4];
    __shared__ C2 Ainv[4][4];
    const float is2 = 0.70710678118654752f;

    if (f < 16) {
        const int r = f >> 2, t = f & 3;
        const long o = (((long)(b * 4 + r)) * 4 + t) * 2;
        H[r][t] = {Hri[o] * is2, Hri[o + 1] * is2};
    }
    __syncthreads();

    const float lam = g_consts[0];
    const float nsc = g_consts[1];

    if (f == 0) {
        C2 Am[4][8];
        for (int i = 0; i < 4; ++i) {
            for (int j = 0; j < 4; ++j) {
                C2 a = {0.f, 0.f};
                for (int r = 0; r < 4; ++r) {
                    C2 p = cmulc(H[r][i], H[r][j]);
                    a.x += p.x; a.y += p.y;
                }
                if (i == j) a.x += lam;
                Am[i][j] = a;
                Am[i][4 + j] = (i == j) ? C2{1.f, 0.f} : C2{0.f, 0.f};
            }
        }
        for (int p = 0; p < 4; ++p) {
            C2 dg = Am[p][p];
            const float inv = 1.f / (dg.x * dg.x + dg.y * dg.y);
            const C2 dinv = {dg.x * inv, -dg.y * inv};
            for (int j = 0; j < 8; ++j) Am[p][j] = cmul(Am[p][j], dinv);
            for (int r = 0; r < 4; ++r) {
                if (r == p) continue;
                const C2 fac = Am[r][p];
                for (int j = 0; j < 8; ++j) {
                    const C2 q = cmul(fac, Am[p][j]);
                    Am[r][j].x -= q.x; Am[r][j].y -= q.y;
                }
            }
        }
        for (int i = 0; i < 4; ++i)
            for (int j = 0; j < 4; ++j)
                Ainv[i][j] = Am[i][4 + j];
    }
    __syncthreads();

    C2 s[4];
#pragma unroll
    for (int t = 0; t < 4; ++t) {
        const long o = ((long)b * 512) + ((long)(f * 4 + t)) * 2;
        s[t] = {encsig[o], encsig[o + 1]};
    }
    const long nbase = ((long)(b * 64 + f)) * 8;
    C2 yv[4];
#pragma unroll
    for (int r = 0; r < 4; ++r) {
        C2 a = {0.f, 0.f};
#pragma unroll
        for (int t = 0; t < 4; ++t) { C2 p = cmul(H[r][t], s[t]); a.x += p.x; a.y += p.y; }
        a.x += nsc * noiseri[nbase + r * 2]     * is2;
        a.y += nsc * noiseri[nbase + r * 2 + 1] * is2;
        yv[r] = a;
        yout[nbase + r * 2]     = a.x;
        yout[nbase + r * 2 + 1] = a.y;
    }
    C2 hy[4];
#pragma unroll
    for (int t = 0; t < 4; ++t) {
        C2 a = {0.f, 0.f};
#pragma unroll
        for (int r = 0; r < 4; ++r) { C2 p = cmulc(H[r][t], yv[r]); a.x += p.x; a.y += p.y; }
        hy[t] = a;
    }
#pragma unroll
    for (int t = 0; t < 4; ++t) {
        C2 a = {0.f, 0.f};
#pragma unroll
        for (int k = 0; k < 4; ++k) { C2 p = cmul(Ainv[t][k], hy[k]); a.x += p.x; a.y += p.y; }
        xeq1out[nbase + t * 2]     = a.x;
        xeq1out[nbase + t * 2 + 1] = a.y;
    }
    float* hyp = &g_HY[((long)(b * 64 + f)) * 40];
#pragma unroll
    for (int r = 0; r < 4; ++r)
#pragma unroll
        for (int t = 0; t < 4; ++t) {
            hyp[(r * 4 + t) * 2]     = H[r][t].x;
            hyp[(r * 4 + t) * 2 + 1] = H[r][t].y;
        }
#pragma unroll
    for (int r = 0; r < 4; ++r) {
        hyp[32 + r * 2]     = yv[r].x;
        hyp[32 + r * 2 + 1] = yv[r].y;
    }
}

__global__ void emit_kernel(const float* __restrict__ src, float* __restrict__ out,
                            long off, long n, long out_size, int mode) {
    const long i = (long)blockIdx.x * blockDim.x + threadIdx.x;
    if (i >= n) return;
    const long o = off + i;
    if (o >= out_size) return;
    out[o] = (mode == 0) ? src[i] : src[2 * i];
}

extern "C" void kernel_launch(void* const* d_in, const int* in_sizes, int n_in,
                              void* d_out, int out_size) {
    const float* x        = (const float*)d_in[0];
    const int*   snr      = (const int*)  d_in[1];
    const float* H_ri     = (const float*)d_in[2];
    const float* noise_ri = (const float*)d_in[3];
    const float* enc_W1 = (const float*)d_in[4];  const float* enc_b1 = (const float*)d_in[5];
    const float* enc_g1 = (const float*)d_in[6];  const float* enc_be1= (const float*)d_in[7];
    const float* enc_W2 = (const float*)d_in[8];  const float* enc_b2 = (const float*)d_in[9];
    const float* enc_g2 = (const float*)d_in[10]; const float* enc_be2= (const float*)d_in[11];
    const float* enc_W3 = (const float*)d_in[12]; const float* enc_b3 = (const float*)d_in[13];
    const float* dec_W1 = (const float*)d_in[14]; const float* dec_b1 = (const float*)d_in[15];
    const float* dec_g1 = (const float*)d_in[16]; const float* dec_be1= (const float*)d_in[17];
    const float* dec_W2 = (const float*)d_in[18]; const float* dec_b2 = (const float*)d_in[19];
    const float* dec_g2 = (const float*)d_in[20]; const float* dec_be2= (const float*)d_in[21];
    const float* dec_W3 = (const float*)d_in[22]; const float* dec_b3 = (const float*)d_in[23];
    const float* res_W1 = (const float*)d_in[24]; const float* res_b1 = (const float*)d_in[25];
    const float* res_W2 = (const float*)d_in[26]; const float* res_b2 = (const float*)d_in[27];
    const float* res_W3 = (const float*)d_in[28]; const float* res_b3 = (const float*)d_in[29];

    float *h1, *h2, *e, *hd1, *hd2, *HY, *r1, *r3p;
    float *Ps, *ys, *xequs, *xeq1s, *sigs;
    float *W2e, *b2e, *W3e, *b3e, *W2d, *b2d, *W3d, *b3d, *part;
    cudaGetSymbolAddress((void**)&h1,  g_h1);
    cudaGetSymbolAddress((void**)&h2,  g_h2);
    cudaGetSymbolAddress((void**)&e,   g_e);
    cudaGetSymbolAddress((void**)&hd1, g_hd1);
    cudaGetSymbolAddress((void**)&hd2, g_hd2);
    cudaGetSymbolAddress((void**)&HY,  g_HY);
    cudaGetSymbolAddress((void**)&r1,  g_r1);
    cudaGetSymbolAddress((void**)&r3p, g_r3p);
    cudaGetSymbolAddress((void**)&Ps,    g_P);
    cudaGetSymbolAddress((void**)&ys,    g_y);
    cudaGetSymbolAddress((void**)&xequs, g_xequ);
    cudaGetSymbolAddress((void**)&xeq1s, g_xeq1);
    cudaGetSymbolAddress((void**)&sigs,  g_sig);
    cudaGetSymbolAddress((void**)&W2e, g_W2e); cudaGetSymbolAddress((void**)&b2e, g_b2e);
    cudaGetSymbolAddress((void**)&W3e, g_W3e); cudaGetSymbolAddress((void**)&b3e, g_b3e);
    cudaGetSymbolAddress((void**)&W2d, g_W2d); cudaGetSymbolAddress((void**)&b2d, g_b2d);
    cudaGetSymbolAddress((void**)&W3d, g_W3d); cudaGetSymbolAddress((void**)&b3d, g_b3d);
    cudaGetSymbolAddress((void**)&part, g_part);

    float* out = (float*)d_out;
    const long LP = 2097152, LY = 4194304, LX = 4194304, LS = 4194304;
    const long FULL = LP + LY + LX + LX + LS;
    const bool direct = ((long)out_size == FULL);
    float* P    = direct ? out                     : Ps;
    float* y    = direct ? out + LP                : ys;
    float* xequ = direct ? out + LP + LY           : xequs;
    float* xeq1 = direct ? out + LP + LY + LX      : xeq1s;
    float* sig  = direct ? out + LP + LY + LX + LX : sigs;

    const int SMB3  = (2 * A_BUF3 + 2 * B_BUF3) * 4;            // 75776 B
    const int SMB1  = (2 * A_BUF1 + 2 * B_BUF1) * 4;            // 71680 B
    const int SMB1R = (2 * A_BUF1 + 2 * B_BUF1 + 2048) * 4;     // + W3 staging
    cudaFuncSetAttribute(mma_gemm3, cudaFuncAttributeMaxDynamicSharedMemorySize, SMB3);
    cudaFuncSetAttribute(mma_gemm1, cudaFuncAttributeMaxDynamicSharedMemorySize, SMB1);
    cudaFuncSetAttribute(mma_gemm1_res2, cudaFuncAttributeMaxDynamicSharedMemorySize, SMB1R);

    prep_kernel<<<1, 1>>>(snr);

    // ---- encoder: enc1/enc2 3x, enc3 1x ----
    mma_gemm3<<<dim3(1, 64, 8), 512, SMB3>>>(x, 256, 32, enc_W1, 32 * 128, enc_b1, 128,
                                             h1, 1024, 128, 32, 128, 1);
    stats_kernel<<<dim3(8, 32), 128>>>(h1, 128, part);
    fuse_kernel<<<dim3(8, 8), 256>>>(enc_W2, enc_b2, enc_g1, enc_be1, 128, 128, W2e, b2e);
    mma_gemm3<<<dim3(1, 64, 8), 512, SMB3>>>(h1, 1024, 128, W2e, 128 * 128, b2e, 128,
                                             h2, 1024, 128, 128, 128, 1);
    stats_kernel<<<dim3(8, 32), 128>>>(h2, 128, part);
    fuse_kernel<<<dim3(8, 8), 256>>>(enc_W3, enc_b3, enc_g2, enc_be2, 128, 512, W3e, b3e);
    mma_gemm1<<<dim3(4, 64, 8), 256, SMB1>>>(h2, 1024, 128, W3e, 128 * 512, b3e, 512,
                                             e, 4096, 512, 128, 512, 0);
    combine_kernel<<<8192, 512>>>(sig);

    // ---- channel + MMSE ----
    channel_kernel<<<8192, 64>>>(H_ri, noise_ri, sig, y, xeq1);

    // ---- residual MLP: res1 (1x), res2+res3 fused, finalize ----
    mma_gemm1<<<dim3(2, 4096, 1), 256, SMB1>>>(HY, 40, 0, res_W1, 0, res_b1, 0,
                                               r1, 256, 0, 40, 256, 1);
    mma_gemm1_res2<<<dim3(2, 4096, 1), 256, SMB1R>>>(r1, res_W2, res_b2, res_W3, r3p);
    res3_fin<<<16384, 256>>>(r3p, res_b3, xeq1, xequ);

    // ---- decoder: dec1 3x, dec2 1x, dec3 1x ----
    mma_gemm3<<<dim3(2, 64, 8), 512, SMB3>>>(xequ, 512, 0, dec_W1, 512 * 256, dec_b1, 256,
                                             hd1, 2048, 256, 512, 256, 1);
    stats_kernel<<<dim3(8, 32), 256>>>(hd1, 256, part);
    fuse_kernel<<<dim3(8, 8), 256>>>(dec_W2, dec_b2, dec_g1, dec_be1, 256, 256, W2d, b2d);
    mma_gemm1<<<dim3(2, 64, 8), 256, SMB1>>>(hd1, 2048, 256, W2d, 256 * 256, b2d, 256,
                                             hd2, 2048, 256, 256, 256, 1);
    stats_kernel<<<dim3(8, 32), 256>>>(hd2, 256, part);
    fuse_kernel<<<dim3(8, 8), 256>>>(dec_W3, dec_b3, dec_g2, dec_be2, 256, 32, W3d, b3d);
    mma_gemm1<<<dim3(1, 64, 8), 256, SMB1>>>(hd2, 2048, 256, W3d, 256 * 32, b3d, 32,
                                             P, 256, 32, 256, 32, 0);

    // ---- fallback emission only if layout differs ----
    if (!direct) {
        const long osz = (long)out_size;
        auto emit = [&](const float* src, long off, long n, int mode) {
            if (off >= osz || n <= 0) return;
            long grid = (n + 255) / 256;
            emit_kernel<<<(unsigned)grid, 256>>>(src, out, off, n, osz, mode);
        };
        if (osz == LP + LY/2 + LX + LX + LS) {
            long off = 0;
            emit(P,    off, LP,   0); off += LP;
            emit(y,    off, LY/2, 1); off += LY/2;
            emit(xequ, off, LX,   0); off += LX;
            emit(xeq1, off, LX,   0); off += LX;
            emit(sig,  off, LS,   0);
        } else {
            long off = 0;
            emit(P,    off, LP, 0); off += LP;
            emit(y,    off, LY, 0); off += LY;
            emit(xequ, off, LX, 0); off += LX;
            emit(xeq1, off, LX, 0); off += LX;
            emit(sig,  off, LS, 0);
        }
    }
}

// round 16
// speedup vs baseline: 1.8754x; 1.0934x over previous
#include <cuda_runtime.h>
#include <math.h>
#include <stdint.h>

#define Bsz 8192
#define Vn  8
#define FcN 64
#define BNEPS 1e-5f

__device__ float g_h1 [(size_t)Bsz*Vn*128];
__device__ float g_h2 [(size_t)Bsz*Vn*128];
__device__ float g_e  [(size_t)Bsz*Vn*512];
__device__ float g_hd1[(size_t)Bsz*Vn*256];
__device__ float g_hd2[(size_t)Bsz*Vn*256];
__device__ float g_HY [(size_t)Bsz*FcN*40];
__device__ float g_r3p[(size_t)4*Bsz*FcN*8];
__device__ float g_P   [(size_t)Bsz*Vn*32];
__device__ float g_y   [(size_t)Bsz*FcN*8];
__device__ float g_xequ[(size_t)Bsz*FcN*8];
__device__ float g_xeq1[(size_t)Bsz*FcN*8];
__device__ float g_sig [(size_t)Bsz*512];
__device__ float g_W2e[Vn*128*128]; __device__ float g_b2e[Vn*128];
__device__ float g_W3e[Vn*128*512]; __device__ float g_b3e[Vn*512];
__device__ float g_W2d[Vn*256*256]; __device__ float g_b2d[Vn*256];
__device__ float g_W3d[Vn*256*32];  __device__ float g_b3d[Vn*32];
__device__ float g_part[32*Vn*256*2];
__device__ float g_consts[4];

__device__ __forceinline__ uint32_t f2tf32(float f) {
    uint32_t r; asm("cvt.rna.tf32.f32 %0, %1;" : "=r"(r) : "f"(f)); return r;
}
__device__ __forceinline__ void split_tf32(float f, uint32_t& hi, uint32_t& lo) {
    hi = f2tf32(f);
    lo = f2tf32(f - __uint_as_float(hi));
}
__device__ __forceinline__ void mma8(float* c, const uint32_t* a, const uint32_t* b) {
    asm volatile(
        "mma.sync.aligned.m16n8k8.row.col.f32.tf32.tf32.f32 "
        "{%0,%1,%2,%3}, {%4,%5,%6,%7}, {%8,%9}, {%0,%1,%2,%3};"
        : "+f"(c[0]), "+f"(c[1]), "+f"(c[2]), "+f"(c[3])
        : "r"(a[0]), "r"(a[1]), "r"(a[2]), "r"(a[3]), "r"(b[0]), "r"(b[1]));
}

__global__ void prep_kernel(const int* __restrict__ snrp) {
    int iv = *snrp;
    float S;
    if (iv >= -1000 && iv <= 1000) S = (float)iv;
    else                            S = __int_as_float(iv);
    float snr = powf(10.f, -S * 0.1f);
    g_consts[0] = 4.f * snr;
    g_consts[1] = sqrtf(4.f * snr);
}

// ================= 3-term GEMM (round-7 proven) ==========
#define AST 20
#define BST 136
#define AS_SZ   (128 * AST)
#define BS_SZ   (16 * BST)
#define A_BUF3  (2 * AS_SZ)
#define B_BUF3  (2 * BS_SZ)
#define BS_BASE3 (2 * A_BUF3)

__global__ __launch_bounds__(512) void mma_gemm3(
    const float* __restrict__ A, int lda, long sAv,
    const float* __restrict__ W, long sWv,
    const float* __restrict__ bias, int sbv,
    float* __restrict__ C, int ldc, long sCv,
    int K, int N, int relu)
{
    extern __shared__ uint32_t smem[];

    const int v = blockIdx.z;
    A    += (long)v * sAv;
    W    += (long)v * sWv;
    bias += (long)v * sbv;
    C    += (long)v * sCv;

    const long row0 = (long)blockIdx.y << 7;
    const int  col0 = blockIdx.x << 7;

    const int tid  = threadIdx.x;
    const int lane = tid & 31;
    const int wid  = tid >> 5;
    const int m0 = (wid & 3) << 5;
    const int n0 = (wid >> 2) << 5;

    const int ar  = tid >> 2;
    const int akq = (tid & 3) << 2;
    const int bk  = tid >> 5;
    const int bnq = (tid & 31) << 2;
    const bool bok = (col0 + bnq) < N;

    const float* Ap = A + (row0 + ar) * (long)lda;
    const float* Wp = W + (long)col0 + bnq;

    const int nch = (K + 15) >> 4;

    auto store_tiles = [&](int nb, float4 a4, float4 b4) {
        uint32_t* ash = smem + nb * A_BUF3 + ar * AST + akq;
        uint32_t* asl = ash + AS_SZ;
        split_tf32(a4.x, ash[0], asl[0]); split_tf32(a4.y, ash[1], asl[1]);
        split_tf32(a4.z, ash[2], asl[2]); split_tf32(a4.w, ash[3], asl[3]);
        uint32_t* bsh = smem + BS_BASE3 + nb * B_BUF3 + bk * BST + bnq;
        uint32_t* bsl = bsh + BS_SZ;
        split_tf32(b4.x, bsh[0], bsl[0]); split_tf32(b4.y, bsh[1], bsl[1]);
        split_tf32(b4.z, bsh[2], bsl[2]); split_tf32(b4.w, bsh[3], bsl[3]);
    };

    {
        float4 a4 = make_float4(0.f, 0.f, 0.f, 0.f);
        if (akq < K) a4 = *(const float4*)(Ap + akq);
        float4 b4 = make_float4(0.f, 0.f, 0.f, 0.f);
        if (bok && bk < K) b4 = *(const float4*)(Wp + (long)bk * N);
        store_tiles(0, a4, b4);
    }
    __syncthreads();

    float c[2][4][4] = {};
    int buf = 0;
    for (int ch = 0; ch < nch; ++ch) {
        float4 a4 = make_float4(0.f, 0.f, 0.f, 0.f);
        float4 b4 = make_float4(0.f, 0.f, 0.f, 0.f);
        const int nk0 = (ch + 1) << 4;
        const bool more = (ch + 1) < nch;
        if (more) {
            if (nk0 + akq < K) a4 = *(const float4*)(Ap + nk0 + akq);
            if (bok && (nk0 + bk) < K) b4 = *(const float4*)(Wp + (long)(nk0 + bk) * N);
        }

        const uint32_t* asb = smem + buf * A_BUF3 + (m0 + (lane >> 2)) * AST + (lane & 3);
        const uint32_t* bsb = smem + BS_BASE3 + buf * B_BUF3 + (lane & 3) * BST + n0 + (lane >> 2);
#pragma unroll
        for (int kk = 0; kk < 2; ++kk) {
            uint32_t ah[2][4], al[2][4];
#pragma unroll
            for (int i = 0; i < 2; ++i) {
                const uint32_t* p = asb + (i << 4) * AST + (kk << 3);
                ah[i][0] = p[0];
                ah[i][1] = p[8 * AST];
                ah[i][2] = p[4];
                ah[i][3] = p[8 * AST + 4];
                const uint32_t* pl = p + AS_SZ;
                al[i][0] = pl[0];
                al[i][1] = pl[8 * AST];
                al[i][2] = pl[4];
                al[i][3] = pl[8 * AST + 4];
            }
            uint32_t bh[4][2], bl[4][2];
#pragma unroll
            for (int j = 0; j < 4; ++j) {
                const uint32_t* q = bsb + (kk << 3) * BST + (j << 3);
                bh[j][0] = q[0];
                bh[j][1] = q[4 * BST];
                const uint32_t* ql = q + BS_SZ;
                bl[j][0] = ql[0];
                bl[j][1] = ql[4 * BST];
            }
#pragma unroll
            for (int i = 0; i < 2; ++i)
#pragma unroll
                for (int j = 0; j < 4; ++j) {
                    mma8(c[i][j], al[i], bh[j]);
                    mma8(c[i][j], ah[i], bl[j]);
                    mma8(c[i][j], ah[i], bh[j]);
                }
        }

        if (more) store_tiles(buf ^ 1, a4, b4);
        __syncthreads();
        buf ^= 1;
    }

#pragma unroll
    for (int i = 0; i < 2; ++i) {
        const long row = row0 + m0 + (i << 4) + (lane >> 2);
#pragma unroll
        for (int j = 0; j < 4; ++j) {
            const int col = col0 + n0 + (j << 3) + ((lane & 3) << 1);
            if (col < N) {
                const float2 bv = *(const float2*)(bias + col);
                float v0 = c[i][j][0] + bv.x;
                float v1 = c[i][j][1] + bv.y;
                float v2 = c[i][j][2] + bv.x;
                float v3 = c[i][j][3] + bv.y;
                if (relu) {
                    v0 = fmaxf(v0, 0.f); v1 = fmaxf(v1, 0.f);
                    v2 = fmaxf(v2, 0.f); v3 = fmaxf(v3, 0.f);
                }
                float2 o0 = {v0, v1}, o1 = {v2, v3};
                *(float2*)(C + row * (long)ldc + col)       = o0;
                *(float2*)(C + (row + 8) * (long)ldc + col) = o1;
            }
        }
    }
}

// ==== 1-term GEMM (round-14 proven): 256 thr, warp 32x64, K-chunk 32 ====
#define AST1 36
#define A_BUF1 (128 * AST1)
#define B_BUF1 (32 * BST)
#define BS_BASE1 (2 * A_BUF1)

__global__ __launch_bounds__(256, 2) void mma_gemm1(
    const float* __restrict__ A, int lda, long sAv,
    const float* __restrict__ W, long sWv,
    const float* __restrict__ bias, int sbv,
    float* __restrict__ C, int ldc, long sCv,
    int K, int N, int relu)
{
    extern __shared__ uint32_t smem[];

    const int v = blockIdx.z;
    A    += (long)v * sAv;
    W    += (long)v * sWv;
    bias += (long)v * sbv;
    C    += (long)v * sCv;

    const long row0 = (long)blockIdx.y << 7;
    const int  col0 = blockIdx.x << 7;

    const int tid  = threadIdx.x;
    const int lane = tid & 31;
    const int wid  = tid >> 5;
    const int m0 = (wid & 3) << 5;
    const int n0 = (wid >> 2) << 6;

    const int arow = tid >> 1;
    const int ak16 = (tid & 1) << 4;
    const int bn   = lane << 2;
    const bool bok = (col0 + bn) < N;

    const float* Ap = A + (row0 + arow) * (long)lda + ak16;
    const float* Wp = W + (long)col0 + bn;

    const int nch = (K + 31) >> 5;

    float4 a4[4], b4[4];

    auto load_chunk = [&](int k0) {
#pragma unroll
        for (int s = 0; s < 4; ++s) {
            const int ka = k0 + ak16 + (s << 2);
            a4[s] = make_float4(0.f, 0.f, 0.f, 0.f);
            if (ka < K) a4[s] = *(const float4*)(Ap + k0 + (s << 2));
            const int kb = k0 + wid + (s << 3);
            b4[s] = make_float4(0.f, 0.f, 0.f, 0.f);
            if (bok && kb < K) b4[s] = *(const float4*)(Wp + (long)kb * N);
        }
    };

    auto store_chunk = [&](int nb) {
        uint32_t* ab = smem + nb * A_BUF1 + arow * AST1 + ak16;
        uint32_t* bb = smem + BS_BASE1 + nb * B_BUF1 + wid * BST + bn;
#pragma unroll
        for (int s = 0; s < 4; ++s) {
            uint4 t;
            t.x = f2tf32(a4[s].x); t.y = f2tf32(a4[s].y);
            t.z = f2tf32(a4[s].z); t.w = f2tf32(a4[s].w);
            *(uint4*)(ab + (s << 2)) = t;
            uint32_t* b = bb + (s << 3) * BST;
            b[0] = f2tf32(b4[s].x); b[1] = f2tf32(b4[s].y);
            b[2] = f2tf32(b4[s].z); b[3] = f2tf32(b4[s].w);
        }
    };

    load_chunk(0);
    store_chunk(0);
    __syncthreads();

    float c[2][8][4] = {};
    int buf = 0;
    for (int ch = 0; ch < nch; ++ch) {
        const bool more = (ch + 1) < nch;
        if (more) load_chunk((ch + 1) << 5);

        const uint32_t* asb = smem + buf * A_BUF1 + (m0 + (lane >> 2)) * AST1 + (lane & 3);
        const uint32_t* bsb = smem + BS_BASE1 + buf * B_BUF1 + (lane & 3) * BST + n0 + (lane >> 2);
#pragma unroll
        for (int kk = 0; kk < 4; ++kk) {
            uint32_t ah[2][4];
#pragma unroll
            for (int i = 0; i < 2; ++i) {
                const uint32_t* p = asb + (i << 4) * AST1 + (kk << 3);
                ah[i][0] = p[0];
                ah[i][1] = p[8 * AST1];
                ah[i][2] = p[4];
                ah[i][3] = p[8 * AST1 + 4];
            }
#pragma unroll
            for (int j = 0; j < 8; ++j) {
                const uint32_t* q = bsb + (kk << 3) * BST + (j << 3);
                uint32_t bh[2];
                bh[0] = q[0];
                bh[1] = q[4 * BST];
#pragma unroll
                for (int i = 0; i < 2; ++i)
                    mma8(c[i][j], ah[i], bh);
            }
        }

        if (more) store_chunk(buf ^ 1);
        __syncthreads();
        buf ^= 1;
    }

#pragma unroll
    for (int i = 0; i < 2; ++i) {
        const long row = row0 + m0 + (i << 4) + (lane >> 2);
#pragma unroll
        for (int j = 0; j < 8; ++j) {
            const int col = col0 + n0 + (j << 3) + ((lane & 3) << 1);
            if (col < N) {
                const float2 bv = *(const float2*)(bias + col);
                float v0 = c[i][j][0] + bv.x;
                float v1 = c[i][j][1] + bv.y;
                float v2 = c[i][j][2] + bv.x;
                float v3 = c[i][j][3] + bv.y;
                if (relu) {
                    v0 = fmaxf(v0, 0.f); v1 = fmaxf(v1, 0.f);
                    v2 = fmaxf(v2, 0.f); v3 = fmaxf(v3, 0.f);
                }
                float2 o0 = {v0, v1}, o1 = {v2, v3};
                *(float2*)(C + row * (long)ldc + col)       = o0;
                *(float2*)(C + (row + 8) * (long)ldc + col) = o1;
            }
        }
    }
}

// ==== fully fused residual MLP: res1+res2+res3, r1 and r2 never hit DRAM ====
// Smem regions (u32): R1 @0 (8*A_BUF1=36864), B @36864 (2*B_BUF1=8704),
// H @45568 (2*A_BUF1=9216; HY staging, later W3). Total 54784 u32 = 219136 B.
#define RF_R1 0
#define RF_B  36864
#define RF_H  45568
#define RF_SMEM_B ((54784) * 4)

__global__ __launch_bounds__(256, 1) void res_fused(
    const float* __restrict__ HY,
    const float* __restrict__ W1, const float* __restrict__ b1,
    const float* __restrict__ W2, const float* __restrict__ b2,
    const float* __restrict__ W3,
    float* __restrict__ partial)      // [2][rows][8]
{
    extern __shared__ uint32_t smem[];
    const long row0 = (long)blockIdx.y << 7;
    const int tid = threadIdx.x, lane = tid & 31, wid = tid >> 5;
    const int m0 = (wid & 3) << 5;
    const int n0 = (wid >> 2) << 6;
    const int arow = tid >> 1, ak16 = (tid & 1) << 4;
    const int bn = lane << 2;

    // ---- stage HY into fragment layout (2 k-chunks, K=40 zero-padded) ----
    {
        const float* Hp = HY + (row0 + arow) * 40;
#pragma unroll
        for (int s2 = 0; s2 < 2; ++s2) {
            uint32_t* ab = smem + RF_H + s2 * A_BUF1 + arow * AST1 + ak16;
#pragma unroll
            for (int s = 0; s < 4; ++s) {
                const int k = s2 * 32 + ak16 + (s << 2);
                float4 a = make_float4(0.f, 0.f, 0.f, 0.f);
                if (k < 40) a = *(const float4*)(Hp + k);
                uint4 t;
                t.x = f2tf32(a.x); t.y = f2tf32(a.y);
                t.z = f2tf32(a.z); t.w = f2tf32(a.w);
                *(uint4*)(ab + (s << 2)) = t;
            }
        }
    }

    // ---- phase 1: r1 = relu(HY @ W1 + b1) -> resident smem (tf32 fragments) ----
#pragma unroll
    for (int cp = 0; cp < 2; ++cp) {
        const int cb = cp << 7;
        {
            const float* Wp = W1 + cb + bn;
#pragma unroll
            for (int s2 = 0; s2 < 2; ++s2) {
                uint32_t* bb = smem + RF_B + s2 * B_BUF1 + wid * BST + bn;
#pragma unroll
                for (int s = 0; s < 4; ++s) {
                    const int kb = s2 * 32 + wid + (s << 3);
                    float4 b = make_float4(0.f, 0.f, 0.f, 0.f);
                    if (kb < 40) b = *(const float4*)(Wp + (long)kb * 256);
                    uint32_t* bq = bb + (s << 3) * BST;
                    bq[0] = f2tf32(b.x); bq[1] = f2tf32(b.y);
                    bq[2] = f2tf32(b.z); bq[3] = f2tf32(b.w);
                }
            }
        }
        __syncthreads();

        float c[2][8][4] = {};
#pragma unroll
        for (int ch = 0; ch < 2; ++ch) {
            const uint32_t* asb = smem + RF_H + ch * A_BUF1 + (m0 + (lane >> 2)) * AST1 + (lane & 3);
            const uint32_t* bsb = smem + RF_B + ch * B_BUF1 + (lane & 3) * BST + n0 + (lane >> 2);
#pragma unroll
            for (int kk = 0; kk < 4; ++kk) {
                uint32_t ah[2][4];
#pragma unroll
                for (int i = 0; i < 2; ++i) {
                    const uint32_t* p = asb + (i << 4) * AST1 + (kk << 3);
                    ah[i][0] = p[0];
                    ah[i][1] = p[8 * AST1];
                    ah[i][2] = p[4];
                    ah[i][3] = p[8 * AST1 + 4];
                }
#pragma unroll
                for (int j = 0; j < 8; ++j) {
                    const uint32_t* q = bsb + (kk << 3) * BST + (j << 3);
                    uint32_t bh[2];
                    bh[0] = q[0];
                    bh[1] = q[4 * BST];
#pragma unroll
                    for (int i = 0; i < 2; ++i)
                        mma8(c[i][j], ah[i], bh);
                }
            }
        }
        __syncthreads();   // all mma done before B overwritten next pass

        // write r1 tf32 fragments into resident R1 region
#pragma unroll
        for (int i = 0; i < 2; ++i) {
            const int rl = m0 + (i << 4) + (lane >> 2);
#pragma unroll
            for (int j = 0; j < 8; ++j) {
                const int col = cb + n0 + (j << 3) + ((lane & 3) << 1);
                const float2 bv = *(const float2*)(b1 + col);
                const float v0 = fmaxf(c[i][j][0] + bv.x, 0.f);
                const float v1 = fmaxf(c[i][j][1] + bv.y, 0.f);
                const float v2 = fmaxf(c[i][j][2] + bv.x, 0.f);
                const float v3 = fmaxf(c[i][j][3] + bv.y, 0.f);
                uint32_t* base = smem + RF_R1 + (col >> 5) * A_BUF1 + (col & 31);
                uint32_t* d0 = base + rl * AST1;
                uint32_t* d1 = base + (rl + 8) * AST1;
                d0[0] = f2tf32(v0); d0[1] = f2tf32(v1);
                d1[0] = f2tf32(v2); d1[1] = f2tf32(v3);
            }
        }
    }
    __syncthreads();

    // stage W3 (overwrites HY region)
    float* ws = (float*)(smem + RF_H);
#pragma unroll
    for (int q = 0; q < 8; ++q) ws[tid + q * 256] = W3[tid + q * 256];
    __syncthreads();

    // ---- phase 2: r2 = relu(r1 @ W2 + b2), projected through W3 ----
    float pacc[2][2][8] = {};
#pragma unroll
    for (int cp = 0; cp < 2; ++cp) {
        const int cb = cp << 7;
        const float* Wp = W2 + cb + bn;
        float4 b4[4];
        auto loadB = [&](int ch) {
#pragma unroll
            for (int s = 0; s < 4; ++s)
                b4[s] = *(const float4*)(Wp + (long)(ch * 32 + wid + (s << 3)) * 256);
        };
        auto storeB = [&](int nb) {
            uint32_t* bb = smem + RF_B + nb * B_BUF1 + wid * BST + bn;
#pragma unroll
            for (int s = 0; s < 4; ++s) {
                uint32_t* b = bb + (s << 3) * BST;
                b[0] = f2tf32(b4[s].x); b[1] = f2tf32(b4[s].y);
                b[2] = f2tf32(b4[s].z); b[3] = f2tf32(b4[s].w);
            }
        };
        loadB(0); storeB(0);
        __syncthreads();

        float c[2][8][4] = {};
        int buf = 0;
        for (int ch = 0; ch < 8; ++ch) {
            const bool more = (ch + 1) < 8;
            if (more) loadB(ch + 1);
            const uint32_t* asb = smem + RF_R1 + ch * A_BUF1 + (m0 + (lane >> 2)) * AST1 + (lane & 3);
            const uint32_t* bsb = smem + RF_B + buf * B_BUF1 + (lane & 3) * BST + n0 + (lane >> 2);
#pragma unroll
            for (int kk = 0; kk < 4; ++kk) {
                uint32_t ah[2][4];
#pragma unroll
                for (int i = 0; i < 2; ++i) {
                    const uint32_t* p = asb + (i << 4) * AST1 + (kk << 3);
                    ah[i][0] = p[0];
                    ah[i][1] = p[8 * AST1];
                    ah[i][2] = p[4];
                    ah[i][3] = p[8 * AST1 + 4];
                }
#pragma unroll
                for (int j = 0; j < 8; ++j) {
                    const uint32_t* q = bsb + (kk << 3) * BST + (j << 3);
                    uint32_t bh[2];
                    bh[0] = q[0];
                    bh[1] = q[4 * BST];
#pragma unroll
                    for (int i = 0; i < 2; ++i)
                        mma8(c[i][j], ah[i], bh);
                }
            }
            if (more) storeB(buf ^ 1);
            __syncthreads();
            buf ^= 1;
        }

        // accumulate W3 projection across both column passes
#pragma unroll
        for (int i = 0; i < 2; ++i)
#pragma unroll
            for (int j = 0; j < 8; ++j) {
                const int col = cb + n0 + (j << 3) + ((lane & 3) << 1);
                const float2 bv = *(const float2*)(b2 + col);
                const float v0 = fmaxf(c[i][j][0] + bv.x, 0.f);
                const float v1 = fmaxf(c[i][j][1] + bv.y, 0.f);
                const float v2 = fmaxf(c[i][j][2] + bv.x, 0.f);
                const float v3 = fmaxf(c[i][j][3] + bv.y, 0.f);
                const float* w0 = ws + col * 8;
                const float* w1 = w0 + 8;
#pragma unroll
                for (int t = 0; t < 8; ++t) {
                    pacc[i][0][t] = fmaf(v0, w0[t], fmaf(v1, w1[t], pacc[i][0][t]));
                    pacc[i][1][t] = fmaf(v2, w0[t], fmaf(v3, w1[t], pacc[i][1][t]));
                }
            }
    }

    // quarter-warp reduce + store per-slot partials (slot = wid>>2, 2 slots)
    const int slot = wid >> 2;
    float* pbase = partial + (long)slot * ((long)Bsz * FcN * 8);
#pragma unroll
    for (int i = 0; i < 2; ++i) {
#pragma unroll
        for (int t = 0; t < 8; ++t) {
            pacc[i][0][t] += __shfl_xor_sync(0xffffffffu, pacc[i][0][t], 1);
            pacc[i][0][t] += __shfl_xor_sync(0xffffffffu, pacc[i][0][t], 2);
            pacc[i][1][t] += __shfl_xor_sync(0xffffffffu, pacc[i][1][t], 1);
            pacc[i][1][t] += __shfl_xor_sync(0xffffffffu, pacc[i][1][t], 2);
        }
        if ((lane & 3) == 0) {
            const long rowA = row0 + m0 + (i << 4) + (lane >> 2);
            float* pA = pbase + rowA * 8;
            float* pB = pA + 64;
#pragma unroll
            for (int t = 0; t < 4; ++t) {
                float2 va = {pacc[i][0][2 * t], pacc[i][0][2 * t + 1]};
                float2 vb = {pacc[i][1][2 * t], pacc[i][1][2 * t + 1]};
                *(float2*)(pA + 2 * t) = va;
                *(float2*)(pB + 2 * t) = vb;
            }
        }
    }
}

// finalize: xequ = xeq1 + b3 + sum of 2 partials
__global__ void res3_fin(const float* __restrict__ partial, const float* __restrict__ b3,
                         const float* __restrict__ xeq1, float* __restrict__ xequ)
{
    const long i = (long)blockIdx.x * blockDim.x + threadIdx.x;
    const long R8 = (long)Bsz * FcN * 8;
    if (i >= R8) return;
    const int t = (int)(i & 7);
    xequ[i] = xeq1[i] + b3[t] + partial[i] + partial[R8 + i];
}

__global__ void stats_kernel(const float* __restrict__ h, int C, float* __restrict__ part) {
    const int v = blockIdx.x, s = blockIdx.y, c = threadIdx.x;
    const long stride = (long)Vn * C;
    const float* p = h + ((long)(s * 256) * Vn + v) * C + c;
    float sum = 0.f, sq = 0.f;
#pragma unroll 4
    for (int i = 0; i < 256; ++i) {
        float val = p[(long)i * stride];
        sum += val;
        sq = fmaf(val, val, sq);
    }
    const long o = (((long)s * Vn + v) * C + c) * 2;
    part[o] = sum; part[o + 1] = sq;
}

__global__ void fuse_kernel(const float* __restrict__ W, const float* __restrict__ bias,
                            const float* __restrict__ g, const float* __restrict__ be,
                            int Cin, int Nout,
                            float* __restrict__ Wp, float* __restrict__ bp)
{
    const int v = blockIdx.x, tid = threadIdx.x;
    __shared__ float sa[512], sc[512];
    for (int n = tid; n < Cin; n += blockDim.x) {
        float sum = 0.f, sq = 0.f;
        for (int s = 0; s < 32; ++s) {
            const long o = (((long)s * Vn + v) * Cin + n) * 2;
            sum += g_part[o]; sq += g_part[o + 1];
        }
        const float mu  = sum * (1.f / Bsz);
        const float var = sq * (1.f / Bsz) - mu * mu;
        const float rs  = rsqrtf(var + BNEPS);
        const float a   = g[v * Cin + n] * rs;
        sa[n] = a;
        sc[n] = be[v * Cin + n] - mu * a;
    }
    __syncthreads();
    const int slice = (Nout + gridDim.y - 1) / gridDim.y;
    const int j0 = blockIdx.y * slice;
    const int j1 = min(j0 + slice, Nout);
    const float* wv = W + (long)v * Cin * Nout;
    float* wpv = Wp + (long)v * Cin * Nout;
    for (int j = j0 + tid; j < j1; j += blockDim.x) {
        float acc = bias[v * Nout + j];
        for (int n = 0; n < Cin; ++n) {
            const float w = wv[(long)n * Nout + j];
            wpv[(long)n * Nout + j] = sa[n] * w;
            acc = fmaf(sc[n], w, acc);
        }
        bp[v * Nout + j] = acc;
    }
}

__global__ void combine_kernel(float* __restrict__ enc_sig) {
    const int b = blockIdx.x;
    const int d = threadIdx.x;
    const int warp = d >> 5, lane = d & 31;
    __shared__ float partial[16][8];
    __shared__ float alpha[8];

    float ev[8];
    float s[8];
#pragma unroll
    for (int v = 0; v < 8; ++v) {
        ev[v] = g_e[((long)b * Vn + v) * 512 + d];
        s[v] = ev[v] * ev[v];
    }
#pragma unroll
    for (int v = 0; v < 8; ++v)
#pragma unroll
        for (int o = 16; o; o >>= 1) s[v] += __shfl_xor_sync(0xffffffffu, s[v], o);
    if (lane == 0)
#pragma unroll
        for (int v = 0; v < 8; ++v) partial[warp][v] = s[v];
    __syncthreads();
    if (warp < 8 && lane < 16) {
        float t = partial[lane][warp];
#pragma unroll
        for (int o = 8; o; o >>= 1) t += __shfl_xor_sync(0xffffu, t, o);
        if (lane == 0) alpha[warp] = 8.f * rsqrtf(t);
    }
    __syncthreads();
    float acc = 0.f;
#pragma unroll
    for (int v = 0; v < 8; ++v) acc = fmaf(alpha[v], ev[v], acc);
    enc_sig[(long)b * 512 + d] = acc * 0.70710678118654752f;
}

struct C2 { float x, y; };
__device__ __forceinline__ C2 cmul(C2 a, C2 b) { return {a.x*b.x - a.y*b.y, a.x*b.y + a.y*b.x}; }
__device__ __forceinline__ C2 cmulc(C2 a, C2 b) { return {a.x*b.x + a.y*b.y, a.x*b.y - a.y*b.x}; }

__global__ void channel_kernel(const float* __restrict__ Hri, const float* __restrict__ noiseri,
                               const float* __restrict__ encsig,
                               float* __restrict__ yout, float* __restrict__ xeq1out)
{
    const int b = blockIdx.x;
    const int f = threadIdx.x;
    __shared__ C2 H[4][4];
    __shared__ C2 Ainv[4][4];
    const float is2 = 0.70710678118654752f;

    if (f < 16) {
        const int r = f >> 2, t = f & 3;
        const long o = (((long)(b * 4 + r)) * 4 + t) * 2;
        H[r][t] = {Hri[o] * is2, Hri[o + 1] * is2};
    }
    __syncthreads();

    const float lam = g_consts[0];
    const float nsc = g_consts[1];

    if (f == 0) {
        C2 Am[4][8];
        for (int i = 0; i < 4; ++i) {
            for (int j = 0; j < 4; ++j) {
                C2 a = {0.f, 0.f};
                for (int r = 0; r < 4; ++r) {
                    C2 p = cmulc(H[r][i], H[r][j]);
                    a.x += p.x; a.y += p.y;
                }
                if (i == j) a.x += lam;
                Am[i][j] = a;
                Am[i][4 + j] = (i == j) ? C2{1.f, 0.f} : C2{0.f, 0.f};
            }
        }
        for (int p = 0; p < 4; ++p) {
            C2 dg = Am[p][p];
            const float inv = 1.f / (dg.x * dg.x + dg.y * dg.y);
            const C2 dinv = {dg.x * inv, -dg.y * inv};
            for (int j = 0; j < 8; ++j) Am[p][j] = cmul(Am[p][j], dinv);
            for (int r = 0; r < 4; ++r) {
                if (r == p) continue;
                const C2 fac = Am[r][p];
                for (int j = 0; j < 8; ++j) {
                    const C2 q = cmul(fac, Am[p][j]);
                    Am[r][j].x -= q.x; Am[r][j].y -= q.y;
                }
            }
        }
        for (int i = 0; i < 4; ++i)
            for (int j = 0; j < 4; ++j)
                Ainv[i][j] = Am[i][4 + j];
    }
    __syncthreads();

    C2 s[4];
#pragma unroll
    for (int t = 0; t < 4; ++t) {
        const long o = ((long)b * 512) + ((long)(f * 4 + t)) * 2;
        s[t] = {encsig[o], encsig[o + 1]};
    }
    const long nbase = ((long)(b * 64 + f)) * 8;
    C2 yv[4];
#pragma unroll
    for (int r = 0; r < 4; ++r) {
        C2 a = {0.f, 0.f};
#pragma unroll
        for (int t = 0; t < 4; ++t) { C2 p = cmul(H[r][t], s[t]); a.x += p.x; a.y += p.y; }
        a.x += nsc * noiseri[nbase + r * 2]     * is2;
        a.y += nsc * noiseri[nbase + r * 2 + 1] * is2;
        yv[r] = a;
        yout[nbase + r * 2]     = a.x;
        yout[nbase + r * 2 + 1] = a.y;
    }
    C2 hy[4];
#pragma unroll
    for (int t = 0; t < 4; ++t) {
        C2 a = {0.f, 0.f};
#pragma unroll
        for (int r = 0; r < 4; ++r) { C2 p = cmulc(H[r][t], yv[r]); a.x += p.x; a.y += p.y; }
        hy[t] = a;
    }
#pragma unroll
    for (int t = 0; t < 4; ++t) {
        C2 a = {0.f, 0.f};
#pragma unroll
        for (int k = 0; k < 4; ++k) { C2 p = cmul(Ainv[t][k], hy[k]); a.x += p.x; a.y += p.y; }
        xeq1out[nbase + t * 2]     = a.x;
        xeq1out[nbase + t * 2 + 1] = a.y;
    }
    float* hyp = &g_HY[((long)(b * 64 + f)) * 40];
#pragma unroll
    for (int r = 0; r < 4; ++r)
#pragma unroll
        for (int t = 0; t < 4; ++t) {
            hyp[(r * 4 + t) * 2]     = H[r][t].x;
            hyp[(r * 4 + t) * 2 + 1] = H[r][t].y;
        }
#pragma unroll
    for (int r = 0; r < 4; ++r) {
        hyp[32 + r * 2]     = yv[r].x;
        hyp[32 + r * 2 + 1] = yv[r].y;
    }
}

__global__ void emit_kernel(const float* __restrict__ src, float* __restrict__ out,
                            long off, long n, long out_size, int mode) {
    const long i = (long)blockIdx.x * blockDim.x + threadIdx.x;
    if (i >= n) return;
    const long o = off + i;
    if (o >= out_size) return;
    out[o] = (mode == 0) ? src[i] : src[2 * i];
}

extern "C" void kernel_launch(void* const* d_in, const int* in_sizes, int n_in,
                              void* d_out, int out_size) {
    const float* x        = (const float*)d_in[0];
    const int*   snr      = (const int*)  d_in[1];
    const float* H_ri     = (const float*)d_in[2];
    const float* noise_ri = (const float*)d_in[3];
    const float* enc_W1 = (const float*)d_in[4];  const float* enc_b1 = (const float*)d_in[5];
    const float* enc_g1 = (const float*)d_in[6];  const float* enc_be1= (const float*)d_in[7];
    const float* enc_W2 = (const float*)d_in[8];  const float* enc_b2 = (const float*)d_in[9];
    const float* enc_g2 = (const float*)d_in[10]; const float* enc_be2= (const float*)d_in[11];
    const float* enc_W3 = (const float*)d_in[12]; const float* enc_b3 = (const float*)d_in[13];
    const float* dec_W1 = (const float*)d_in[14]; const float* dec_b1 = (const float*)d_in[15];
    const float* dec_g1 = (const float*)d_in[16]; const float* dec_be1= (const float*)d_in[17];
    const float* dec_W2 = (const float*)d_in[18]; const float* dec_b2 = (const float*)d_in[19];
    const float* dec_g2 = (const float*)d_in[20]; const float* dec_be2= (const float*)d_in[21];
    const float* dec_W3 = (const float*)d_in[22]; const float* dec_b3 = (const float*)d_in[23];
    const float* res_W1 = (const float*)d_in[24]; const float* res_b1 = (const float*)d_in[25];
    const float* res_W2 = (const float*)d_in[26]; const float* res_b2 = (const float*)d_in[27];
    const float* res_W3 = (const float*)d_in[28]; const float* res_b3 = (const float*)d_in[29];

    float *h1, *h2, *e, *hd1, *hd2, *HY, *r3p;
    float *Ps, *ys, *xequs, *xeq1s, *sigs;
    float *W2e, *b2e, *W3e, *b3e, *W2d, *b2d, *W3d, *b3d, *part;
    cudaGetSymbolAddress((void**)&h1,  g_h1);
    cudaGetSymbolAddress((void**)&h2,  g_h2);
    cudaGetSymbolAddress((void**)&e,   g_e);
    cudaGetSymbolAddress((void**)&hd1, g_hd1);
    cudaGetSymbolAddress((void**)&hd2, g_hd2);
    cudaGetSymbolAddress((void**)&HY,  g_HY);
    cudaGetSymbolAddress((void**)&r3p, g_r3p);
    cudaGetSymbolAddress((void**)&Ps,    g_P);
    cudaGetSymbolAddress((void**)&ys,    g_y);
    cudaGetSymbolAddress((void**)&xequs, g_xequ);
    cudaGetSymbolAddress((void**)&xeq1s, g_xeq1);
    cudaGetSymbolAddress((void**)&sigs,  g_sig);
    cudaGetSymbolAddress((void**)&W2e, g_W2e); cudaGetSymbolAddress((void**)&b2e, g_b2e);
    cudaGetSymbolAddress((void**)&W3e, g_W3e); cudaGetSymbolAddress((void**)&b3e, g_b3e);
    cudaGetSymbolAddress((void**)&W2d, g_W2d); cudaGetSymbolAddress((void**)&b2d, g_b2d);
    cudaGetSymbolAddress((void**)&W3d, g_W3d); cudaGetSymbolAddress((void**)&b3d, g_b3d);
    cudaGetSymbolAddress((void**)&part, g_part);

    float* out = (float*)d_out;
    const long LP = 2097152, LY = 4194304, LX = 4194304, LS = 4194304;
    const long FULL = LP + LY + LX + LX + LS;
    const bool direct = ((long)out_size == FULL);
    float* P    = direct ? out                     : Ps;
    float* y    = direct ? out + LP                : ys;
    float* xequ = direct ? out + LP + LY           : xequs;
    float* xeq1 = direct ? out + LP + LY + LX      : xeq1s;
    float* sig  = direct ? out + LP + LY + LX + LX : sigs;

    const int SMB3 = (2 * A_BUF3 + 2 * B_BUF3) * 4;
    const int SMB1 = (2 * A_BUF1 + 2 * B_BUF1) * 4;
    cudaFuncSetAttribute(mma_gemm3, cudaFuncAttributeMaxDynamicSharedMemorySize, SMB3);
    cudaFuncSetAttribute(mma_gemm1, cudaFuncAttributeMaxDynamicSharedMemorySize, SMB1);
    cudaFuncSetAttribute(res_fused, cudaFuncAttributeMaxDynamicSharedMemorySize, RF_SMEM_B);

    prep_kernel<<<1, 1>>>(snr);

    // ---- encoder: enc1/enc2 3x, enc3 1x ----
    mma_gemm3<<<dim3(1, 64, 8), 512, SMB3>>>(x, 256, 32, enc_W1, 32 * 128, enc_b1, 128,
                                             h1, 1024, 128, 32, 128, 1);
    stats_kernel<<<dim3(8, 32), 128>>>(h1, 128, part);
    fuse_kernel<<<dim3(8, 8), 256>>>(enc_W2, enc_b2, enc_g1, enc_be1, 128, 128, W2e, b2e);
    mma_gemm3<<<dim3(1, 64, 8), 512, SMB3>>>(h1, 1024, 128, W2e, 128 * 128, b2e, 128,
                                             h2, 1024, 128, 128, 128, 1);
    stats_kernel<<<dim3(8, 32), 128>>>(h2, 128, part);
    fuse_kernel<<<dim3(8, 8), 256>>>(enc_W3, enc_b3, enc_g2, enc_be2, 128, 512, W3e, b3e);
    mma_gemm1<<<dim3(4, 64, 8), 256, SMB1>>>(h2, 1024, 128, W3e, 128 * 512, b3e, 512,
                                             e, 4096, 512, 128, 512, 0);
    combine_kernel<<<8192, 512>>>(sig);

    // ---- channel + MMSE ----
    channel_kernel<<<8192, 64>>>(H_ri, noise_ri, sig, y, xeq1);

    // ---- residual MLP: fully fused ----
    res_fused<<<dim3(1, 4096, 1), 256, RF_SMEM_B>>>(HY, res_W1, res_b1, res_W2, res_b2,
                                                    res_W3, r3p);
    res3_fin<<<16384, 256>>>(r3p, res_b3, xeq1, xequ);

    // ---- decoder: dec1 3x, dec2 1x, dec3 1x ----
    mma_gemm3<<<dim3(2, 64, 8), 512, SMB3>>>(xequ, 512, 0, dec_W1, 512 * 256, dec_b1, 256,
                                             hd1, 2048, 256, 512, 256, 1);
    stats_kernel<<<dim3(8, 32), 256>>>(hd1, 256, part);
    fuse_kernel<<<dim3(8, 8), 256>>>(dec_W2, dec_b2, dec_g1, dec_be1, 256, 256, W2d, b2d);
    mma_gemm1<<<dim3(2, 64, 8), 256, SMB1>>>(hd1, 2048, 256, W2d, 256 * 256, b2d, 256,
                                             hd2, 2048, 256, 256, 256, 1);
    stats_kernel<<<dim3(8, 32), 256>>>(hd2, 256, part);
    fuse_kernel<<<dim3(8, 8), 256>>>(dec_W3, dec_b3, dec_g2, dec_be2, 256, 32, W3d, b3d);
    mma_gemm1<<<dim3(1, 64, 8), 256, SMB1>>>(hd2, 2048, 256, W3d, 256 * 32, b3d, 32,
                                             P, 256, 32, 256, 32, 0);

    // ---- fallback emission only if layout differs ----
    if (!direct) {
        const long osz = (long)out_size;
        auto emit = [&](const float* src, long off, long n, int mode) {
            if (off >= osz || n <= 0) return;
            long grid = (n + 255) / 256;
            emit_kernel<<<(unsigned)grid, 256>>>(src, out, off, n, osz, mode);
        };
        if (osz == LP + LY/2 + LX + LX + LS) {
            long off = 0;
            emit(P,    off, LP,   0); off += LP;
            emit(y,    off, LY/2, 1); off += LY/2;
            emit(xequ, off, LX,   0); off += LX;
            emit(xeq1, off, LX,   0); off += LX;
            emit(sig,  off, LS,   0);
        } else {
            long off = 0;
            emit(P,    off, LP, 0); off += LP;
            emit(y,    off, LY, 0); off += LY;
            emit(xequ, off, LX, 0); off += LX;
            emit(xeq1, off, LX, 0); off += LX;
            emit(sig,  off, LS, 0);
        }
    }
}

// round 17
// speedup vs baseline: 1.9076x; 1.0171x over previous
#include <cuda_runtime.h>
#include <math.h>
#include <stdint.h>

#define Bsz 8192
#define Vn  8
#define FcN 64
#define BNEPS 1e-5f

__device__ float g_h1 [(size_t)Bsz*Vn*128];
__device__ float g_h2 [(size_t)Bsz*Vn*128];
__device__ float g_e  [(size_t)Bsz*Vn*512];
__device__ float g_hd1[(size_t)Bsz*Vn*256];
__device__ float g_hd2[(size_t)Bsz*Vn*256];
__device__ float g_HY [(size_t)Bsz*FcN*40];
__device__ float g_r3p[(size_t)4*Bsz*FcN*8];
__device__ float g_P   [(size_t)Bsz*Vn*32];
__device__ float g_y   [(size_t)Bsz*FcN*8];
__device__ float g_xequ[(size_t)Bsz*FcN*8];
__device__ float g_xeq1[(size_t)Bsz*FcN*8];
__device__ float g_sig [(size_t)Bsz*512];
__device__ float g_W2e[Vn*128*128]; __device__ float g_b2e[Vn*128];
__device__ float g_W3e[Vn*128*512]; __device__ float g_b3e[Vn*512];
__device__ float g_W2d[Vn*256*256]; __device__ float g_b2d[Vn*256];
__device__ float g_W3d[Vn*256*32];  __device__ float g_b3d[Vn*32];
__device__ float g_part[64*Vn*256*2];
__device__ float g_consts[4];

__device__ __forceinline__ uint32_t f2tf32(float f) {
    uint32_t r; asm("cvt.rna.tf32.f32 %0, %1;" : "=r"(r) : "f"(f)); return r;
}
__device__ __forceinline__ void split_tf32(float f, uint32_t& hi, uint32_t& lo) {
    hi = f2tf32(f);
    lo = f2tf32(f - __uint_as_float(hi));
}
__device__ __forceinline__ void mma8(float* c, const uint32_t* a, const uint32_t* b) {
    asm volatile(
        "mma.sync.aligned.m16n8k8.row.col.f32.tf32.tf32.f32 "
        "{%0,%1,%2,%3}, {%4,%5,%6,%7}, {%8,%9}, {%0,%1,%2,%3};"
        : "+f"(c[0]), "+f"(c[1]), "+f"(c[2]), "+f"(c[3])
        : "r"(a[0]), "r"(a[1]), "r"(a[2]), "r"(a[3]), "r"(b[0]), "r"(b[1]));
}

__global__ void prep_kernel(const int* __restrict__ snrp) {
    int iv = *snrp;
    float S;
    if (iv >= -1000 && iv <= 1000) S = (float)iv;
    else                            S = __int_as_float(iv);
    float snr = powf(10.f, -S * 0.1f);
    g_consts[0] = 4.f * snr;
    g_consts[1] = sqrtf(4.f * snr);
}

// ================= 3-term GEMM with optional fused BN-stats ==========
#define AST 20
#define BST 136
#define AS_SZ   (128 * AST)
#define BS_SZ   (16 * BST)
#define A_BUF3  (2 * AS_SZ)
#define B_BUF3  (2 * BS_SZ)
#define BS_BASE3 (2 * A_BUF3)

__global__ __launch_bounds__(512) void mma_gemm3(
    const float* __restrict__ A, int lda, long sAv,
    const float* __restrict__ W, long sWv,
    const float* __restrict__ bias, int sbv,
    float* __restrict__ C, int ldc, long sCv,
    int K, int N, int relu,
    float* __restrict__ statp, int statC)
{
    extern __shared__ uint32_t smem[];

    const int v = blockIdx.z;
    A    += (long)v * sAv;
    W    += (long)v * sWv;
    bias += (long)v * sbv;
    C    += (long)v * sCv;

    const long row0 = (long)blockIdx.y << 7;
    const int  col0 = blockIdx.x << 7;

    const int tid  = threadIdx.x;
    const int lane = tid & 31;
    const int wid  = tid >> 5;
    const int m0 = (wid & 3) << 5;
    const int n0 = (wid >> 2) << 5;

    const int ar  = tid >> 2;
    const int akq = (tid & 3) << 2;
    const int bk  = tid >> 5;
    const int bnq = (tid & 31) << 2;
    const bool bok = (col0 + bnq) < N;

    const float* Ap = A + (row0 + ar) * (long)lda;
    const float* Wp = W + (long)col0 + bnq;

    const int nch = (K + 15) >> 4;

    auto store_tiles = [&](int nb, float4 a4, float4 b4) {
        uint32_t* ash = smem + nb * A_BUF3 + ar * AST + akq;
        uint32_t* asl = ash + AS_SZ;
        split_tf32(a4.x, ash[0], asl[0]); split_tf32(a4.y, ash[1], asl[1]);
        split_tf32(a4.z, ash[2], asl[2]); split_tf32(a4.w, ash[3], asl[3]);
        uint32_t* bsh = smem + BS_BASE3 + nb * B_BUF3 + bk * BST + bnq;
        uint32_t* bsl = bsh + BS_SZ;
        split_tf32(b4.x, bsh[0], bsl[0]); split_tf32(b4.y, bsh[1], bsl[1]);
        split_tf32(b4.z, bsh[2], bsl[2]); split_tf32(b4.w, bsh[3], bsl[3]);
    };

    {
        float4 a4 = make_float4(0.f, 0.f, 0.f, 0.f);
        if (akq < K) a4 = *(const float4*)(Ap + akq);
        float4 b4 = make_float4(0.f, 0.f, 0.f, 0.f);
        if (bok && bk < K) b4 = *(const float4*)(Wp + (long)bk * N);
        store_tiles(0, a4, b4);
    }
    __syncthreads();

    float c[2][4][4] = {};
    int buf = 0;
    for (int ch = 0; ch < nch; ++ch) {
        float4 a4 = make_float4(0.f, 0.f, 0.f, 0.f);
        float4 b4 = make_float4(0.f, 0.f, 0.f, 0.f);
        const int nk0 = (ch + 1) << 4;
        const bool more = (ch + 1) < nch;
        if (more) {
            if (nk0 + akq < K) a4 = *(const float4*)(Ap + nk0 + akq);
            if (bok && (nk0 + bk) < K) b4 = *(const float4*)(Wp + (long)(nk0 + bk) * N);
        }

        const uint32_t* asb = smem + buf * A_BUF3 + (m0 + (lane >> 2)) * AST + (lane & 3);
        const uint32_t* bsb = smem + BS_BASE3 + buf * B_BUF3 + (lane & 3) * BST + n0 + (lane >> 2);
#pragma unroll
        for (int kk = 0; kk < 2; ++kk) {
            uint32_t ah[2][4], al[2][4];
#pragma unroll
            for (int i = 0; i < 2; ++i) {
                const uint32_t* p = asb + (i << 4) * AST + (kk << 3);
                ah[i][0] = p[0];
                ah[i][1] = p[8 * AST];
                ah[i][2] = p[4];
                ah[i][3] = p[8 * AST + 4];
                const uint32_t* pl = p + AS_SZ;
                al[i][0] = pl[0];
                al[i][1] = pl[8 * AST];
                al[i][2] = pl[4];
                al[i][3] = pl[8 * AST + 4];
            }
            uint32_t bh[4][2], bl[4][2];
#pragma unroll
            for (int j = 0; j < 4; ++j) {
                const uint32_t* q = bsb + (kk << 3) * BST + (j << 3);
                bh[j][0] = q[0];
                bh[j][1] = q[4 * BST];
                const uint32_t* ql = q + BS_SZ;
                bl[j][0] = ql[0];
                bl[j][1] = ql[4 * BST];
            }
#pragma unroll
            for (int i = 0; i < 2; ++i)
#pragma unroll
                for (int j = 0; j < 4; ++j) {
                    mma8(c[i][j], al[i], bh[j]);
                    mma8(c[i][j], ah[i], bl[j]);
                    mma8(c[i][j], ah[i], bh[j]);
                }
        }

        if (more) store_tiles(buf ^ 1, a4, b4);
        __syncthreads();
        buf ^= 1;
    }

    float tsum[4][2], tsq[4][2];
    if (statp) {
#pragma unroll
        for (int j = 0; j < 4; ++j) {
            tsum[j][0] = tsum[j][1] = 0.f;
            tsq[j][0] = tsq[j][1] = 0.f;
        }
    }
#pragma unroll
    for (int i = 0; i < 2; ++i) {
        const long row = row0 + m0 + (i << 4) + (lane >> 2);
#pragma unroll
        for (int j = 0; j < 4; ++j) {
            const int col = col0 + n0 + (j << 3) + ((lane & 3) << 1);
            if (col < N) {
                const float2 bv = *(const float2*)(bias + col);
                float v0 = c[i][j][0] + bv.x;
                float v1 = c[i][j][1] + bv.y;
                float v2 = c[i][j][2] + bv.x;
                float v3 = c[i][j][3] + bv.y;
                if (relu) {
                    v0 = fmaxf(v0, 0.f); v1 = fmaxf(v1, 0.f);
                    v2 = fmaxf(v2, 0.f); v3 = fmaxf(v3, 0.f);
                }
                if (statp) {
                    tsum[j][0] += v0 + v2;
                    tsq[j][0]  += v0 * v0 + v2 * v2;
                    tsum[j][1] += v1 + v3;
                    tsq[j][1]  += v1 * v1 + v3 * v3;
                }
                float2 o0 = {v0, v1}, o1 = {v2, v3};
                *(float2*)(C + row * (long)ldc + col)       = o0;
                *(float2*)(C + (row + 8) * (long)ldc + col) = o1;
            }
        }
    }
    if (statp) {
#pragma unroll
        for (int j = 0; j < 4; ++j)
#pragma unroll
            for (int p = 0; p < 2; ++p) {
                float s = tsum[j][p], q = tsq[j][p];
                s += __shfl_xor_sync(0xffffffffu, s, 4);
                q += __shfl_xor_sync(0xffffffffu, q, 4);
                s += __shfl_xor_sync(0xffffffffu, s, 8);
                q += __shfl_xor_sync(0xffffffffu, q, 8);
                s += __shfl_xor_sync(0xffffffffu, s, 16);
                q += __shfl_xor_sync(0xffffffffu, q, 16);
                tsum[j][p] = s; tsq[j][p] = q;
            }
        float* redS = (float*)smem;     // post-mainloop: smem safe to alias
        float* redQ = redS + 512;
        if (lane < 4) {
#pragma unroll
            for (int j = 0; j < 4; ++j)
#pragma unroll
                for (int p = 0; p < 2; ++p) {
                    const int lc = (j << 3) + (lane << 1) + p;
                    redS[wid * 32 + lc] = tsum[j][p];
                    redQ[wid * 32 + lc] = tsq[j][p];
                }
        }
        __syncthreads();
        if (tid < 128) {
            const int nw2 = tid >> 5, lc = tid & 31;
            float s = 0.f, q = 0.f;
#pragma unroll
            for (int mw = 0; mw < 4; ++mw) {
                s += redS[(nw2 * 4 + mw) * 32 + lc];
                q += redQ[(nw2 * 4 + mw) * 32 + lc];
            }
            const int col = col0 + (nw2 << 5) + lc;
            const long o = (((long)blockIdx.y * Vn + v) * statC + col) * 2;
            statp[o] = s; statp[o + 1] = q;
        }
    }
}

// ==== 1-term GEMM with optional fused BN-stats: 256 thr, warp 32x64 ====
#define AST1 36
#define A_BUF1 (128 * AST1)
#define B_BUF1 (32 * BST)
#define BS_BASE1 (2 * A_BUF1)

__global__ __launch_bounds__(256, 2) void mma_gemm1(
    const float* __restrict__ A, int lda, long sAv,
    const float* __restrict__ W, long sWv,
    const float* __restrict__ bias, int sbv,
    float* __restrict__ C, int ldc, long sCv,
    int K, int N, int relu,
    float* __restrict__ statp, int statC)
{
    extern __shared__ uint32_t smem[];

    const int v = blockIdx.z;
    A    += (long)v * sAv;
    W    += (long)v * sWv;
    bias += (long)v * sbv;
    C    += (long)v * sCv;

    const long row0 = (long)blockIdx.y << 7;
    const int  col0 = blockIdx.x << 7;

    const int tid  = threadIdx.x;
    const int lane = tid & 31;
    const int wid  = tid >> 5;
    const int m0 = (wid & 3) << 5;
    const int n0 = (wid >> 2) << 6;

    const int arow = tid >> 1;
    const int ak16 = (tid & 1) << 4;
    const int bn   = lane << 2;
    const bool bok = (col0 + bn) < N;

    const float* Ap = A + (row0 + arow) * (long)lda + ak16;
    const float* Wp = W + (long)col0 + bn;

    const int nch = (K + 31) >> 5;

    float4 a4[4], b4[4];

    auto load_chunk = [&](int k0) {
#pragma unroll
        for (int s = 0; s < 4; ++s) {
            const int ka = k0 + ak16 + (s << 2);
            a4[s] = make_float4(0.f, 0.f, 0.f, 0.f);
            if (ka < K) a4[s] = *(const float4*)(Ap + k0 + (s << 2));
            const int kb = k0 + wid + (s << 3);
            b4[s] = make_float4(0.f, 0.f, 0.f, 0.f);
            if (bok && kb < K) b4[s] = *(const float4*)(Wp + (long)kb * N);
        }
    };

    auto store_chunk = [&](int nb) {
        uint32_t* ab = smem + nb * A_BUF1 + arow * AST1 + ak16;
        uint32_t* bb = smem + BS_BASE1 + nb * B_BUF1 + wid * BST + bn;
#pragma unroll
        for (int s = 0; s < 4; ++s) {
            uint4 t;
            t.x = f2tf32(a4[s].x); t.y = f2tf32(a4[s].y);
            t.z = f2tf32(a4[s].z); t.w = f2tf32(a4[s].w);
            *(uint4*)(ab + (s << 2)) = t;
            uint32_t* b = bb + (s << 3) * BST;
            b[0] = f2tf32(b4[s].x); b[1] = f2tf32(b4[s].y);
            b[2] = f2tf32(b4[s].z); b[3] = f2tf32(b4[s].w);
        }
    };

    load_chunk(0);
    store_chunk(0);
    __syncthreads();

    float c[2][8][4] = {};
    int buf = 0;
    for (int ch = 0; ch < nch; ++ch) {
        const bool more = (ch + 1) < nch;
        if (more) load_chunk((ch + 1) << 5);

        const uint32_t* asb = smem + buf * A_BUF1 + (m0 + (lane >> 2)) * AST1 + (lane & 3);
        const uint32_t* bsb = smem + BS_BASE1 + buf * B_BUF1 + (lane & 3) * BST + n0 + (lane >> 2);
#pragma unroll
        for (int kk = 0; kk < 4; ++kk) {
            uint32_t ah[2][4];
#pragma unroll
            for (int i = 0; i < 2; ++i) {
                const uint32_t* p = asb + (i << 4) * AST1 + (kk << 3);
                ah[i][0] = p[0];
                ah[i][1] = p[8 * AST1];
                ah[i][2] = p[4];
                ah[i][3] = p[8 * AST1 + 4];
            }
#pragma unroll
            for (int j = 0; j < 8; ++j) {
                const uint32_t* q = bsb + (kk << 3) * BST + (j << 3);
                uint32_t bh[2];
                bh[0] = q[0];
                bh[1] = q[4 * BST];
#pragma unroll
                for (int i = 0; i < 2; ++i)
                    mma8(c[i][j], ah[i], bh);
            }
        }

        if (more) store_chunk(buf ^ 1);
        __syncthreads();
        buf ^= 1;
    }

    float tsum[8][2], tsq[8][2];
    if (statp) {
#pragma unroll
        for (int j = 0; j < 8; ++j) {
            tsum[j][0] = tsum[j][1] = 0.f;
            tsq[j][0] = tsq[j][1] = 0.f;
        }
    }
#pragma unroll
    for (int i = 0; i < 2; ++i) {
        const long row = row0 + m0 + (i << 4) + (lane >> 2);
#pragma unroll
        for (int j = 0; j < 8; ++j) {
            const int col = col0 + n0 + (j << 3) + ((lane & 3) << 1);
            if (col < N) {
                const float2 bv = *(const float2*)(bias + col);
                float v0 = c[i][j][0] + bv.x;
                float v1 = c[i][j][1] + bv.y;
                float v2 = c[i][j][2] + bv.x;
                float v3 = c[i][j][3] + bv.y;
                if (relu) {
                    v0 = fmaxf(v0, 0.f); v1 = fmaxf(v1, 0.f);
                    v2 = fmaxf(v2, 0.f); v3 = fmaxf(v3, 0.f);
                }
                if (statp) {
                    tsum[j][0] += v0 + v2;
                    tsq[j][0]  += v0 * v0 + v2 * v2;
                    tsum[j][1] += v1 + v3;
                    tsq[j][1]  += v1 * v1 + v3 * v3;
                }
                float2 o0 = {v0, v1}, o1 = {v2, v3};
                *(float2*)(C + row * (long)ldc + col)       = o0;
                *(float2*)(C + (row + 8) * (long)ldc + col) = o1;
            }
        }
    }
    if (statp) {
#pragma unroll
        for (int j = 0; j < 8; ++j)
#pragma unroll
            for (int p = 0; p < 2; ++p) {
                float s = tsum[j][p], q = tsq[j][p];
                s += __shfl_xor_sync(0xffffffffu, s, 4);
                q += __shfl_xor_sync(0xffffffffu, q, 4);
                s += __shfl_xor_sync(0xffffffffu, s, 8);
                q += __shfl_xor_sync(0xffffffffu, q, 8);
                s += __shfl_xor_sync(0xffffffffu, s, 16);
                q += __shfl_xor_sync(0xffffffffu, q, 16);
                tsum[j][p] = s; tsq[j][p] = q;
            }
        float* redS = (float*)smem;
        float* redQ = redS + 512;
        if (lane < 4) {
#pragma unroll
            for (int j = 0; j < 8; ++j)
#pragma unroll
                for (int p = 0; p < 2; ++p) {
                    const int lc = (j << 3) + (lane << 1) + p;
                    redS[wid * 64 + lc] = tsum[j][p];
                    redQ[wid * 64 + lc] = tsq[j][p];
                }
        }
        __syncthreads();
        if (tid < 128) {
            const int nw2 = tid >> 6, lc = tid & 63;
            float s = 0.f, q = 0.f;
#pragma unroll
            for (int mw = 0; mw < 4; ++mw) {
                s += redS[(nw2 * 4 + mw) * 64 + lc];
                q += redQ[(nw2 * 4 + mw) * 64 + lc];
            }
            const int col = col0 + (nw2 << 6) + lc;
            const long o = (((long)blockIdx.y * Vn + v) * statC + col) * 2;
            statp[o] = s; statp[o + 1] = q;
        }
    }
}

// ==== fully fused residual MLP (round-16 proven) ====
#define RF_R1 0
#define RF_B  36864
#define RF_H  45568
#define RF_SMEM_B ((54784) * 4)

__global__ __launch_bounds__(256, 1) void res_fused(
    const float* __restrict__ HY,
    const float* __restrict__ W1, const float* __restrict__ b1,
    const float* __restrict__ W2, const float* __restrict__ b2,
    const float* __restrict__ W3,
    float* __restrict__ partial)
{
    extern __shared__ uint32_t smem[];
    const long row0 = (long)blockIdx.y << 7;
    const int tid = threadIdx.x, lane = tid & 31, wid = tid >> 5;
    const int m0 = (wid & 3) << 5;
    const int n0 = (wid >> 2) << 6;
    const int arow = tid >> 1, ak16 = (tid & 1) << 4;
    const int bn = lane << 2;

    {
        const float* Hp = HY + (row0 + arow) * 40;
#pragma unroll
        for (int s2 = 0; s2 < 2; ++s2) {
            uint32_t* ab = smem + RF_H + s2 * A_BUF1 + arow * AST1 + ak16;
#pragma unroll
            for (int s = 0; s < 4; ++s) {
                const int k = s2 * 32 + ak16 + (s << 2);
                float4 a = make_float4(0.f, 0.f, 0.f, 0.f);
                if (k < 40) a = *(const float4*)(Hp + k);
                uint4 t;
                t.x = f2tf32(a.x); t.y = f2tf32(a.y);
                t.z = f2tf32(a.z); t.w = f2tf32(a.w);
                *(uint4*)(ab + (s << 2)) = t;
            }
        }
    }

#pragma unroll
    for (int cp = 0; cp < 2; ++cp) {
        const int cb = cp << 7;
        {
            const float* Wp = W1 + cb + bn;
#pragma unroll
            for (int s2 = 0; s2 < 2; ++s2) {
                uint32_t* bb = smem + RF_B + s2 * B_BUF1 + wid * BST + bn;
#pragma unroll
                for (int s = 0; s < 4; ++s) {
                    const int kb = s2 * 32 + wid + (s << 3);
                    float4 b = make_float4(0.f, 0.f, 0.f, 0.f);
                    if (kb < 40) b = *(const float4*)(Wp + (long)kb * 256);
                    uint32_t* bq = bb + (s << 3) * BST;
                    bq[0] = f2tf32(b.x); bq[1] = f2tf32(b.y);
                    bq[2] = f2tf32(b.z); bq[3] = f2tf32(b.w);
                }
            }
        }
        __syncthreads();

        float c[2][8][4] = {};
#pragma unroll
        for (int ch = 0; ch < 2; ++ch) {
            const uint32_t* asb = smem + RF_H + ch * A_BUF1 + (m0 + (lane >> 2)) * AST1 + (lane & 3);
            const uint32_t* bsb = smem + RF_B + ch * B_BUF1 + (lane & 3) * BST + n0 + (lane >> 2);
#pragma unroll
            for (int kk = 0; kk < 4; ++kk) {
                uint32_t ah[2][4];
#pragma unroll
                for (int i = 0; i < 2; ++i) {
                    const uint32_t* p = asb + (i << 4) * AST1 + (kk << 3);
                    ah[i][0] = p[0];
                    ah[i][1] = p[8 * AST1];
                    ah[i][2] = p[4];
                    ah[i][3] = p[8 * AST1 + 4];
                }
#pragma unroll
                for (int j = 0; j < 8; ++j) {
                    const uint32_t* q = bsb + (kk << 3) * BST + (j << 3);
                    uint32_t bh[2];
                    bh[0] = q[0];
                    bh[1] = q[4 * BST];
#pragma unroll
                    for (int i = 0; i < 2; ++i)
                        mma8(c[i][j], ah[i], bh);
                }
            }
        }
        __syncthreads();

#pragma unroll
        for (int i = 0; i < 2; ++i) {
            const int rl = m0 + (i << 4) + (lane >> 2);
#pragma unroll
            for (int j = 0; j < 8; ++j) {
                const int col = cb + n0 + (j << 3) + ((lane & 3) << 1);
                const float2 bv = *(const float2*)(b1 + col);
                const float v0 = fmaxf(c[i][j][0] + bv.x, 0.f);
                const float v1 = fmaxf(c[i][j][1] + bv.y, 0.f);
                const float v2 = fmaxf(c[i][j][2] + bv.x, 0.f);
                const float v3 = fmaxf(c[i][j][3] + bv.y, 0.f);
                uint32_t* base = smem + RF_R1 + (col >> 5) * A_BUF1 + (col & 31);
                uint32_t* d0 = base + rl * AST1;
                uint32_t* d1 = base + (rl + 8) * AST1;
                d0[0] = f2tf32(v0); d0[1] = f2tf32(v1);
                d1[0] = f2tf32(v2); d1[1] = f2tf32(v3);
            }
        }
    }
    __syncthreads();

    float* ws = (float*)(smem + RF_H);
#pragma unroll
    for (int q = 0; q < 8; ++q) ws[tid + q * 256] = W3[tid + q * 256];
    __syncthreads();

    float pacc[2][2][8] = {};
#pragma unroll
    for (int cp = 0; cp < 2; ++cp) {
        const int cb = cp << 7;
        const float* Wp = W2 + cb + bn;
        float4 b4[4];
        auto loadB = [&](int ch) {
#pragma unroll
            for (int s = 0; s < 4; ++s)
                b4[s] = *(const float4*)(Wp + (long)(ch * 32 + wid + (s << 3)) * 256);
        };
        auto storeB = [&](int nb) {
            uint32_t* bb = smem + RF_B + nb * B_BUF1 + wid * BST + bn;
#pragma unroll
            for (int s = 0; s < 4; ++s) {
                uint32_t* b = bb + (s << 3) * BST;
                b[0] = f2tf32(b4[s].x); b[1] = f2tf32(b4[s].y);
                b[2] = f2tf32(b4[s].z); b[3] = f2tf32(b4[s].w);
            }
        };
        loadB(0); storeB(0);
        __syncthreads();

        float c[2][8][4] = {};
        int buf = 0;
        for (int ch = 0; ch < 8; ++ch) {
            const bool more = (ch + 1) < 8;
            if (more) loadB(ch + 1);
            const uint32_t* asb = smem + RF_R1 + ch * A_BUF1 + (m0 + (lane >> 2)) * AST1 + (lane & 3);
            const uint32_t* bsb = smem + RF_B + buf * B_BUF1 + (lane & 3) * BST + n0 + (lane >> 2);
#pragma unroll
            for (int kk = 0; kk < 4; ++kk) {
                uint32_t ah[2][4];
#pragma unroll
                for (int i = 0; i < 2; ++i) {
                    const uint32_t* p = asb + (i << 4) * AST1 + (kk << 3);
                    ah[i][0] = p[0];
                    ah[i][1] = p[8 * AST1];
                    ah[i][2] = p[4];
                    ah[i][3] = p[8 * AST1 + 4];
                }
#pragma unroll
                for (int j = 0; j < 8; ++j) {
                    const uint32_t* q = bsb + (kk << 3) * BST + (j << 3);
                    uint32_t bh[2];
                    bh[0] = q[0];
                    bh[1] = q[4 * BST];
#pragma unroll
                    for (int i = 0; i < 2; ++i)
                        mma8(c[i][j], ah[i], bh);
                }
            }
            if (more) storeB(buf ^ 1);
            __syncthreads();
            buf ^= 1;
        }

#pragma unroll
        for (int i = 0; i < 2; ++i)
#pragma unroll
            for (int j = 0; j < 8; ++j) {
                const int col = cb + n0 + (j << 3) + ((lane & 3) << 1);
                const float2 bv = *(const float2*)(b2 + col);
                const float v0 = fmaxf(c[i][j][0] + bv.x, 0.f);
                const float v1 = fmaxf(c[i][j][1] + bv.y, 0.f);
                const float v2 = fmaxf(c[i][j][2] + bv.x, 0.f);
                const float v3 = fmaxf(c[i][j][3] + bv.y, 0.f);
                const float* w0 = ws + col * 8;
                const float* w1 = w0 + 8;
#pragma unroll
                for (int t = 0; t < 8; ++t) {
                    pacc[i][0][t] = fmaf(v0, w0[t], fmaf(v1, w1[t], pacc[i][0][t]));
                    pacc[i][1][t] = fmaf(v2, w0[t], fmaf(v3, w1[t], pacc[i][1][t]));
                }
            }
    }

    const int slot = wid >> 2;
    float* pbase = partial + (long)slot * ((long)Bsz * FcN * 8);
#pragma unroll
    for (int i = 0; i < 2; ++i) {
#pragma unroll
        for (int t = 0; t < 8; ++t) {
            pacc[i][0][t] += __shfl_xor_sync(0xffffffffu, pacc[i][0][t], 1);
            pacc[i][0][t] += __shfl_xor_sync(0xffffffffu, pacc[i][0][t], 2);
            pacc[i][1][t] += __shfl_xor_sync(0xffffffffu, pacc[i][1][t], 1);
            pacc[i][1][t] += __shfl_xor_sync(0xffffffffu, pacc[i][1][t], 2);
        }
        if ((lane & 3) == 0) {
            const long rowA = row0 + m0 + (i << 4) + (lane >> 2);
            float* pA = pbase + rowA * 8;
            float* pB = pA + 64;
#pragma unroll
            for (int t = 0; t < 4; ++t) {
                float2 va = {pacc[i][0][2 * t], pacc[i][0][2 * t + 1]};
                float2 vb = {pacc[i][1][2 * t], pacc[i][1][2 * t + 1]};
                *(float2*)(pA + 2 * t) = va;
                *(float2*)(pB + 2 * t) = vb;
            }
        }
    }
}

__global__ void res3_fin(const float* __restrict__ partial, const float* __restrict__ b3,
                         const float* __restrict__ xeq1, float* __restrict__ xequ)
{
    const long i = (long)blockIdx.x * blockDim.x + threadIdx.x;
    const long R8 = (long)Bsz * FcN * 8;
    if (i >= R8) return;
    const int t = (int)(i & 7);
    xequ[i] = xeq1[i] + b3[t] + partial[i] + partial[R8 + i];
}

// fold BN into next layer; 64 partial slots
__global__ void fuse_kernel(const float* __restrict__ W, const float* __restrict__ bias,
                            const float* __restrict__ g, const float* __restrict__ be,
                            int Cin, int Nout,
                            float* __restrict__ Wp, float* __restrict__ bp)
{
    const int v = blockIdx.x, tid = threadIdx.x;
    __shared__ float sa[512], sc[512];
    for (int n = tid; n < Cin; n += blockDim.x) {
        float sum = 0.f, sq = 0.f;
        for (int s = 0; s < 64; ++s) {
            const long o = (((long)s * Vn + v) * Cin + n) * 2;
            sum += g_part[o]; sq += g_part[o + 1];
        }
        const float mu  = sum * (1.f / Bsz);
        const float var = sq * (1.f / Bsz) - mu * mu;
        const float rs  = rsqrtf(var + BNEPS);
        const float a   = g[v * Cin + n] * rs;
        sa[n] = a;
        sc[n] = be[v * Cin + n] - mu * a;
    }
    __syncthreads();
    const int slice = (Nout + gridDim.y - 1) / gridDim.y;
    const int j0 = blockIdx.y * slice;
    const int j1 = min(j0 + slice, Nout);
    const float* wv = W + (long)v * Cin * Nout;
    float* wpv = Wp + (long)v * Cin * Nout;
    for (int j = j0 + tid; j < j1; j += blockDim.x) {
        float acc = bias[v * Nout + j];
        for (int n = 0; n < Cin; ++n) {
            const float w = wv[(long)n * Nout + j];
            wpv[(long)n * Nout + j] = sa[n] * w;
            acc = fmaf(sc[n], w, acc);
        }
        bp[v * Nout + j] = acc;
    }
}

__global__ void combine_kernel(float* __restrict__ enc_sig) {
    const int b = blockIdx.x;
    const int d = threadIdx.x;
    const int warp = d >> 5, lane = d & 31;
    __shared__ float partial[16][8];
    __shared__ float alpha[8];

    float ev[8];
    float s[8];
#pragma unroll
    for (int v = 0; v < 8; ++v) {
        ev[v] = g_e[((long)b * Vn + v) * 512 + d];
        s[v] = ev[v] * ev[v];
    }
#pragma unroll
    for (int v = 0; v < 8; ++v)
#pragma unroll
        for (int o = 16; o; o >>= 1) s[v] += __shfl_xor_sync(0xffffffffu, s[v], o);
    if (lane == 0)
#pragma unroll
        for (int v = 0; v < 8; ++v) partial[warp][v] = s[v];
    __syncthreads();
    if (warp < 8 && lane < 16) {
        float t = partial[lane][warp];
#pragma unroll
        for (int o = 8; o; o >>= 1) t += __shfl_xor_sync(0xffffu, t, o);
        if (lane == 0) alpha[warp] = 8.f * rsqrtf(t);
    }
    __syncthreads();
    float acc = 0.f;
#pragma unroll
    for (int v = 0; v < 8; ++v) acc = fmaf(alpha[v], ev[v], acc);
    enc_sig[(long)b * 512 + d] = acc * 0.70710678118654752f;
}

struct C2 { float x, y; };
__device__ __forceinline__ C2 cmul(C2 a, C2 b) { return {a.x*b.x - a.y*b.y, a.x*b.y + a.y*b.x}; }
__device__ __forceinline__ C2 cmulc(C2 a, C2 b) { return {a.x*b.x + a.y*b.y, a.x*b.y - a.y*b.x}; }

__global__ void channel_kernel(const float* __restrict__ Hri, const float* __restrict__ noiseri,
                               const float* __restrict__ encsig,
                               float* __restrict__ yout, float* __restrict__ xeq1out)
{
    const int b = blockIdx.x;
    const int f = threadIdx.x;
    __shared__ C2 H[4][4];
    __shared__ C2 Ainv[4][4];
    const float is2 = 0.70710678118654752f;

    if (f < 16) {
        const int r = f >> 2, t = f & 3;
        const long o = (((long)(b * 4 + r)) * 4 + t) * 2;
        H[r][t] = {Hri[o] * is2, Hri[o + 1] * is2};
    }
    __syncthreads();

    const float lam = g_consts[0];
    const float nsc = g_consts[1];

    if (f == 0) {
        C2 Am[4][8];
        for (int i = 0; i < 4; ++i) {
            for (int j = 0; j < 4; ++j) {
                C2 a = {0.f, 0.f};
                for (int r = 0; r < 4; ++r) {
                    C2 p = cmulc(H[r][i], H[r][j]);
                    a.x += p.x; a.y += p.y;
                }
                if (i == j) a.x += lam;
                Am[i][j] = a;
                Am[i][4 + j] = (i == j) ? C2{1.f, 0.f} : C2{0.f, 0.f};
            }
        }
        for (int p = 0; p < 4; ++p) {
            C2 dg = Am[p][p];
            const float inv = 1.f / (dg.x * dg.x + dg.y * dg.y);
            const C2 dinv = {dg.x * inv, -dg.y * inv};
            for (int j = 0; j < 8; ++j) Am[p][j] = cmul(Am[p][j], dinv);
            for (int r = 0; r < 4; ++r) {
                if (r == p) continue;
                const C2 fac = Am[r][p];
                for (int j = 0; j < 8; ++j) {
                    const C2 q = cmul(fac, Am[p][j]);
                    Am[r][j].x -= q.x; Am[r][j].y -= q.y;
                }
            }
        }
        for (int i = 0; i < 4; ++i)
            for (int j = 0; j < 4; ++j)
                Ainv[i][j] = Am[i][4 + j];
    }
    __syncthreads();

    C2 s[4];
#pragma unroll
    for (int t = 0; t < 4; ++t) {
        const long o = ((long)b * 512) + ((long)(f * 4 + t)) * 2;
        s[t] = {encsig[o], encsig[o + 1]};
    }
    const long nbase = ((long)(b * 64 + f)) * 8;
    C2 yv[4];
#pragma unroll
    for (int r = 0; r < 4; ++r) {
        C2 a = {0.f, 0.f};
#pragma unroll
        for (int t = 0; t < 4; ++t) { C2 p = cmul(H[r][t], s[t]); a.x += p.x; a.y += p.y; }
        a.x += nsc * noiseri[nbase + r * 2]     * is2;
        a.y += nsc * noiseri[nbase + r * 2 + 1] * is2;
        yv[r] = a;
        yout[nbase + r * 2]     = a.x;
        yout[nbase + r * 2 + 1] = a.y;
    }
    C2 hy[4];
#pragma unroll
    for (int t = 0; t < 4; ++t) {
        C2 a = {0.f, 0.f};
#pragma unroll
        for (int r = 0; r < 4; ++r) { C2 p = cmulc(H[r][t], yv[r]); a.x += p.x; a.y += p.y; }
        hy[t] = a;
    }
#pragma unroll
    for (int t = 0; t < 4; ++t) {
        C2 a = {0.f, 0.f};
#pragma unroll
        for (int k = 0; k < 4; ++k) { C2 p = cmul(Ainv[t][k], hy[k]); a.x += p.x; a.y += p.y; }
        xeq1out[nbase + t * 2]     = a.x;
        xeq1out[nbase + t * 2 + 1] = a.y;
    }
    float* hyp = &g_HY[((long)(b * 64 + f)) * 40];
#pragma unroll
    for (int r = 0; r < 4; ++r)
#pragma unroll
        for (int t = 0; t < 4; ++t) {
            hyp[(r * 4 + t) * 2]     = H[r][t].x;
            hyp[(r * 4 + t) * 2 + 1] = H[r][t].y;
        }
#pragma unroll
    for (int r = 0; r < 4; ++r) {
        hyp[32 + r * 2]     = yv[r].x;
        hyp[32 + r * 2 + 1] = yv[r].y;
    }
}

__global__ void emit_kernel(const float* __restrict__ src, float* __restrict__ out,
                            long off, long n, long out_size, int mode) {
    const long i = (long)blockIdx.x * blockDim.x + threadIdx.x;
    if (i >= n) return;
    const long o = off + i;
    if (o >= out_size) return;
    out[o] = (mode == 0) ? src[i] : src[2 * i];
}

extern "C" void kernel_launch(void* const* d_in, const int* in_sizes, int n_in,
                              void* d_out, int out_size) {
    const float* x        = (const float*)d_in[0];
    const int*   snr      = (const int*)  d_in[1];
    const float* H_ri     = (const float*)d_in[2];
    const float* noise_ri = (const float*)d_in[3];
    const float* enc_W1 = (const float*)d_in[4];  const float* enc_b1 = (const float*)d_in[5];
    const float* enc_g1 = (const float*)d_in[6];  const float* enc_be1= (const float*)d_in[7];
    const float* enc_W2 = (const float*)d_in[8];  const float* enc_b2 = (const float*)d_in[9];
    const float* enc_g2 = (const float*)d_in[10]; const float* enc_be2= (const float*)d_in[11];
    const float* enc_W3 = (const float*)d_in[12]; const float* enc_b3 = (const float*)d_in[13];
    const float* dec_W1 = (const float*)d_in[14]; const float* dec_b1 = (const float*)d_in[15];
    const float* dec_g1 = (const float*)d_in[16]; const float* dec_be1= (const float*)d_in[17];
    const float* dec_W2 = (const float*)d_in[18]; const float* dec_b2 = (const float*)d_in[19];
    const float* dec_g2 = (const float*)d_in[20]; const float* dec_be2= (const float*)d_in[21];
    const float* dec_W3 = (const float*)d_in[22]; const float* dec_b3 = (const float*)d_in[23];
    const float* res_W1 = (const float*)d_in[24]; const float* res_b1 = (const float*)d_in[25];
    const float* res_W2 = (const float*)d_in[26]; const float* res_b2 = (const float*)d_in[27];
    const float* res_W3 = (const float*)d_in[28]; const float* res_b3 = (const float*)d_in[29];

    float *h1, *h2, *e, *hd1, *hd2, *HY, *r3p;
    float *Ps, *ys, *xequs, *xeq1s, *sigs;
    float *W2e, *b2e, *W3e, *b3e, *W2d, *b2d, *W3d, *b3d, *part;
    cudaGetSymbolAddress((void**)&h1,  g_h1);
    cudaGetSymbolAddress((void**)&h2,  g_h2);
    cudaGetSymbolAddress((void**)&e,   g_e);
    cudaGetSymbolAddress((void**)&hd1, g_hd1);
    cudaGetSymbolAddress((void**)&hd2, g_hd2);
    cudaGetSymbolAddress((void**)&HY,  g_HY);
    cudaGetSymbolAddress((void**)&r3p, g_r3p);
    cudaGetSymbolAddress((void**)&Ps,    g_P);
    cudaGetSymbolAddress((void**)&ys,    g_y);
    cudaGetSymbolAddress((void**)&xequs, g_xequ);
    cudaGetSymbolAddress((void**)&xeq1s, g_xeq1);
    cudaGetSymbolAddress((void**)&sigs,  g_sig);
    cudaGetSymbolAddress((void**)&W2e, g_W2e); cudaGetSymbolAddress((void**)&b2e, g_b2e);
    cudaGetSymbolAddress((void**)&W3e, g_W3e); cudaGetSymbolAddress((void**)&b3e, g_b3e);
    cudaGetSymbolAddress((void**)&W2d, g_W2d); cudaGetSymbolAddress((void**)&b2d, g_b2d);
    cudaGetSymbolAddress((void**)&W3d, g_W3d); cudaGetSymbolAddress((void**)&b3d, g_b3d);
    cudaGetSymbolAddress((void**)&part, g_part);

    float* out = (float*)d_out;
    const long LP = 2097152, LY = 4194304, LX = 4194304, LS = 4194304;
    const long FULL = LP + LY + LX + LX + LS;
    const bool direct = ((long)out_size == FULL);
    float* P    = direct ? out                     : Ps;
    float* y    = direct ? out + LP                : ys;
    float* xequ = direct ? out + LP + LY           : xequs;
    float* xeq1 = direct ? out + LP + LY + LX      : xeq1s;
    float* sig  = direct ? out + LP + LY + LX + LX : sigs;

    const int SMB3 = (2 * A_BUF3 + 2 * B_BUF3) * 4;
    const int SMB1 = (2 * A_BUF1 + 2 * B_BUF1) * 4;
    cudaFuncSetAttribute(mma_gemm3, cudaFuncAttributeMaxDynamicSharedMemorySize, SMB3);
    cudaFuncSetAttribute(mma_gemm1, cudaFuncAttributeMaxDynamicSharedMemorySize, SMB1);
    cudaFuncSetAttribute(res_fused, cudaFuncAttributeMaxDynamicSharedMemorySize, RF_SMEM_B);

    prep_kernel<<<1, 1>>>(snr);

    // ---- encoder: enc1/enc2 3x (stats fused), enc3 1x ----
    mma_gemm3<<<dim3(1, 64, 8), 512, SMB3>>>(x, 256, 32, enc_W1, 32 * 128, enc_b1, 128,
                                             h1, 1024, 128, 32, 128, 1, part, 128);
    fuse_kernel<<<dim3(8, 8), 256>>>(enc_W2, enc_b2, enc_g1, enc_be1, 128, 128, W2e, b2e);
    mma_gemm3<<<dim3(1, 64, 8), 512, SMB3>>>(h1, 1024, 128, W2e, 128 * 128, b2e, 128,
                                             h2, 1024, 128, 128, 128, 1, part, 128);
    fuse_kernel<<<dim3(8, 8), 256>>>(enc_W3, enc_b3, enc_g2, enc_be2, 128, 512, W3e, b3e);
    mma_gemm1<<<dim3(4, 64, 8), 256, SMB1>>>(h2, 1024, 128, W3e, 128 * 512, b3e, 512,
                                             e, 4096, 512, 128, 512, 0, nullptr, 0);
    combine_kernel<<<8192, 512>>>(sig);

    // ---- channel + MMSE ----
    channel_kernel<<<8192, 64>>>(H_ri, noise_ri, sig, y, xeq1);

    // ---- residual MLP: fully fused ----
    res_fused<<<dim3(1, 4096, 1), 256, RF_SMEM_B>>>(HY, res_W1, res_b1, res_W2, res_b2,
                                                    res_W3, r3p);
    res3_fin<<<16384, 256>>>(r3p, res_b3, xeq1, xequ);

    // ---- decoder: dec1 3x (stats fused), dec2 1x (stats fused), dec3 1x ----
    mma_gemm3<<<dim3(2, 64, 8), 512, SMB3>>>(xequ, 512, 0, dec_W1, 512 * 256, dec_b1, 256,
                                             hd1, 2048, 256, 512, 256, 1, part, 256);
    fuse_kernel<<<dim3(8, 8), 256>>>(dec_W2, dec_b2, dec_g1, dec_be1, 256, 256, W2d, b2d);
    mma_gemm1<<<dim3(2, 64, 8), 256, SMB1>>>(hd1, 2048, 256, W2d, 256 * 256, b2d, 256,
                                             hd2, 2048, 256, 256, 256, 1, part, 256);
    fuse_kernel<<<dim3(8, 8), 256>>>(dec_W3, dec_b3, dec_g2, dec_be2, 256, 32, W3d, b3d);
    mma_gemm1<<<dim3(1, 64, 8), 256, SMB1>>>(hd2, 2048, 256, W3d, 256 * 32, b3d, 32,
                                             P, 256, 32, 256, 32, 0, nullptr, 0);

    // ---- fallback emission only if layout differs ----
    if (!direct) {
        const long osz = (long)out_size;
        auto emit = [&](const float* src, long off, long n, int mode) {
            if (off >= osz || n <= 0) return;
            long grid = (n + 255) / 256;
            emit_kernel<<<(unsigned)grid, 256>>>(src, out, off, n, osz, mode);
        };
        if (osz == LP + LY/2 + LX + LX + LS) {
            long off = 0;
            emit(P,    off, LP,   0); off += LP;
            emit(y,    off, LY/2, 1); off += LY/2;
            emit(xequ, off, LX,   0); off += LX;
            emit(xeq1, off, LX,   0); off += LX;
            emit(sig,  off, LS,   0);
        } else {
            long off = 0;
            emit(P,    off, LP, 0); off += LP;
            emit(y,    off, LY, 0); off += LY;
            emit(xequ, off, LX, 0); off += LX;
            emit(xeq1, off, LX, 0); off += LX;
            emit(sig,  off, LS, 0);
        }
    }
}